// round 1
// baseline (speedup 1.0000x reference)
#include <cuda_runtime.h>
#include <math.h>

// ---------------------------------------------------------------------------
// Problem constants
// ---------------------------------------------------------------------------
#define BATCH   2
#define RES_H   32
#define RES_W   32
#define RES_L   16
#define WSZ     8
#define CDIM    384
#define NHEADS  12
#define HD      32
#define NTOK    (RES_H*RES_W*RES_L)       // 16384
#define BTROWS  (BATCH*NTOK)              // 32768 rows total
#define NWIN_B  ((RES_H/WSZ)*(RES_W/WSZ)*(RES_L/WSZ))  // 32 windows / batch
#define NWIN    (BATCH*NWIN_B)            // 64 windows
#define WN      (WSZ*WSZ*WSZ)             // 512 tokens / window
#define KVGC    1152                      // k|v|g columns
#define HIDDEN  1536

// ---------------------------------------------------------------------------
// Scratch (static device globals; no allocation anywhere)
// ---------------------------------------------------------------------------
static __device__ float d_xw [BTROWS*CDIM];
static __device__ float d_yw [BTROWS*CDIM];
static __device__ float d_kvg[BTROWS*KVGC];
static __device__ float d_qb [BTROWS*CDIM];
static __device__ float d_xo [BTROWS*CDIM];
static __device__ float d_aw [BTROWS*CDIM];
static __device__ float d_x2 [BTROWS*CDIM];
static __device__ float d_hn [BTROWS*CDIM];
static __device__ float d_h1 [BTROWS*HIDDEN];

// ---------------------------------------------------------------------------
// Helpers
// ---------------------------------------------------------------------------
__device__ __forceinline__ float warp_sum(float v) {
    #pragma unroll
    for (int o = 16; o; o >>= 1) v += __shfl_xor_sync(0xffffffffu, v, o);
    return v;
}

// token index (b, t) -> row in window-partitioned layout [NWIN*WN]
__device__ __forceinline__ int window_row(int bt) {
    int bb = bt >> 14;          // / 16384
    int t  = bt & 16383;
    int hh = t >> 9;            // / (32*16)
    int ww = (t >> 4) & 31;
    int ll = t & 15;
    int win = bb * NWIN_B + (((hh >> 3) * 4 + (ww >> 3)) * 2 + (ll >> 3));
    int n   = (((hh & 7) << 3) + (ww & 7)) * 8 + (ll & 7);
    return win * WN + n;
}

// ---------------------------------------------------------------------------
// LayerNorm fused with window partition: out[window_row(bt)] = LN(x[bt])
// one warp per row, 12 elems per lane
// ---------------------------------------------------------------------------
__global__ void __launch_bounds__(256) ln_win_kernel(
    const float* __restrict__ x, const float* __restrict__ g,
    const float* __restrict__ b, float* __restrict__ out)
{
    int warp = (blockIdx.x * blockDim.x + threadIdx.x) >> 5;
    int lane = threadIdx.x & 31;
    if (warp >= BTROWS) return;
    const float* xr = x + (size_t)warp * CDIM;
    float v[12];
    float s = 0.f;
    #pragma unroll
    for (int i = 0; i < 12; i++) { v[i] = xr[lane + i * 32]; s += v[i]; }
    s = warp_sum(s);
    float mu = s * (1.f / 384.f);
    float sq = 0.f;
    #pragma unroll
    for (int i = 0; i < 12; i++) { float dv = v[i] - mu; sq += dv * dv; }
    sq = warp_sum(sq);
    float rstd = rsqrtf(sq * (1.f / 384.f) + 1e-5f);
    float* orp = out + (size_t)window_row(warp) * CDIM;
    #pragma unroll
    for (int i = 0; i < 12; i++) {
        int c = lane + i * 32;
        orp[c] = (v[i] - mu) * rstd * g[c] + b[c];
    }
}

// ---------------------------------------------------------------------------
// residual-add (window_reverse) fused with LayerNorm2:
//   x2[bt] = x[bt] + aw[window_row(bt)];  hn[bt] = LN(x2, g2, b2)
// ---------------------------------------------------------------------------
__global__ void __launch_bounds__(256) resln_kernel(
    const float* __restrict__ x, const float* __restrict__ aw,
    const float* __restrict__ g, const float* __restrict__ b,
    float* __restrict__ x2, float* __restrict__ hn)
{
    int warp = (blockIdx.x * blockDim.x + threadIdx.x) >> 5;
    int lane = threadIdx.x & 31;
    if (warp >= BTROWS) return;
    const float* xr = x  + (size_t)warp * CDIM;
    const float* ar = aw + (size_t)window_row(warp) * CDIM;
    float v[12];
    float s = 0.f;
    #pragma unroll
    for (int i = 0; i < 12; i++) {
        int c = lane + i * 32;
        v[i] = xr[c] + ar[c];
        s += v[i];
    }
    s = warp_sum(s);
    float mu = s * (1.f / 384.f);
    float sq = 0.f;
    #pragma unroll
    for (int i = 0; i < 12; i++) { float dv = v[i] - mu; sq += dv * dv; }
    sq = warp_sum(sq);
    float rstd = rsqrtf(sq * (1.f / 384.f) + 1e-5f);
    float* x2r = x2 + (size_t)warp * CDIM;
    float* hnr = hn + (size_t)warp * CDIM;
    #pragma unroll
    for (int i = 0; i < 12; i++) {
        int c = lane + i * 32;
        x2r[c] = v[i];
        hnr[c] = (v[i] - mu) * rstd * g[c] + b[c];
    }
}

// ---------------------------------------------------------------------------
// SGEMM: C[M,N] = A[M,K] @ W[N,K]^T + bias[N]   (+ epilogue)
// BM=BN=128, BK=8, 256 threads, 8x8 per thread. All dims divide tiles.
// EPI: 0 = bias, 1 = bias+GELU(erf), 2 = bias+residual(res[row*N+col])
// ---------------------------------------------------------------------------
template <int EPI>
__global__ void __launch_bounds__(256) sgemm_kernel(
    const float* __restrict__ A, const float* __restrict__ W,
    const float* __restrict__ bias, const float* __restrict__ res,
    float* __restrict__ C, int N, int K)
{
    __shared__ float As[8][128];
    __shared__ float Bs[8][128];
    const int bm = blockIdx.y * 128;
    const int bn = blockIdx.x * 128;
    const int tid = threadIdx.x;
    const int trow = tid >> 4;      // 0..15
    const int tcol = tid & 15;      // 0..15

    float acc[8][8];
    #pragma unroll
    for (int i = 0; i < 8; i++)
        #pragma unroll
        for (int j = 0; j < 8; j++) acc[i][j] = 0.f;

    const int lr = tid >> 1;          // 0..127
    const int lc = (tid & 1) * 4;     // 0 or 4
    const float* Abase = A + (size_t)(bm + lr) * K + lc;
    const float* Wbase = W + (size_t)(bn + lr) * K + lc;

    for (int k0 = 0; k0 < K; k0 += 8) {
        float4 av = *(const float4*)(Abase + k0);
        float4 wv = *(const float4*)(Wbase + k0);
        As[lc + 0][lr] = av.x; As[lc + 1][lr] = av.y;
        As[lc + 2][lr] = av.z; As[lc + 3][lr] = av.w;
        Bs[lc + 0][lr] = wv.x; Bs[lc + 1][lr] = wv.y;
        Bs[lc + 2][lr] = wv.z; Bs[lc + 3][lr] = wv.w;
        __syncthreads();
        #pragma unroll
        for (int kk = 0; kk < 8; kk++) {
            float a[8], b[8];
            float4 a0 = *(const float4*)&As[kk][trow * 8];
            float4 a1 = *(const float4*)&As[kk][trow * 8 + 4];
            float4 b0 = *(const float4*)&Bs[kk][tcol * 8];
            float4 b1 = *(const float4*)&Bs[kk][tcol * 8 + 4];
            a[0]=a0.x; a[1]=a0.y; a[2]=a0.z; a[3]=a0.w;
            a[4]=a1.x; a[5]=a1.y; a[6]=a1.z; a[7]=a1.w;
            b[0]=b0.x; b[1]=b0.y; b[2]=b0.z; b[3]=b0.w;
            b[4]=b1.x; b[5]=b1.y; b[6]=b1.z; b[7]=b1.w;
            #pragma unroll
            for (int i = 0; i < 8; i++)
                #pragma unroll
                for (int j = 0; j < 8; j++)
                    acc[i][j] += a[i] * b[j];
        }
        __syncthreads();
    }

    #pragma unroll
    for (int i = 0; i < 8; i++) {
        int row = bm + trow * 8 + i;
        #pragma unroll
        for (int j = 0; j < 8; j++) {
            int col = bn + tcol * 8 + j;
            float v = acc[i][j] + bias[col];
            if (EPI == 1) v = 0.5f * v * (1.f + erff(v * 0.70710678118654752f));
            if (EPI == 2) v += res[(size_t)row * N + col];
            C[(size_t)row * N + col] = v;
        }
    }
}

// ---------------------------------------------------------------------------
// Pola linear attention, one block per (window, head). 256 threads.
//   kvg layout per row: [k(0..383) | v(384..767) | g(768..1151)]
// ---------------------------------------------------------------------------
__global__ void __launch_bounds__(256) attn_kernel(
    const float* __restrict__ kvg, const float* __restrict__ qb,
    const float* __restrict__ pos_enc, const float* __restrict__ scale_p,
    const float* __restrict__ power_p, float* __restrict__ xo)
{
    const int wg = blockIdx.x;   // 0..63
    const int h  = blockIdx.y;   // 0..11
    const int tid = threadIdx.x;

    __shared__ float sc_s[32], pw_s[32];
    __shared__ float kc_s[64][64];
    __shared__ float v_s[64][32];
    __shared__ float kv_s[2][64][16];
    __shared__ float km_s[64];
    __shared__ float qf_s[8][64];

    if (tid < 32) {
        float sp = scale_p[h * 32 + tid];
        sc_s[tid] = 1.f / log1pf(expf(sp));          // reciprocal of softplus
        float pp = power_p[h * 32 + tid];
        pw_s[tid] = 1.f + 4.f / (1.f + expf(-pp));   // 1 + ALPHA*sigmoid
    }
    __syncthreads();

    float kvacc[8] = {0,0,0,0,0,0,0,0};
    float ksum = 0.f;

    for (int c0 = 0; c0 < WN; c0 += 64) {
        // build kc + v chunk
        #pragma unroll
        for (int i = 0; i < 8; i++) {
            int idx = tid + 256 * i;        // 0..2047
            int nl = idx >> 5;
            int d  = idx & 31;
            int row = wg * WN + c0 + nl;
            float kval = (kvg[(size_t)row * KVGC + h * 32 + d]
                          + pos_enc[(c0 + nl) * CDIM + h * 32 + d]) * sc_s[d];
            float mag = fabsf(kval);
            float r = powf(mag, pw_s[d]);   // powf(0,p)=0 for p>0
            kc_s[nl][d]      = kval > 0.f ? r : 0.f;
            kc_s[nl][d + 32] = kval < 0.f ? r : 0.f;
            v_s[nl][d] = kvg[(size_t)row * KVGC + 384 + h * 32 + d];
        }
        __syncthreads();
        // kv accumulation: thread owns 8 (branch,f,d) outputs
        #pragma unroll
        for (int jj = 0; jj < 8; jj++) {
            int o = tid + 256 * jj;
            int br = o >> 10;
            int rem = o & 1023;
            int f = rem >> 4, d = rem & 15;
            float a = kvacc[jj];
            #pragma unroll 8
            for (int n = 0; n < 64; n++) a += kc_s[n][f] * v_s[n][br * 16 + d];
            kvacc[jj] = a;
        }
        if (tid < 64) {
            float s = ksum;
            #pragma unroll 8
            for (int n = 0; n < 64; n++) s += kc_s[n][tid];
            ksum = s;
        }
        __syncthreads();
    }

    #pragma unroll
    for (int jj = 0; jj < 8; jj++) {
        int o = tid + 256 * jj;
        int br = o >> 10;
        int rem = o & 1023;
        kv_s[br][rem >> 4][rem & 15] = kvacc[jj] * (1.f / 512.f);
    }
    if (tid < 64) km_s[tid] = ksum * (1.f / 512.f);
    __syncthreads();

    // q pass: 8 warps x 64 tokens
    const int warp = tid >> 5;
    const int lane = tid & 31;
    const float p  = pw_s[lane];
    const float rs = sc_s[lane];
    for (int n = warp * 64; n < warp * 64 + 64; n++) {
        int row = wg * WN + n;
        float qv = qb[(size_t)row * CDIM + h * 32 + lane] * rs;
        float mag = fabsf(qv);
        float r = powf(mag, p);
        float qpos = qv > 0.f ? r : 0.f;
        float qneg = qv < 0.f ? r : 0.f;
        qf_s[warp][lane]      = qpos;
        qf_s[warp][lane + 32] = qneg;
        __syncwarp();
        float zs = 1e-6f, zo = 1e-6f;
        #pragma unroll
        for (int f = 0; f < 64; f++) {
            float q = qf_s[warp][f];
            zs += q * km_s[f];
            zo += q * km_s[(f + 32) & 63];
        }
        float out = 0.f;
        if (lane < 16) {
            #pragma unroll
            for (int f = 0; f < 64; f++) out += qf_s[warp][f] * kv_s[0][f][lane];
            out /= zs;
        } else {
            #pragma unroll
            for (int f = 0; f < 64; f++) out += qf_s[warp][(f + 32) & 63] * kv_s[1][f][lane - 16];
            out /= zo;
        }
        xo[(size_t)row * CDIM + h * 32 + lane] = out;
        __syncwarp();
    }
}

// ---------------------------------------------------------------------------
// Depthwise 5x5x5 conv over (8,8,8,HD) per (window,head), fused with
// xo = (xo + conv(v)) * g, replicating the reference's RAW reshape:
// conv output (b_,h,n,d) lands at flat = b_*196608 + h*16384 + n*32 + d.
// dynamic smem: v_s[512*32] + w_s[125*32]
// ---------------------------------------------------------------------------
__global__ void __launch_bounds__(256) dwconv_kernel(
    const float* __restrict__ kvg, const float* __restrict__ dwc_w,
    const float* __restrict__ dwc_b, float* __restrict__ xo)
{
    extern __shared__ float sm[];
    float* v_s = sm;              // [512][32]
    float* w_s = sm + 512 * 32;   // [125][32]
    const int bh = blockIdx.x;    // 0..767
    const int b_ = bh / NHEADS, h = bh % NHEADS;
    const int tid = threadIdx.x;

    for (int i = tid; i < 512 * 32; i += 256) {
        int n = i >> 5, d = i & 31;
        v_s[i] = kvg[(size_t)(b_ * WN + n) * KVGC + 384 + h * 32 + d];
    }
    for (int i = tid; i < 125 * 32; i += 256) w_s[i] = dwc_w[i];
    __syncthreads();

    const int d  = tid & 31;
    const int lo = tid >> 5;       // this thread's fixed l-coordinate (0..7)
    const float bval = dwc_b[d];
    const size_t base = (size_t)b_ * (WN * CDIM) + (size_t)h * (WN * HD);

    for (int jg = 0; jg < 4; jg++) {
        float acc[16];
        #pragma unroll
        for (int jj = 0; jj < 16; jj++) acc[jj] = bval;
        for (int kd = 0; kd < 5; kd++) {
            for (int kh = 0; kh < 5; kh++) {
                for (int kw = 0; kw < 5; kw++) {
                    int li = lo + kw - 2;
                    if (li < 0 || li > 7) continue;
                    float w = w_s[((kd * 5 + kh) * 5 + kw) * 32 + d];
                    #pragma unroll
                    for (int jj = 0; jj < 16; jj++) {
                        int j = jg * 16 + jj;          // output (ho=j>>3, wo=j&7, lo)
                        int hi = (j >> 3) + kd - 2;
                        int wi = (j & 7) + kh - 2;
                        if (hi < 0 || hi > 7 || wi < 0 || wi > 7) continue;
                        acc[jj] += v_s[((hi * 8 + wi) * 8 + li) * 32 + d] * w;
                    }
                }
            }
        }
        #pragma unroll
        for (int jj = 0; jj < 16; jj++) {
            int j = jg * 16 + jj;
            size_t flat = base + (size_t)(lo + 8 * j) * 32 + d;
            size_t grow = flat / CDIM;
            int    gcol = (int)(flat % CDIM);
            float g = kvg[grow * KVGC + 768 + gcol];
            xo[flat] = (xo[flat] + acc[jj]) * g;
        }
    }
}

// ---------------------------------------------------------------------------
// kernel_launch
// inputs: 0 x, 1 y, 2 w_qkvg, 3 b_qkvg, 4 w_proj, 5 b_proj, 6 dwc_w, 7 dwc_b,
//         8 power_p, 9 scale_p, 10 pos_enc, 11 g1, 12 b1, 13 g2, 14 b2,
//         15 w_fc1, 16 b_fc1, 17 w_fc2, 18 b_fc2
// ---------------------------------------------------------------------------
extern "C" void kernel_launch(void* const* d_in, const int* in_sizes, int n_in,
                              void* d_out, int out_size)
{
    const float* x       = (const float*)d_in[0];
    const float* y       = (const float*)d_in[1];
    const float* w_qkvg  = (const float*)d_in[2];
    const float* b_qkvg  = (const float*)d_in[3];
    const float* w_proj  = (const float*)d_in[4];
    const float* b_proj  = (const float*)d_in[5];
    const float* dwc_w   = (const float*)d_in[6];
    const float* dwc_b   = (const float*)d_in[7];
    const float* power_p = (const float*)d_in[8];
    const float* scale_p = (const float*)d_in[9];
    const float* pos_enc = (const float*)d_in[10];
    const float* g1      = (const float*)d_in[11];
    const float* b1      = (const float*)d_in[12];
    const float* g2      = (const float*)d_in[13];
    const float* b2      = (const float*)d_in[14];
    const float* w_fc1   = (const float*)d_in[15];
    const float* b_fc1   = (const float*)d_in[16];
    const float* w_fc2   = (const float*)d_in[17];
    const float* b_fc2   = (const float*)d_in[18];
    float* out = (float*)d_out;

    float *p_xw, *p_yw, *p_kvg, *p_qb, *p_xo, *p_aw, *p_x2, *p_hn, *p_h1;
    cudaGetSymbolAddress((void**)&p_xw,  d_xw);
    cudaGetSymbolAddress((void**)&p_yw,  d_yw);
    cudaGetSymbolAddress((void**)&p_kvg, d_kvg);
    cudaGetSymbolAddress((void**)&p_qb,  d_qb);
    cudaGetSymbolAddress((void**)&p_xo,  d_xo);
    cudaGetSymbolAddress((void**)&p_aw,  d_aw);
    cudaGetSymbolAddress((void**)&p_x2,  d_x2);
    cudaGetSymbolAddress((void**)&p_hn,  d_hn);
    cudaGetSymbolAddress((void**)&p_h1,  d_h1);

    const int conv_smem = (512 * 32 + 125 * 32) * (int)sizeof(float);  // 81536
    cudaFuncSetAttribute(dwconv_kernel,
                         cudaFuncAttributeMaxDynamicSharedMemorySize, conv_smem);

    // 1) LN + window partition
    ln_win_kernel<<<BTROWS / 8, 256>>>(x, g1, b1, p_xw);
    ln_win_kernel<<<BTROWS / 8, 256>>>(y, g1, b1, p_yw);

    // 2) kvg = xw @ W[384:1536]^T + b[384:]   (M=32768, N=1152, K=384)
    sgemm_kernel<0><<<dim3(KVGC / 128, BTROWS / 128), 256>>>(
        p_xw, w_qkvg + 384 * 384, b_qkvg + 384, nullptr, p_kvg, KVGC, 384);

    // 3) q = yw @ W[0:384]^T + b[0:384]       (N=384, K=384)
    sgemm_kernel<0><<<dim3(CDIM / 128, BTROWS / 128), 256>>>(
        p_yw, w_qkvg, b_qkvg, nullptr, p_qb, CDIM, 384);

    // 4) attention -> xo
    attn_kernel<<<dim3(NWIN, NHEADS), 256>>>(p_kvg, p_qb, pos_enc,
                                             scale_p, power_p, p_xo);

    // 5) depthwise conv + (xo + vv) * g, in place
    dwconv_kernel<<<NWIN * NHEADS, 256, conv_smem>>>(p_kvg, dwc_w, dwc_b, p_xo);

    // 6) aw = xo @ w_proj^T + b_proj          (N=384, K=384)
    sgemm_kernel<0><<<dim3(CDIM / 128, BTROWS / 128), 256>>>(
        p_xo, w_proj, b_proj, nullptr, p_aw, CDIM, 384);

    // 7) x2 = x + window_reverse(aw); hn = LN(x2, g2, b2)
    resln_kernel<<<BTROWS / 8, 256>>>(x, p_aw, g2, b2, p_x2, p_hn);

    // 8) h1 = gelu(hn @ w_fc1^T + b_fc1)      (N=1536, K=384)
    sgemm_kernel<1><<<dim3(HIDDEN / 128, BTROWS / 128), 256>>>(
        p_hn, w_fc1, b_fc1, nullptr, p_h1, HIDDEN, 384);

    // 9) out = x2 + h1 @ w_fc2^T + b_fc2      (N=384, K=1536)
    sgemm_kernel<2><<<dim3(CDIM / 128, BTROWS / 128), 256>>>(
        p_h1, w_fc2, b_fc2, p_x2, out, CDIM, 1536);
}

// round 3
// speedup vs baseline: 1.9952x; 1.9952x over previous
#include <cuda_runtime.h>
#include <cuda_bf16.h>
#include <math.h>
#include <stdint.h>

// ---------------------------------------------------------------------------
// Problem constants
// ---------------------------------------------------------------------------
#define BATCH   2
#define RES_H   32
#define RES_W   32
#define RES_L   16
#define WSZ     8
#define CDIM    384
#define NHEADS  12
#define HD      32
#define NTOK    (RES_H*RES_W*RES_L)       // 16384
#define BTROWS  (BATCH*NTOK)              // 32768
#define NWIN_B  ((RES_H/WSZ)*(RES_W/WSZ)*(RES_L/WSZ))  // 32
#define NWIN    (BATCH*NWIN_B)            // 64
#define WN      (WSZ*WSZ*WSZ)             // 512
#define KVGC    1152
#define HIDDEN  1536

// ---------------------------------------------------------------------------
// Scratch (static device globals)
// ---------------------------------------------------------------------------
static __device__ __align__(256) __nv_bfloat16 d_xwh[BTROWS*CDIM];
static __device__ __align__(256) __nv_bfloat16 d_xwl[BTROWS*CDIM];
static __device__ __align__(256) __nv_bfloat16 d_ywh[BTROWS*CDIM];
static __device__ __align__(256) __nv_bfloat16 d_ywl[BTROWS*CDIM];
static __device__ __align__(256) __nv_bfloat16 d_hnh[BTROWS*CDIM];
static __device__ __align__(256) __nv_bfloat16 d_hnl[BTROWS*CDIM];
static __device__ __align__(256) __nv_bfloat16 d_xoh[BTROWS*CDIM];
static __device__ __align__(256) __nv_bfloat16 d_xol[BTROWS*CDIM];
static __device__ __align__(256) __nv_bfloat16 d_h1h[BTROWS*HIDDEN];
static __device__ __align__(256) __nv_bfloat16 d_h1l[BTROWS*HIDDEN];
static __device__ __align__(256) __nv_bfloat16 d_wqh[1536*384];
static __device__ __align__(256) __nv_bfloat16 d_wql[1536*384];
static __device__ __align__(256) __nv_bfloat16 d_wph[384*384];
static __device__ __align__(256) __nv_bfloat16 d_wpl[384*384];
static __device__ __align__(256) __nv_bfloat16 d_w1h[1536*384];
static __device__ __align__(256) __nv_bfloat16 d_w1l[1536*384];
static __device__ __align__(256) __nv_bfloat16 d_w2h[384*1536];
static __device__ __align__(256) __nv_bfloat16 d_w2l[384*1536];

static __device__ float d_kvg[BTROWS*KVGC];
static __device__ float d_qb [BTROWS*CDIM];
static __device__ float d_xo [BTROWS*CDIM];
static __device__ float d_aw [BTROWS*CDIM];
static __device__ float d_x2 [BTROWS*CDIM];

// ---------------------------------------------------------------------------
// PTX helpers (arch-portable: cp.async / ldmatrix / mma.sync only)
// ---------------------------------------------------------------------------
__device__ __forceinline__ uint32_t smem_u32(const void* p) {
    uint32_t a;
    asm("{ .reg .u64 t; cvta.to.shared.u64 t, %1; cvt.u32.u64 %0, t; }"
        : "=r"(a) : "l"(p));
    return a;
}
__device__ __forceinline__ void cp_async16(uint32_t dst, const void* src) {
    asm volatile("cp.async.cg.shared.global [%0], [%1], 16;"
        :: "r"(dst), "l"(src) : "memory");
}
__device__ __forceinline__ void ldm4(uint32_t* r, uint32_t addr) {
    asm volatile("ldmatrix.sync.aligned.m8n8.x4.shared.b16 {%0,%1,%2,%3}, [%4];"
        : "=r"(r[0]), "=r"(r[1]), "=r"(r[2]), "=r"(r[3]) : "r"(addr));
}
__device__ __forceinline__ void mma16816(float* c, const uint32_t* a, const uint32_t* b) {
    asm volatile("mma.sync.aligned.m16n8k16.row.col.f32.bf16.bf16.f32 "
        "{%0,%1,%2,%3}, {%4,%5,%6,%7}, {%8,%9}, {%0,%1,%2,%3};"
        : "+f"(c[0]), "+f"(c[1]), "+f"(c[2]), "+f"(c[3])
        : "r"(a[0]), "r"(a[1]), "r"(a[2]), "r"(a[3]), "r"(b[0]), "r"(b[1]));
}

// ---------------------------------------------------------------------------
// misc helpers
// ---------------------------------------------------------------------------
__device__ __forceinline__ float warp_sum(float v) {
    #pragma unroll
    for (int o = 16; o; o >>= 1) v += __shfl_xor_sync(0xffffffffu, v, o);
    return v;
}
__device__ __forceinline__ int window_row(int bt) {
    int bb = bt >> 14;
    int t  = bt & 16383;
    int hh = t >> 9;
    int ww = (t >> 4) & 31;
    int ll = t & 15;
    int win = bb * NWIN_B + (((hh >> 3) * 4 + (ww >> 3)) * 2 + (ll >> 3));
    int n   = (((hh & 7) << 3) + (ww & 7)) * 8 + (ll & 7);
    return win * WN + n;
}
__device__ __forceinline__ void split_bf16(float v, __nv_bfloat16& h, __nv_bfloat16& l) {
    h = __float2bfloat16(v);
    l = __float2bfloat16(v - __bfloat162float(h));
}

// ---------------------------------------------------------------------------
// fp32 -> bf16 hi/lo split conversion (vectorized by 4)
// ---------------------------------------------------------------------------
__global__ void __launch_bounds__(256) cvt_kernel(
    const float4* __restrict__ in, uint2* __restrict__ hi,
    uint2* __restrict__ lo, int n4)
{
    int i = blockIdx.x * blockDim.x + threadIdx.x;
    if (i >= n4) return;
    float4 v = in[i];
    __nv_bfloat16 h0, h1, h2, h3, l0, l1, l2, l3;
    split_bf16(v.x, h0, l0); split_bf16(v.y, h1, l1);
    split_bf16(v.z, h2, l2); split_bf16(v.w, h3, l3);
    __nv_bfloat162 ph0; ph0.x = h0; ph0.y = h1;
    __nv_bfloat162 ph1; ph1.x = h2; ph1.y = h3;
    __nv_bfloat162 pl0; pl0.x = l0; pl0.y = l1;
    __nv_bfloat162 pl1; pl1.x = l2; pl1.y = l3;
    uint2 uh; uh.x = *(uint32_t*)&ph0; uh.y = *(uint32_t*)&ph1;
    uint2 ul; ul.x = *(uint32_t*)&pl0; ul.y = *(uint32_t*)&pl1;
    hi[i] = uh; lo[i] = ul;
}

// ---------------------------------------------------------------------------
// LayerNorm fused with window partition -> bf16 hi/lo planes
// ---------------------------------------------------------------------------
__global__ void __launch_bounds__(256) ln_win_kernel(
    const float* __restrict__ x, const float* __restrict__ g,
    const float* __restrict__ b, __nv_bfloat16* __restrict__ oh,
    __nv_bfloat16* __restrict__ ol)
{
    int warp = (blockIdx.x * blockDim.x + threadIdx.x) >> 5;
    int lane = threadIdx.x & 31;
    if (warp >= BTROWS) return;
    const float* xr = x + (size_t)warp * CDIM;
    float v[12];
    float s = 0.f;
    #pragma unroll
    for (int i = 0; i < 12; i++) { v[i] = xr[lane + i * 32]; s += v[i]; }
    s = warp_sum(s);
    float mu = s * (1.f / 384.f);
    float sq = 0.f;
    #pragma unroll
    for (int i = 0; i < 12; i++) { float dv = v[i] - mu; sq += dv * dv; }
    sq = warp_sum(sq);
    float rstd = rsqrtf(sq * (1.f / 384.f) + 1e-5f);
    size_t ro = (size_t)window_row(warp) * CDIM;
    #pragma unroll
    for (int i = 0; i < 12; i++) {
        int c = lane + i * 32;
        float o = (v[i] - mu) * rstd * g[c] + b[c];
        __nv_bfloat16 h, l; split_bf16(o, h, l);
        oh[ro + c] = h; ol[ro + c] = l;
    }
}

// ---------------------------------------------------------------------------
// residual-add (window_reverse) + LN2 -> x2 fp32, hn bf16 hi/lo
// ---------------------------------------------------------------------------
__global__ void __launch_bounds__(256) resln_kernel(
    const float* __restrict__ x, const float* __restrict__ aw,
    const float* __restrict__ g, const float* __restrict__ b,
    float* __restrict__ x2, __nv_bfloat16* __restrict__ hh,
    __nv_bfloat16* __restrict__ hl)
{
    int warp = (blockIdx.x * blockDim.x + threadIdx.x) >> 5;
    int lane = threadIdx.x & 31;
    if (warp >= BTROWS) return;
    const float* xr = x  + (size_t)warp * CDIM;
    const float* ar = aw + (size_t)window_row(warp) * CDIM;
    float v[12];
    float s = 0.f;
    #pragma unroll
    for (int i = 0; i < 12; i++) {
        int c = lane + i * 32;
        v[i] = xr[c] + ar[c];
        s += v[i];
    }
    s = warp_sum(s);
    float mu = s * (1.f / 384.f);
    float sq = 0.f;
    #pragma unroll
    for (int i = 0; i < 12; i++) { float dv = v[i] - mu; sq += dv * dv; }
    sq = warp_sum(sq);
    float rstd = rsqrtf(sq * (1.f / 384.f) + 1e-5f);
    size_t ro = (size_t)warp * CDIM;
    #pragma unroll
    for (int i = 0; i < 12; i++) {
        int c = lane + i * 32;
        x2[ro + c] = v[i];
        float o = (v[i] - mu) * rstd * g[c] + b[c];
        __nv_bfloat16 h, l; split_bf16(o, h, l);
        hh[ro + c] = h; hl[ro + c] = l;
    }
}

// ---------------------------------------------------------------------------
// mma.sync GEMM: C[M,N] = A[M,K] @ W[N,K]^T (+ bias / gelu / residual)
// bf16-split (3 MMA passes). BM=BN=128, BK=32. 256 threads, 8 warps (2Mx4N),
// warp tile 64x32, m16n8k16. cp.async double buffer, XOR-swizzled smem.
// EPI: 0 = bias->fp32 C, 1 = bias+gelu->bf16 hi/lo planes, 2 = bias+res->fp32 C
// ---------------------------------------------------------------------------
#define GSTAGE 32768
#define GSMEM_BYTES (2*GSTAGE)

template <int EPI>
__global__ void __launch_bounds__(256, 1) mma_gemm(
    const __nv_bfloat16* __restrict__ Ah, const __nv_bfloat16* __restrict__ Al,
    const __nv_bfloat16* __restrict__ Bh, const __nv_bfloat16* __restrict__ Bl,
    const float* __restrict__ bias, const float* __restrict__ res,
    float* __restrict__ C, __nv_bfloat16* __restrict__ Ch,
    __nv_bfloat16* __restrict__ Cl, int N, int K)
{
    extern __shared__ char smem[];
    const uint32_t sbase = smem_u32(smem);
    const int tid  = threadIdx.x;
    const int lane = tid & 31;
    const int wid  = tid >> 5;
    const int wm   = wid & 1;    // 0..1
    const int wn   = wid >> 1;   // 0..3
    const int bm = blockIdx.y * 128;
    const int bn = blockIdx.x * 128;

    float acc[4][4][4];
    #pragma unroll
    for (int i = 0; i < 4; i++)
        #pragma unroll
        for (int j = 0; j < 4; j++)
            #pragma unroll
            for (int q = 0; q < 4; q++) acc[i][j][q] = 0.f;

    // ---- stage loader: 4 sub-tiles (Ah,Al,Bh,Bl) 128x32 bf16, swizzled ----
    #define LOAD_STAGE(stage, k0) do {                                        \
        uint32_t sb_ = sbase + (uint32_t)(stage) * GSTAGE;                    \
        const __nv_bfloat16* bases_[4] = {Ah, Al, Bh, Bl};                    \
        _Pragma("unroll")                                                     \
        for (int sub_ = 0; sub_ < 4; sub_++) {                                \
            const __nv_bfloat16* bp_ = bases_[sub_];                          \
            int ro_ = (sub_ < 2) ? bm : bn;                                   \
            _Pragma("unroll")                                                 \
            for (int jj_ = 0; jj_ < 2; jj_++) {                               \
                int cid_ = tid + 256 * jj_;                                   \
                int row_ = cid_ >> 2, ck_ = cid_ & 3;                         \
                int cs_ = ck_ ^ ((row_ >> 1) & 3);                            \
                const void* src_ = bp_ + (size_t)(ro_ + row_) * K + (k0) + ck_ * 8; \
                cp_async16(sb_ + (uint32_t)(sub_ << 13)                       \
                           + (uint32_t)(row_ * 64 + cs_ * 16), src_);         \
            }                                                                 \
        }                                                                     \
    } while (0)

    const int NC = K >> 5;
    LOAD_STAGE(0, 0);
    asm volatile("cp.async.commit_group;" ::: "memory");

    // ldmatrix address precompute (row/chunk patterns per warp/lane)
    const int arow = wm * 64 + (lane & 15);          // + mt*16
    const int asel = lane >> 4;                      // k-half within k16
    const int brow = wn * 32 + ((lane >> 4) << 3) + (lane & 7);  // + bt*16
    const int bsel = (lane >> 3) & 1;

    for (int c = 0; c < NC; c++) {
        if (c + 1 < NC) {
            LOAD_STAGE((c + 1) & 1, (c + 1) << 5);
            asm volatile("cp.async.commit_group;" ::: "memory");
            asm volatile("cp.async.wait_group 1;" ::: "memory");
        } else {
            asm volatile("cp.async.wait_group 0;" ::: "memory");
        }
        __syncthreads();

        const uint32_t sb = sbase + (uint32_t)(c & 1) * GSTAGE;
        #pragma unroll
        for (int kk = 0; kk < 2; kk++) {
            uint32_t ah[4][4], al[4][4], bh[2][4], bl[2][4];
            #pragma unroll
            for (int mt = 0; mt < 4; mt++) {
                int row = arow + mt * 16;
                int ck  = kk * 2 + asel;
                uint32_t off = (uint32_t)(row * 64 + (ck ^ ((row >> 1) & 3)) * 16);
                ldm4(ah[mt], sb + off);
                ldm4(al[mt], sb + 8192u + off);
            }
            #pragma unroll
            for (int bt = 0; bt < 2; bt++) {
                int row = brow + bt * 16;
                int ck  = kk * 2 + bsel;
                uint32_t off = (uint32_t)(row * 64 + (ck ^ ((row >> 1) & 3)) * 16);
                ldm4(bh[bt], sb + 16384u + off);
                ldm4(bl[bt], sb + 24576u + off);
            }
            #pragma unroll
            for (int mt = 0; mt < 4; mt++) {
                #pragma unroll
                for (int nt = 0; nt < 4; nt++) {
                    const uint32_t* bhf = &bh[nt >> 1][(nt & 1) * 2];
                    const uint32_t* blf = &bl[nt >> 1][(nt & 1) * 2];
                    mma16816(acc[mt][nt], ah[mt], bhf);
                    mma16816(acc[mt][nt], ah[mt], blf);
                    mma16816(acc[mt][nt], al[mt], bhf);
                }
            }
        }
        __syncthreads();
    }

    // ---- epilogue ----
    const int gr = lane >> 2;
    const int nc0 = (lane & 3) * 2;
    #pragma unroll
    for (int mt = 0; mt < 4; mt++) {
        #pragma unroll
        for (int nt = 0; nt < 4; nt++) {
            int col = bn + wn * 32 + nt * 8 + nc0;
            float bs0 = bias[col], bs1 = bias[col + 1];
            #pragma unroll
            for (int half = 0; half < 2; half++) {
                int row = bm + wm * 64 + mt * 16 + gr + half * 8;
                float v0 = acc[mt][nt][half * 2 + 0] + bs0;
                float v1 = acc[mt][nt][half * 2 + 1] + bs1;
                size_t off = (size_t)row * N + col;
                if (EPI == 1) {
                    v0 = 0.5f * v0 * (1.f + erff(v0 * 0.70710678118654752f));
                    v1 = 0.5f * v1 * (1.f + erff(v1 * 0.70710678118654752f));
                    __nv_bfloat16 h0, l0, h1, l1;
                    split_bf16(v0, h0, l0); split_bf16(v1, h1, l1);
                    __nv_bfloat162 ph; ph.x = h0; ph.y = h1;
                    __nv_bfloat162 pl; pl.x = l0; pl.y = l1;
                    *(uint32_t*)(Ch + off) = *(uint32_t*)&ph;
                    *(uint32_t*)(Cl + off) = *(uint32_t*)&pl;
                } else {
                    if (EPI == 2) { v0 += res[off]; v1 += res[off + 1]; }
                    float2 o; o.x = v0; o.y = v1;
                    *(float2*)(C + off) = o;
                }
            }
        }
    }
    #undef LOAD_STAGE
}

// ---------------------------------------------------------------------------
// Pola linear attention (unchanged)
// ---------------------------------------------------------------------------
__global__ void __launch_bounds__(256) attn_kernel(
    const float* __restrict__ kvg, const float* __restrict__ qb,
    const float* __restrict__ pos_enc, const float* __restrict__ scale_p,
    const float* __restrict__ power_p, float* __restrict__ xo)
{
    const int wg = blockIdx.x;
    const int h  = blockIdx.y;
    const int tid = threadIdx.x;

    __shared__ float sc_s[32], pw_s[32];
    __shared__ float kc_s[64][64];
    __shared__ float v_s[64][32];
    __shared__ float kv_s[2][64][16];
    __shared__ float km_s[64];
    __shared__ float qf_s[8][64];

    if (tid < 32) {
        float sp = scale_p[h * 32 + tid];
        sc_s[tid] = 1.f / log1pf(expf(sp));
        float pp = power_p[h * 32 + tid];
        pw_s[tid] = 1.f + 4.f / (1.f + expf(-pp));
    }
    __syncthreads();

    float kvacc[8] = {0,0,0,0,0,0,0,0};
    float ksum = 0.f;

    for (int c0 = 0; c0 < WN; c0 += 64) {
        #pragma unroll
        for (int i = 0; i < 8; i++) {
            int idx = tid + 256 * i;
            int nl = idx >> 5;
            int d  = idx & 31;
            int row = wg * WN + c0 + nl;
            float kval = (kvg[(size_t)row * KVGC + h * 32 + d]
                          + pos_enc[(c0 + nl) * CDIM + h * 32 + d]) * sc_s[d];
            float mag = fabsf(kval);
            float r = powf(mag, pw_s[d]);
            kc_s[nl][d]      = kval > 0.f ? r : 0.f;
            kc_s[nl][d + 32] = kval < 0.f ? r : 0.f;
            v_s[nl][d] = kvg[(size_t)row * KVGC + 384 + h * 32 + d];
        }
        __syncthreads();
        #pragma unroll
        for (int jj = 0; jj < 8; jj++) {
            int o = tid + 256 * jj;
            int br = o >> 10;
            int rem = o & 1023;
            int f = rem >> 4, d = rem & 15;
            float a = kvacc[jj];
            #pragma unroll 8
            for (int n = 0; n < 64; n++) a += kc_s[n][f] * v_s[n][br * 16 + d];
            kvacc[jj] = a;
        }
        if (tid < 64) {
            float s = ksum;
            #pragma unroll 8
            for (int n = 0; n < 64; n++) s += kc_s[n][tid];
            ksum = s;
        }
        __syncthreads();
    }

    #pragma unroll
    for (int jj = 0; jj < 8; jj++) {
        int o = tid + 256 * jj;
        int br = o >> 10;
        int rem = o & 1023;
        kv_s[br][rem >> 4][rem & 15] = kvacc[jj] * (1.f / 512.f);
    }
    if (tid < 64) km_s[tid] = ksum * (1.f / 512.f);
    __syncthreads();

    const int warp = tid >> 5;
    const int lane = tid & 31;
    const float p  = pw_s[lane];
    const float rs = sc_s[lane];
    for (int n = warp * 64; n < warp * 64 + 64; n++) {
        int row = wg * WN + n;
        float qv = qb[(size_t)row * CDIM + h * 32 + lane] * rs;
        float mag = fabsf(qv);
        float r = powf(mag, p);
        float qpos = qv > 0.f ? r : 0.f;
        float qneg = qv < 0.f ? r : 0.f;
        qf_s[warp][lane]      = qpos;
        qf_s[warp][lane + 32] = qneg;
        __syncwarp();
        float zs = 1e-6f, zo = 1e-6f;
        #pragma unroll
        for (int f = 0; f < 64; f++) {
            float q = qf_s[warp][f];
            zs += q * km_s[f];
            zo += q * km_s[(f + 32) & 63];
        }
        float out = 0.f;
        if (lane < 16) {
            #pragma unroll
            for (int f = 0; f < 64; f++) out += qf_s[warp][f] * kv_s[0][f][lane];
            out /= zs;
        } else {
            #pragma unroll
            for (int f = 0; f < 64; f++) out += qf_s[warp][(f + 32) & 63] * kv_s[1][f][lane - 16];
            out /= zo;
        }
        xo[(size_t)row * CDIM + h * 32 + lane] = out;
        __syncwarp();
    }
}

// ---------------------------------------------------------------------------
// Depthwise 5^3 conv + (xo + vv) * g, in place (unchanged)
// ---------------------------------------------------------------------------
__global__ void __launch_bounds__(256) dwconv_kernel(
    const float* __restrict__ kvg, const float* __restrict__ dwc_w,
    const float* __restrict__ dwc_b, float* __restrict__ xo)
{
    extern __shared__ float sm[];
    float* v_s = sm;
    float* w_s = sm + 512 * 32;
    const int bh = blockIdx.x;
    const int b_ = bh / NHEADS, h = bh % NHEADS;
    const int tid = threadIdx.x;

    for (int i = tid; i < 512 * 32; i += 256) {
        int n = i >> 5, d = i & 31;
        v_s[i] = kvg[(size_t)(b_ * WN + n) * KVGC + 384 + h * 32 + d];
    }
    for (int i = tid; i < 125 * 32; i += 256) w_s[i] = dwc_w[i];
    __syncthreads();

    const int d  = tid & 31;
    const int lo = tid >> 5;
    const float bval = dwc_b[d];
    const size_t base = (size_t)b_ * (WN * CDIM) + (size_t)h * (WN * HD);

    for (int jg = 0; jg < 4; jg++) {
        float acc[16];
        #pragma unroll
        for (int jj = 0; jj < 16; jj++) acc[jj] = bval;
        for (int kd = 0; kd < 5; kd++) {
            for (int kh = 0; kh < 5; kh++) {
                for (int kw = 0; kw < 5; kw++) {
                    int li = lo + kw - 2;
                    if (li < 0 || li > 7) continue;
                    float w = w_s[((kd * 5 + kh) * 5 + kw) * 32 + d];
                    #pragma unroll
                    for (int jj = 0; jj < 16; jj++) {
                        int j = jg * 16 + jj;
                        int hi = (j >> 3) + kd - 2;
                        int wi = (j & 7) + kh - 2;
                        if (hi < 0 || hi > 7 || wi < 0 || wi > 7) continue;
                        acc[jj] += v_s[((hi * 8 + wi) * 8 + li) * 32 + d] * w;
                    }
                }
            }
        }
        #pragma unroll
        for (int jj = 0; jj < 16; jj++) {
            int j = jg * 16 + jj;
            size_t flat = base + (size_t)(lo + 8 * j) * 32 + d;
            size_t grow = flat / CDIM;
            int    gcol = (int)(flat % CDIM);
            float g = kvg[grow * KVGC + 768 + gcol];
            xo[flat] = (xo[flat] + acc[jj]) * g;
        }
    }
}

// ---------------------------------------------------------------------------
// kernel_launch
// ---------------------------------------------------------------------------
extern "C" void kernel_launch(void* const* d_in, const int* in_sizes, int n_in,
                              void* d_out, int out_size)
{
    const float* x       = (const float*)d_in[0];
    const float* y       = (const float*)d_in[1];
    const float* w_qkvg  = (const float*)d_in[2];
    const float* b_qkvg  = (const float*)d_in[3];
    const float* w_proj  = (const float*)d_in[4];
    const float* b_proj  = (const float*)d_in[5];
    const float* dwc_w   = (const float*)d_in[6];
    const float* dwc_b   = (const float*)d_in[7];
    const float* power_p = (const float*)d_in[8];
    const float* scale_p = (const float*)d_in[9];
    const float* pos_enc = (const float*)d_in[10];
    const float* g1      = (const float*)d_in[11];
    const float* b1      = (const float*)d_in[12];
    const float* g2      = (const float*)d_in[13];
    const float* b2      = (const float*)d_in[14];
    const float* w_fc1   = (const float*)d_in[15];
    const float* b_fc1   = (const float*)d_in[16];
    const float* w_fc2   = (const float*)d_in[17];
    const float* b_fc2   = (const float*)d_in[18];
    float* out = (float*)d_out;

    __nv_bfloat16 *p_xwh, *p_xwl, *p_ywh, *p_ywl, *p_hnh, *p_hnl;
    __nv_bfloat16 *p_xoh, *p_xol, *p_h1h, *p_h1l;
    __nv_bfloat16 *p_wqh, *p_wql, *p_wph, *p_wpl, *p_w1h, *p_w1l, *p_w2h, *p_w2l;
    float *p_kvg, *p_qb, *p_xo, *p_aw, *p_x2;
    cudaGetSymbolAddress((void**)&p_xwh, d_xwh);
    cudaGetSymbolAddress((void**)&p_xwl, d_xwl);
    cudaGetSymbolAddress((void**)&p_ywh, d_ywh);
    cudaGetSymbolAddress((void**)&p_ywl, d_ywl);
    cudaGetSymbolAddress((void**)&p_hnh, d_hnh);
    cudaGetSymbolAddress((void**)&p_hnl, d_hnl);
    cudaGetSymbolAddress((void**)&p_xoh, d_xoh);
    cudaGetSymbolAddress((void**)&p_xol, d_xol);
    cudaGetSymbolAddress((void**)&p_h1h, d_h1h);
    cudaGetSymbolAddress((void**)&p_h1l, d_h1l);
    cudaGetSymbolAddress((void**)&p_wqh, d_wqh);
    cudaGetSymbolAddress((void**)&p_wql, d_wql);
    cudaGetSymbolAddress((void**)&p_wph, d_wph);
    cudaGetSymbolAddress((void**)&p_wpl, d_wpl);
    cudaGetSymbolAddress((void**)&p_w1h, d_w1h);
    cudaGetSymbolAddress((void**)&p_w1l, d_w1l);
    cudaGetSymbolAddress((void**)&p_w2h, d_w2h);
    cudaGetSymbolAddress((void**)&p_w2l, d_w2l);
    cudaGetSymbolAddress((void**)&p_kvg, d_kvg);
    cudaGetSymbolAddress((void**)&p_qb,  d_qb);
    cudaGetSymbolAddress((void**)&p_xo,  d_xo);
    cudaGetSymbolAddress((void**)&p_aw,  d_aw);
    cudaGetSymbolAddress((void**)&p_x2,  d_x2);

    const int conv_smem = (512 * 32 + 125 * 32) * (int)sizeof(float);
    cudaFuncSetAttribute(dwconv_kernel,
                         cudaFuncAttributeMaxDynamicSharedMemorySize, conv_smem);
    cudaFuncSetAttribute(mma_gemm<0>,
                         cudaFuncAttributeMaxDynamicSharedMemorySize, GSMEM_BYTES);
    cudaFuncSetAttribute(mma_gemm<1>,
                         cudaFuncAttributeMaxDynamicSharedMemorySize, GSMEM_BYTES);
    cudaFuncSetAttribute(mma_gemm<2>,
                         cudaFuncAttributeMaxDynamicSharedMemorySize, GSMEM_BYTES);

    // 0) weight splits
    cvt_kernel<<<(1536*384/4 + 255)/256, 256>>>((const float4*)w_qkvg,
        (uint2*)p_wqh, (uint2*)p_wql, 1536*384/4);
    cvt_kernel<<<(384*384/4 + 255)/256, 256>>>((const float4*)w_proj,
        (uint2*)p_wph, (uint2*)p_wpl, 384*384/4);
    cvt_kernel<<<(1536*384/4 + 255)/256, 256>>>((const float4*)w_fc1,
        (uint2*)p_w1h, (uint2*)p_w1l, 1536*384/4);
    cvt_kernel<<<(384*1536/4 + 255)/256, 256>>>((const float4*)w_fc2,
        (uint2*)p_w2h, (uint2*)p_w2l, 384*1536/4);

    // 1) LN + window partition -> bf16 splits
    ln_win_kernel<<<BTROWS / 8, 256>>>(x, g1, b1, p_xwh, p_xwl);
    ln_win_kernel<<<BTROWS / 8, 256>>>(y, g1, b1, p_ywh, p_ywl);

    // 2) kvg = xw @ W[384:1536]^T + b[384:]   (N=1152, K=384)
    mma_gemm<0><<<dim3(KVGC/128, BTROWS/128), 256, GSMEM_BYTES>>>(
        p_xwh, p_xwl, p_wqh + 384*384, p_wql + 384*384, b_qkvg + 384,
        nullptr, p_kvg, nullptr, nullptr, KVGC, 384);

    // 3) q = yw @ W[0:384]^T + b[0:384]
    mma_gemm<0><<<dim3(CDIM/128, BTROWS/128), 256, GSMEM_BYTES>>>(
        p_ywh, p_ywl, p_wqh, p_wql, b_qkvg,
        nullptr, p_qb, nullptr, nullptr, CDIM, 384);

    // 4) attention -> xo
    attn_kernel<<<dim3(NWIN, NHEADS), 256>>>(p_kvg, p_qb, pos_enc,
                                             scale_p, power_p, p_xo);

    // 5) depthwise conv + gating, in place
    dwconv_kernel<<<NWIN * NHEADS, 256, conv_smem>>>(p_kvg, dwc_w, dwc_b, p_xo);

    // 5b) split xo
    cvt_kernel<<<(BTROWS*CDIM/4 + 255)/256, 256>>>((const float4*)p_xo,
        (uint2*)p_xoh, (uint2*)p_xol, BTROWS*CDIM/4);

    // 6) aw = xo @ w_proj^T + b_proj
    mma_gemm<0><<<dim3(CDIM/128, BTROWS/128), 256, GSMEM_BYTES>>>(
        p_xoh, p_xol, p_wph, p_wpl, b_proj,
        nullptr, p_aw, nullptr, nullptr, CDIM, 384);

    // 7) x2 = x + window_reverse(aw); hn = LN2(x2) -> bf16 splits
    resln_kernel<<<BTROWS / 8, 256>>>(x, p_aw, g2, b2, p_x2, p_hnh, p_hnl);

    // 8) h1 = gelu(hn @ w_fc1^T + b_fc1) -> bf16 splits   (N=1536, K=384)
    mma_gemm<1><<<dim3(HIDDEN/128, BTROWS/128), 256, GSMEM_BYTES>>>(
        p_hnh, p_hnl, p_w1h, p_w1l, b_fc1,
        nullptr, nullptr, p_h1h, p_h1l, HIDDEN, 384);

    // 9) out = x2 + h1 @ w_fc2^T + b_fc2    (N=384, K=1536)
    mma_gemm<2><<<dim3(CDIM/128, BTROWS/128), 256, GSMEM_BYTES>>>(
        p_h1h, p_h1l, p_w2h, p_w2l, b_fc2,
        p_x2, out, nullptr, nullptr, CDIM, 1536);
}

// round 5
// speedup vs baseline: 2.4086x; 1.2071x over previous
#include <cuda_runtime.h>
#include <cuda_bf16.h>
#include <math.h>
#include <stdint.h>

// ---------------------------------------------------------------------------
// Problem constants
// ---------------------------------------------------------------------------
#define BATCH   2
#define RES_H   32
#define RES_W   32
#define RES_L   16
#define WSZ     8
#define CDIM    384
#define NHEADS  12
#define HD      32
#define NTOK    (RES_H*RES_W*RES_L)       // 16384
#define BTROWS  (BATCH*NTOK)              // 32768
#define NWIN_B  ((RES_H/WSZ)*(RES_W/WSZ)*(RES_L/WSZ))  // 32
#define NWIN    (BATCH*NWIN_B)            // 64
#define WN      (WSZ*WSZ*WSZ)             // 512
#define KVGC    1152
#define HIDDEN  1536

// ---------------------------------------------------------------------------
// Scratch (static device globals)
// ---------------------------------------------------------------------------
static __device__ __align__(256) __nv_bfloat16 d_xwh[BTROWS*CDIM];
static __device__ __align__(256) __nv_bfloat16 d_xwl[BTROWS*CDIM];
static __device__ __align__(256) __nv_bfloat16 d_ywh[BTROWS*CDIM];
static __device__ __align__(256) __nv_bfloat16 d_ywl[BTROWS*CDIM];
static __device__ __align__(256) __nv_bfloat16 d_hnh[BTROWS*CDIM];
static __device__ __align__(256) __nv_bfloat16 d_hnl[BTROWS*CDIM];
static __device__ __align__(256) __nv_bfloat16 d_xoh[BTROWS*CDIM];
static __device__ __align__(256) __nv_bfloat16 d_xol[BTROWS*CDIM];
static __device__ __align__(256) __nv_bfloat16 d_h1h[BTROWS*HIDDEN];
static __device__ __align__(256) __nv_bfloat16 d_h1l[BTROWS*HIDDEN];
static __device__ __align__(256) __nv_bfloat16 d_wqh[1536*384];
static __device__ __align__(256) __nv_bfloat16 d_wql[1536*384];
static __device__ __align__(256) __nv_bfloat16 d_wph[384*384];
static __device__ __align__(256) __nv_bfloat16 d_wpl[384*384];
static __device__ __align__(256) __nv_bfloat16 d_w1h[1536*384];
static __device__ __align__(256) __nv_bfloat16 d_w1l[1536*384];
static __device__ __align__(256) __nv_bfloat16 d_w2h[384*1536];
static __device__ __align__(256) __nv_bfloat16 d_w2l[384*1536];

static __device__ float d_kvg[BTROWS*KVGC];
static __device__ float d_qb [BTROWS*CDIM];
static __device__ float d_xo [BTROWS*CDIM];
static __device__ float d_aw [BTROWS*CDIM];
static __device__ float d_x2 [BTROWS*CDIM];

// ---------------------------------------------------------------------------
// PTX helpers (arch-portable: cp.async / ldmatrix / mma.sync only)
// ---------------------------------------------------------------------------
__device__ __forceinline__ uint32_t smem_u32(const void* p) {
    uint32_t a;
    asm("{ .reg .u64 t; cvta.to.shared.u64 t, %1; cvt.u32.u64 %0, t; }"
        : "=r"(a) : "l"(p));
    return a;
}
__device__ __forceinline__ void cp_async16(uint32_t dst, const void* src) {
    asm volatile("cp.async.cg.shared.global [%0], [%1], 16;"
        :: "r"(dst), "l"(src) : "memory");
}
__device__ __forceinline__ void ldm4(uint32_t* r, uint32_t addr) {
    asm volatile("ldmatrix.sync.aligned.m8n8.x4.shared.b16 {%0,%1,%2,%3}, [%4];"
        : "=r"(r[0]), "=r"(r[1]), "=r"(r[2]), "=r"(r[3]) : "r"(addr));
}
__device__ __forceinline__ void mma16816(float* c, const uint32_t* a, const uint32_t* b) {
    asm volatile("mma.sync.aligned.m16n8k16.row.col.f32.bf16.bf16.f32 "
        "{%0,%1,%2,%3}, {%4,%5,%6,%7}, {%8,%9}, {%0,%1,%2,%3};"
        : "+f"(c[0]), "+f"(c[1]), "+f"(c[2]), "+f"(c[3])
        : "r"(a[0]), "r"(a[1]), "r"(a[2]), "r"(a[3]), "r"(b[0]), "r"(b[1]));
}

// ---------------------------------------------------------------------------
// misc helpers
// ---------------------------------------------------------------------------
__device__ __forceinline__ float warp_sum(float v) {
    #pragma unroll
    for (int o = 16; o; o >>= 1) v += __shfl_xor_sync(0xffffffffu, v, o);
    return v;
}
__device__ __forceinline__ int window_row(int bt) {
    int bb = bt >> 14;
    int t  = bt & 16383;
    int hh = t >> 9;
    int ww = (t >> 4) & 31;
    int ll = t & 15;
    int win = bb * NWIN_B + (((hh >> 3) * 4 + (ww >> 3)) * 2 + (ll >> 3));
    int n   = (((hh & 7) << 3) + (ww & 7)) * 8 + (ll & 7);
    return win * WN + n;
}
__device__ __forceinline__ void split_bf16(float v, __nv_bfloat16& h, __nv_bfloat16& l) {
    h = __float2bfloat16(v);
    l = __float2bfloat16(v - __bfloat162float(h));
}
// fast x^p for x >= 0 (x==0 -> lg2 gives -inf -> ex2 gives 0)
__device__ __forceinline__ float fast_pow(float m, float p) {
    float lg, r;
    asm("lg2.approx.f32 %0, %1;" : "=f"(lg) : "f"(m));
    asm("ex2.approx.f32 %0, %1;" : "=f"(r) : "f"(p * lg));
    return r;
}

// ---------------------------------------------------------------------------
// fp32 -> bf16 hi/lo split conversion (vectorized by 4)
// ---------------------------------------------------------------------------
__global__ void __launch_bounds__(256) cvt_kernel(
    const float4* __restrict__ in, uint2* __restrict__ hi,
    uint2* __restrict__ lo, int n4)
{
    int i = blockIdx.x * blockDim.x + threadIdx.x;
    if (i >= n4) return;
    float4 v = in[i];
    __nv_bfloat16 h0, h1, h2, h3, l0, l1, l2, l3;
    split_bf16(v.x, h0, l0); split_bf16(v.y, h1, l1);
    split_bf16(v.z, h2, l2); split_bf16(v.w, h3, l3);
    __nv_bfloat162 ph0; ph0.x = h0; ph0.y = h1;
    __nv_bfloat162 ph1; ph1.x = h2; ph1.y = h3;
    __nv_bfloat162 pl0; pl0.x = l0; pl0.y = l1;
    __nv_bfloat162 pl1; pl1.x = l2; pl1.y = l3;
    uint2 uh; uh.x = *(uint32_t*)&ph0; uh.y = *(uint32_t*)&ph1;
    uint2 ul; ul.x = *(uint32_t*)&pl0; ul.y = *(uint32_t*)&pl1;
    hi[i] = uh; lo[i] = ul;
}

// ---------------------------------------------------------------------------
// LayerNorm fused with window partition -> bf16 hi/lo planes
// ---------------------------------------------------------------------------
__global__ void __launch_bounds__(256) ln_win_kernel(
    const float* __restrict__ x, const float* __restrict__ g,
    const float* __restrict__ b, __nv_bfloat16* __restrict__ oh,
    __nv_bfloat16* __restrict__ ol)
{
    int warp = (blockIdx.x * blockDim.x + threadIdx.x) >> 5;
    int lane = threadIdx.x & 31;
    if (warp >= BTROWS) return;
    const float* xr = x + (size_t)warp * CDIM;
    float v[12];
    float s = 0.f;
    #pragma unroll
    for (int i = 0; i < 12; i++) { v[i] = xr[lane + i * 32]; s += v[i]; }
    s = warp_sum(s);
    float mu = s * (1.f / 384.f);
    float sq = 0.f;
    #pragma unroll
    for (int i = 0; i < 12; i++) { float dv = v[i] - mu; sq += dv * dv; }
    sq = warp_sum(sq);
    float rstd = rsqrtf(sq * (1.f / 384.f) + 1e-5f);
    size_t ro = (size_t)window_row(warp) * CDIM;
    #pragma unroll
    for (int i = 0; i < 12; i++) {
        int c = lane + i * 32;
        float o = (v[i] - mu) * rstd * g[c] + b[c];
        __nv_bfloat16 h, l; split_bf16(o, h, l);
        oh[ro + c] = h; ol[ro + c] = l;
    }
}

// ---------------------------------------------------------------------------
// residual-add (window_reverse) + LN2 -> x2 fp32, hn bf16 hi/lo
// ---------------------------------------------------------------------------
__global__ void __launch_bounds__(256) resln_kernel(
    const float* __restrict__ x, const float* __restrict__ aw,
    const float* __restrict__ g, const float* __restrict__ b,
    float* __restrict__ x2, __nv_bfloat16* __restrict__ hh,
    __nv_bfloat16* __restrict__ hl)
{
    int warp = (blockIdx.x * blockDim.x + threadIdx.x) >> 5;
    int lane = threadIdx.x & 31;
    if (warp >= BTROWS) return;
    const float* xr = x  + (size_t)warp * CDIM;
    const float* ar = aw + (size_t)window_row(warp) * CDIM;
    float v[12];
    float s = 0.f;
    #pragma unroll
    for (int i = 0; i < 12; i++) {
        int c = lane + i * 32;
        v[i] = xr[c] + ar[c];
        s += v[i];
    }
    s = warp_sum(s);
    float mu = s * (1.f / 384.f);
    float sq = 0.f;
    #pragma unroll
    for (int i = 0; i < 12; i++) { float dv = v[i] - mu; sq += dv * dv; }
    sq = warp_sum(sq);
    float rstd = rsqrtf(sq * (1.f / 384.f) + 1e-5f);
    size_t ro = (size_t)warp * CDIM;
    #pragma unroll
    for (int i = 0; i < 12; i++) {
        int c = lane + i * 32;
        x2[ro + c] = v[i];
        float o = (v[i] - mu) * rstd * g[c] + b[c];
        __nv_bfloat16 h, l; split_bf16(o, h, l);
        hh[ro + c] = h; hl[ro + c] = l;
    }
}

// ---------------------------------------------------------------------------
// mma.sync GEMM: C[M,N] = A[M,K] @ W[N,K]^T (+ bias / gelu / residual)
// bf16-split (3 MMA passes). BM=BN=128, BK=32. 256 threads, 8 warps (2Mx4N),
// warp tile 64x32, m16n8k16. cp.async 3-stage pipeline, XOR-swizzled smem.
// EPI: 0 = bias->fp32 C, 1 = bias+gelu->bf16 hi/lo planes, 2 = bias+res->fp32 C
// ---------------------------------------------------------------------------
#define GSTAGE 32768
#define GSMEM_BYTES (3*GSTAGE)

template <int EPI>
__global__ void __launch_bounds__(256, 1) mma_gemm(
    const __nv_bfloat16* __restrict__ Ah, const __nv_bfloat16* __restrict__ Al,
    const __nv_bfloat16* __restrict__ Bh, const __nv_bfloat16* __restrict__ Bl,
    const float* __restrict__ bias, const float* __restrict__ res,
    float* __restrict__ C, __nv_bfloat16* __restrict__ Ch,
    __nv_bfloat16* __restrict__ Cl, int N, int K)
{
    extern __shared__ char smem[];
    const uint32_t sbase = smem_u32(smem);
    const int tid  = threadIdx.x;
    const int lane = tid & 31;
    const int wid  = tid >> 5;
    const int wm   = wid & 1;    // 0..1
    const int wn   = wid >> 1;   // 0..3
    const int bm = blockIdx.y * 128;
    const int bn = blockIdx.x * 128;

    float acc[4][4][4];
    #pragma unroll
    for (int i = 0; i < 4; i++)
        #pragma unroll
        for (int j = 0; j < 4; j++)
            #pragma unroll
            for (int q = 0; q < 4; q++) acc[i][j][q] = 0.f;

    // ---- stage loader: 4 sub-tiles (Ah,Al,Bh,Bl) 128x32 bf16, swizzled ----
    #define LOAD_STAGE(stage, k0) do {                                        \
        uint32_t sb_ = sbase + (uint32_t)(stage) * GSTAGE;                    \
        const __nv_bfloat16* bases_[4] = {Ah, Al, Bh, Bl};                    \
        _Pragma("unroll")                                                     \
        for (int sub_ = 0; sub_ < 4; sub_++) {                                \
            const __nv_bfloat16* bp_ = bases_[sub_];                          \
            int ro_ = (sub_ < 2) ? bm : bn;                                   \
            _Pragma("unroll")                                                 \
            for (int jj_ = 0; jj_ < 2; jj_++) {                               \
                int cid_ = tid + 256 * jj_;                                   \
                int row_ = cid_ >> 2, ck_ = cid_ & 3;                         \
                int cs_ = ck_ ^ ((row_ >> 1) & 3);                            \
                const void* src_ = bp_ + (size_t)(ro_ + row_) * K + (k0) + ck_ * 8; \
                cp_async16(sb_ + (uint32_t)(sub_ << 13)                       \
                           + (uint32_t)(row_ * 64 + cs_ * 16), src_);         \
            }                                                                 \
        }                                                                     \
    } while (0)

    const int NC = K >> 5;
    LOAD_STAGE(0, 0);
    asm volatile("cp.async.commit_group;" ::: "memory");
    LOAD_STAGE(1, 32);
    asm volatile("cp.async.commit_group;" ::: "memory");

    // ldmatrix address precompute
    const int arow = wm * 64 + (lane & 15);
    const int asel = lane >> 4;
    const int brow = wn * 32 + ((lane >> 4) << 3) + (lane & 7);
    const int bsel = (lane >> 3) & 1;

    int scur = 0;   // compute stage
    int sld  = 2;   // next load stage
    for (int c = 0; c < NC; c++) {
        if (c + 1 < NC) {
            asm volatile("cp.async.wait_group 1;" ::: "memory");
        } else {
            asm volatile("cp.async.wait_group 0;" ::: "memory");
        }
        __syncthreads();
        if (c + 2 < NC) {
            LOAD_STAGE(sld, (c + 2) << 5);
            asm volatile("cp.async.commit_group;" ::: "memory");
            sld = (sld == 2) ? 0 : sld + 1;
        }

        const uint32_t sb = sbase + (uint32_t)scur * GSTAGE;
        scur = (scur == 2) ? 0 : scur + 1;
        #pragma unroll
        for (int kk = 0; kk < 2; kk++) {
            uint32_t ah[4][4], al[4][4], bh[2][4], bl[2][4];
            #pragma unroll
            for (int mt = 0; mt < 4; mt++) {
                int row = arow + mt * 16;
                int ck  = kk * 2 + asel;
                uint32_t off = (uint32_t)(row * 64 + (ck ^ ((row >> 1) & 3)) * 16);
                ldm4(ah[mt], sb + off);
                ldm4(al[mt], sb + 8192u + off);
            }
            #pragma unroll
            for (int bt = 0; bt < 2; bt++) {
                int row = brow + bt * 16;
                int ck  = kk * 2 + bsel;
                uint32_t off = (uint32_t)(row * 64 + (ck ^ ((row >> 1) & 3)) * 16);
                ldm4(bh[bt], sb + 16384u + off);
                ldm4(bl[bt], sb + 24576u + off);
            }
            #pragma unroll
            for (int mt = 0; mt < 4; mt++) {
                #pragma unroll
                for (int nt = 0; nt < 4; nt++) {
                    const uint32_t* bhf = &bh[nt >> 1][(nt & 1) * 2];
                    const uint32_t* blf = &bl[nt >> 1][(nt & 1) * 2];
                    mma16816(acc[mt][nt], ah[mt], bhf);
                    mma16816(acc[mt][nt], ah[mt], blf);
                    mma16816(acc[mt][nt], al[mt], bhf);
                }
            }
        }
    }

    // ---- epilogue ----
    const int gr = lane >> 2;
    const int nc0 = (lane & 3) * 2;
    #pragma unroll
    for (int mt = 0; mt < 4; mt++) {
        #pragma unroll
        for (int nt = 0; nt < 4; nt++) {
            int col = bn + wn * 32 + nt * 8 + nc0;
            float bs0 = bias[col], bs1 = bias[col + 1];
            #pragma unroll
            for (int half = 0; half < 2; half++) {
                int row = bm + wm * 64 + mt * 16 + gr + half * 8;
                float v0 = acc[mt][nt][half * 2 + 0] + bs0;
                float v1 = acc[mt][nt][half * 2 + 1] + bs1;
                size_t off = (size_t)row * N + col;
                if (EPI == 1) {
                    v0 = 0.5f * v0 * (1.f + erff(v0 * 0.70710678118654752f));
                    v1 = 0.5f * v1 * (1.f + erff(v1 * 0.70710678118654752f));
                    __nv_bfloat16 h0, l0, h1, l1;
                    split_bf16(v0, h0, l0); split_bf16(v1, h1, l1);
                    __nv_bfloat162 ph; ph.x = h0; ph.y = h1;
                    __nv_bfloat162 pl; pl.x = l0; pl.y = l1;
                    *(uint32_t*)(Ch + off) = *(uint32_t*)&ph;
                    *(uint32_t*)(Cl + off) = *(uint32_t*)&pl;
                } else {
                    if (EPI == 2) { v0 += res[off]; v1 += res[off + 1]; }
                    float2 o; o.x = v0; o.y = v1;
                    *(float2*)(C + off) = o;
                }
            }
        }
    }
    #undef LOAD_STAGE
}

// ---------------------------------------------------------------------------
// Pola linear attention, one block per (window, head). 256 threads.
// Restructured: kv pass + q pass as shared-mem GEMMs, fast pow.
// ---------------------------------------------------------------------------
__global__ void __launch_bounds__(256) attn_kernel(
    const float* __restrict__ kvg, const float* __restrict__ qb,
    const float* __restrict__ pos_enc, const float* __restrict__ scale_p,
    const float* __restrict__ power_p, float* __restrict__ xo)
{
    const int wg = blockIdx.x;   // 0..63
    const int h  = blockIdx.y;   // 0..11
    const int tid = threadIdx.x;

    __shared__ float sc_s[32], pw_s[32];
    __shared__ float buf[64][65];    // kc (phase A) / qf (phase C)
    __shared__ float vm[64][32];     // v (phase A) / M (phase C)
    __shared__ float km2_s[2][64];   // z feature vectors
    __shared__ float z_s[64][2];

    if (tid < 32) {
        float sp = scale_p[h * 32 + tid];
        sc_s[tid] = 1.f / log1pf(expf(sp));          // 1/softplus
        float pp = power_p[h * 32 + tid];
        pw_s[tid] = 1.f + 4.f / (1.f + expf(-pp));   // 1 + ALPHA*sigmoid
    }
    __syncthreads();

    const int f0 = (tid >> 3) << 1;   // 0,2,..,62
    const int vc = (tid & 7) << 2;    // 0,4,..,28

    float kv00 = 0.f, kv01 = 0.f, kv02 = 0.f, kv03 = 0.f;
    float kv10 = 0.f, kv11 = 0.f, kv12 = 0.f, kv13 = 0.f;
    float ksum = 0.f;

    // -------- phase A: kc features, kv = kc^T v, ksum --------
    for (int c0 = 0; c0 < WN; c0 += 64) {
        #pragma unroll
        for (int i = 0; i < 8; i++) {
            int idx = tid + 256 * i;
            int nl = idx >> 5;
            int d  = idx & 31;
            int row = wg * WN + c0 + nl;
            float kval = (kvg[(size_t)row * KVGC + h * 32 + d]
                          + pos_enc[(c0 + nl) * CDIM + h * 32 + d]) * sc_s[d];
            float r = fast_pow(fabsf(kval), pw_s[d]);
            buf[nl][d]      = kval > 0.f ? r : 0.f;
            buf[nl][d + 32] = kval < 0.f ? r : 0.f;
            vm[nl][d] = kvg[(size_t)row * KVGC + 384 + h * 32 + d];
        }
        __syncthreads();
        #pragma unroll 4
        for (int n = 0; n < 64; n++) {
            float k0 = buf[n][f0];
            float k1 = buf[n][f0 + 1];
            float4 v4 = *(const float4*)&vm[n][vc];
            kv00 += k0 * v4.x; kv01 += k0 * v4.y;
            kv02 += k0 * v4.z; kv03 += k0 * v4.w;
            kv10 += k1 * v4.x; kv11 += k1 * v4.y;
            kv12 += k1 * v4.z; kv13 += k1 * v4.w;
        }
        if (tid < 64) {
            float s = ksum;
            #pragma unroll 8
            for (int n = 0; n < 64; n++) s += buf[n][tid];
            ksum = s;
        }
        __syncthreads();
    }

    // -------- finalize: write M (reordered kv) and km vectors --------
    // M[g][d<16]  = kv[g][d]          (sim branch)
    // M[g][d>=16] = kv[(g+32)&63][d]  (opp branch folded)
    {
        const float sN2 = 1.f / 512.f;
        int fr0 = (vc < 16) ? f0 : ((f0 + 32) & 63);
        vm[fr0][vc + 0] = kv00 * sN2; vm[fr0][vc + 1] = kv01 * sN2;
        vm[fr0][vc + 2] = kv02 * sN2; vm[fr0][vc + 3] = kv03 * sN2;
        int fr1 = (vc < 16) ? (f0 + 1) : ((f0 + 33) & 63);
        vm[fr1][vc + 0] = kv10 * sN2; vm[fr1][vc + 1] = kv11 * sN2;
        vm[fr1][vc + 2] = kv12 * sN2; vm[fr1][vc + 3] = kv13 * sN2;
        if (tid < 64) {
            float km = ksum * sN2;
            km2_s[0][tid] = km;
            km2_s[1][(tid + 32) & 63] = km;
        }
    }
    __syncthreads();

    // -------- phase C: q features + O = qf @ M, z, write --------
    const int n0 = (tid >> 3) << 1;   // 0,2,..,62
    for (int c0 = 0; c0 < WN; c0 += 64) {
        #pragma unroll
        for (int i = 0; i < 8; i++) {
            int idx = tid + 256 * i;
            int nl = idx >> 5;
            int d  = idx & 31;
            int row = wg * WN + c0 + nl;
            float qv = qb[(size_t)row * CDIM + h * 32 + d] * sc_s[d];
            float r = fast_pow(fabsf(qv), pw_s[d]);
            buf[nl][d]      = qv > 0.f ? r : 0.f;
            buf[nl][d + 32] = qv < 0.f ? r : 0.f;
        }
        __syncthreads();

        float a00 = 0.f, a01 = 0.f, a02 = 0.f, a03 = 0.f;
        float a10 = 0.f, a11 = 0.f, a12 = 0.f, a13 = 0.f;
        #pragma unroll 4
        for (int f = 0; f < 64; f++) {
            float q0 = buf[n0][f];
            float q1 = buf[n0 + 1][f];
            float4 m = *(const float4*)&vm[f][vc];
            a00 += q0 * m.x; a01 += q0 * m.y; a02 += q0 * m.z; a03 += q0 * m.w;
            a10 += q1 * m.x; a11 += q1 * m.y; a12 += q1 * m.z; a13 += q1 * m.w;
        }
        if (tid < 128) {
            int n = tid >> 1, zi = tid & 1;
            float z = 1e-6f;
            #pragma unroll 8
            for (int f = 0; f < 64; f++) z += buf[n][f] * km2_s[zi][f];
            z_s[n][zi] = z;
        }
        __syncthreads();

        int zi = (vc >= 16) ? 1 : 0;
        float rz0 = 1.f / z_s[n0][zi];
        float rz1 = 1.f / z_s[n0 + 1][zi];
        size_t base0 = (size_t)(wg * WN + c0 + n0) * CDIM + h * 32 + vc;
        float4 o0; o0.x = a00 * rz0; o0.y = a01 * rz0; o0.z = a02 * rz0; o0.w = a03 * rz0;
        float4 o1; o1.x = a10 * rz1; o1.y = a11 * rz1; o1.z = a12 * rz1; o1.w = a13 * rz1;
        *(float4*)&xo[base0] = o0;
        *(float4*)&xo[base0 + CDIM] = o1;
        __syncthreads();
    }
}

// ---------------------------------------------------------------------------
// Depthwise 5^3 conv + (xo + vv) * g -> bf16 hi/lo planes
// ---------------------------------------------------------------------------
__global__ void __launch_bounds__(256) dwconv_kernel(
    const float* __restrict__ kvg, const float* __restrict__ dwc_w,
    const float* __restrict__ dwc_b, const float* __restrict__ xo,
    __nv_bfloat16* __restrict__ xoh, __nv_bfloat16* __restrict__ xol)
{
    extern __shared__ float sm[];
    float* v_s = sm;
    float* w_s = sm + 512 * 32;
    const int bh = blockIdx.x;
    const int b_ = bh / NHEADS, h = bh % NHEADS;
    const int tid = threadIdx.x;

    for (int i = tid; i < 512 * 32; i += 256) {
        int n = i >> 5, d = i & 31;
        v_s[i] = kvg[(size_t)(b_ * WN + n) * KVGC + 384 + h * 32 + d];
    }
    for (int i = tid; i < 125 * 32; i += 256) w_s[i] = dwc_w[i];
    __syncthreads();

    const int d  = tid & 31;
    const int lo = tid >> 5;
    const float bval = dwc_b[d];
    const size_t base = (size_t)b_ * (WN * CDIM) + (size_t)h * (WN * HD);

    for (int jg = 0; jg < 4; jg++) {
        float acc[16];
        #pragma unroll
        for (int jj = 0; jj < 16; jj++) acc[jj] = bval;
        for (int kd = 0; kd < 5; kd++) {
            for (int kh = 0; kh < 5; kh++) {
                for (int kw = 0; kw < 5; kw++) {
                    int li = lo + kw - 2;
                    if (li < 0 || li > 7) continue;
                    float w = w_s[((kd * 5 + kh) * 5 + kw) * 32 + d];
                    #pragma unroll
                    for (int jj = 0; jj < 16; jj++) {
                        int j = jg * 16 + jj;
                        int hi = (j >> 3) + kd - 2;
                        int wi = (j & 7) + kh - 2;
                        if (hi < 0 || hi > 7 || wi < 0 || wi > 7) continue;
                        acc[jj] += v_s[((hi * 8 + wi) * 8 + li) * 32 + d] * w;
                    }
                }
            }
        }
        #pragma unroll
        for (int jj = 0; jj < 16; jj++) {
            int j = jg * 16 + jj;
            size_t flat = base + (size_t)(lo + 8 * j) * 32 + d;
            size_t grow = flat / CDIM;
            int    gcol = (int)(flat % CDIM);
            float g = kvg[grow * KVGC + 768 + gcol];
            float val = (xo[flat] + acc[jj]) * g;
            __nv_bfloat16 hh, ll; split_bf16(val, hh, ll);
            xoh[flat] = hh; xol[flat] = ll;
        }
    }
}

// ---------------------------------------------------------------------------
// kernel_launch
// ---------------------------------------------------------------------------
extern "C" void kernel_launch(void* const* d_in, const int* in_sizes, int n_in,
                              void* d_out, int out_size)
{
    const float* x       = (const float*)d_in[0];
    const float* y       = (const float*)d_in[1];
    const float* w_qkvg  = (const float*)d_in[2];
    const float* b_qkvg  = (const float*)d_in[3];
    const float* w_proj  = (const float*)d_in[4];
    const float* b_proj  = (const float*)d_in[5];
    const float* dwc_w   = (const float*)d_in[6];
    const float* dwc_b   = (const float*)d_in[7];
    const float* power_p = (const float*)d_in[8];
    const float* scale_p = (const float*)d_in[9];
    const float* pos_enc = (const float*)d_in[10];
    const float* g1      = (const float*)d_in[11];
    const float* b1      = (const float*)d_in[12];
    const float* g2      = (const float*)d_in[13];
    const float* b2      = (const float*)d_in[14];
    const float* w_fc1   = (const float*)d_in[15];
    const float* b_fc1   = (const float*)d_in[16];
    const float* w_fc2   = (const float*)d_in[17];
    const float* b_fc2   = (const float*)d_in[18];
    float* out = (float*)d_out;

    __nv_bfloat16 *p_xwh, *p_xwl, *p_ywh, *p_ywl, *p_hnh, *p_hnl;
    __nv_bfloat16 *p_xoh, *p_xol, *p_h1h, *p_h1l;
    __nv_bfloat16 *p_wqh, *p_wql, *p_wph, *p_wpl, *p_w1h, *p_w1l, *p_w2h, *p_w2l;
    float *p_kvg, *p_qb, *p_xo, *p_aw, *p_x2;
    cudaGetSymbolAddress((void**)&p_xwh, d_xwh);
    cudaGetSymbolAddress((void**)&p_xwl, d_xwl);
    cudaGetSymbolAddress((void**)&p_ywh, d_ywh);
    cudaGetSymbolAddress((void**)&p_ywl, d_ywl);
    cudaGetSymbolAddress((void**)&p_hnh, d_hnh);
    cudaGetSymbolAddress((void**)&p_hnl, d_hnl);
    cudaGetSymbolAddress((void**)&p_xoh, d_xoh);
    cudaGetSymbolAddress((void**)&p_xol, d_xol);
    cudaGetSymbolAddress((void**)&p_h1h, d_h1h);
    cudaGetSymbolAddress((void**)&p_h1l, d_h1l);
    cudaGetSymbolAddress((void**)&p_wqh, d_wqh);
    cudaGetSymbolAddress((void**)&p_wql, d_wql);
    cudaGetSymbolAddress((void**)&p_wph, d_wph);
    cudaGetSymbolAddress((void**)&p_wpl, d_wpl);
    cudaGetSymbolAddress((void**)&p_w1h, d_w1h);
    cudaGetSymbolAddress((void**)&p_w1l, d_w1l);
    cudaGetSymbolAddress((void**)&p_w2h, d_w2h);
    cudaGetSymbolAddress((void**)&p_w2l, d_w2l);
    cudaGetSymbolAddress((void**)&p_kvg, d_kvg);
    cudaGetSymbolAddress((void**)&p_qb,  d_qb);
    cudaGetSymbolAddress((void**)&p_xo,  d_xo);
    cudaGetSymbolAddress((void**)&p_aw,  d_aw);
    cudaGetSymbolAddress((void**)&p_x2,  d_x2);

    const int conv_smem = (512 * 32 + 125 * 32) * (int)sizeof(float);
    cudaFuncSetAttribute(dwconv_kernel,
                         cudaFuncAttributeMaxDynamicSharedMemorySize, conv_smem);
    cudaFuncSetAttribute(mma_gemm<0>,
                         cudaFuncAttributeMaxDynamicSharedMemorySize, GSMEM_BYTES);
    cudaFuncSetAttribute(mma_gemm<1>,
                         cudaFuncAttributeMaxDynamicSharedMemorySize, GSMEM_BYTES);
    cudaFuncSetAttribute(mma_gemm<2>,
                         cudaFuncAttributeMaxDynamicSharedMemorySize, GSMEM_BYTES);

    // 0) weight splits
    cvt_kernel<<<(1536*384/4 + 255)/256, 256>>>((const float4*)w_qkvg,
        (uint2*)p_wqh, (uint2*)p_wql, 1536*384/4);
    cvt_kernel<<<(384*384/4 + 255)/256, 256>>>((const float4*)w_proj,
        (uint2*)p_wph, (uint2*)p_wpl, 384*384/4);
    cvt_kernel<<<(1536*384/4 + 255)/256, 256>>>((const float4*)w_fc1,
        (uint2*)p_w1h, (uint2*)p_w1l, 1536*384/4);
    cvt_kernel<<<(384*1536/4 + 255)/256, 256>>>((const float4*)w_fc2,
        (uint2*)p_w2h, (uint2*)p_w2l, 384*1536/4);

    // 1) LN + window partition -> bf16 splits
    ln_win_kernel<<<BTROWS / 8, 256>>>(x, g1, b1, p_xwh, p_xwl);
    ln_win_kernel<<<BTROWS / 8, 256>>>(y, g1, b1, p_ywh, p_ywl);

    // 2) kvg = xw @ W[384:1536]^T + b[384:]   (N=1152, K=384)
    mma_gemm<0><<<dim3(KVGC/128, BTROWS/128), 256, GSMEM_BYTES>>>(
        p_xwh, p_xwl, p_wqh + 384*384, p_wql + 384*384, b_qkvg + 384,
        nullptr, p_kvg, nullptr, nullptr, KVGC, 384);

    // 3) q = yw @ W[0:384]^T + b[0:384]
    mma_gemm<0><<<dim3(CDIM/128, BTROWS/128), 256, GSMEM_BYTES>>>(
        p_ywh, p_ywl, p_wqh, p_wql, b_qkvg,
        nullptr, p_qb, nullptr, nullptr, CDIM, 384);

    // 4) attention -> xo
    attn_kernel<<<dim3(NWIN, NHEADS), 256>>>(p_kvg, p_qb, pos_enc,
                                             scale_p, power_p, p_xo);

    // 5) depthwise conv + gating -> bf16 splits
    dwconv_kernel<<<NWIN * NHEADS, 256, conv_smem>>>(p_kvg, dwc_w, dwc_b,
                                                     p_xo, p_xoh, p_xol);

    // 6) aw = xo @ w_proj^T + b_proj
    mma_gemm<0><<<dim3(CDIM/128, BTROWS/128), 256, GSMEM_BYTES>>>(
        p_xoh, p_xol, p_wph, p_wpl, b_proj,
        nullptr, p_aw, nullptr, nullptr, CDIM, 384);

    // 7) x2 = x + window_reverse(aw); hn = LN2(x2) -> bf16 splits
    resln_kernel<<<BTROWS / 8, 256>>>(x, p_aw, g2, b2, p_x2, p_hnh, p_hnl);

    // 8) h1 = gelu(hn @ w_fc1^T + b_fc1) -> bf16 splits   (N=1536, K=384)
    mma_gemm<1><<<dim3(HIDDEN/128, BTROWS/128), 256, GSMEM_BYTES>>>(
        p_hnh, p_hnl, p_w1h, p_w1l, b_fc1,
        nullptr, nullptr, p_h1h, p_h1l, HIDDEN, 384);

    // 9) out = x2 + h1 @ w_fc2^T + b_fc2    (N=384, K=1536)
    mma_gemm<2><<<dim3(CDIM/128, BTROWS/128), 256, GSMEM_BYTES>>>(
        p_h1h, p_h1l, p_w2h, p_w2l, b_fc2,
        p_x2, out, nullptr, nullptr, CDIM, 1536);
}

// round 6
// speedup vs baseline: 3.3964x; 1.4102x over previous
#include <cuda_runtime.h>
#include <cuda_fp16.h>
#include <math.h>
#include <stdint.h>

// ---------------------------------------------------------------------------
// Problem constants
// ---------------------------------------------------------------------------
#define BATCH   2
#define RES_H   32
#define RES_W   32
#define RES_L   16
#define WSZ     8
#define CDIM    384
#define NHEADS  12
#define HD      32
#define NTOK    (RES_H*RES_W*RES_L)       // 16384
#define BTROWS  (BATCH*NTOK)              // 32768
#define NWIN_B  ((RES_H/WSZ)*(RES_W/WSZ)*(RES_L/WSZ))  // 32
#define NWIN    (BATCH*NWIN_B)            // 64
#define WN      (WSZ*WSZ*WSZ)             // 512
#define KVGC    1152
#define HIDDEN  1536

// ---------------------------------------------------------------------------
// Scratch (static device globals)
// ---------------------------------------------------------------------------
static __device__ __align__(256) __half d_xw16[BTROWS*CDIM];
static __device__ __align__(256) __half d_yw16[BTROWS*CDIM];
static __device__ __align__(256) __half d_hn16[BTROWS*CDIM];
static __device__ __align__(256) __half d_xo16[BTROWS*CDIM];
static __device__ __align__(256) __half d_h116[BTROWS*HIDDEN];
static __device__ __align__(256) __half d_wqh[1536*384];
static __device__ __align__(256) __half d_wql[1536*384];
static __device__ __align__(256) __half d_wph[384*384];
static __device__ __align__(256) __half d_wpl[384*384];
static __device__ __align__(256) __half d_w1h[1536*384];
static __device__ __align__(256) __half d_w1l[1536*384];
static __device__ __align__(256) __half d_w2h[384*1536];
static __device__ __align__(256) __half d_w2l[384*1536];

static __device__ float d_kvg[BTROWS*KVGC];
static __device__ float d_qb [BTROWS*CDIM];
static __device__ float d_xo [BTROWS*CDIM];
static __device__ float d_aw [BTROWS*CDIM];
static __device__ float d_x2 [BTROWS*CDIM];

// ---------------------------------------------------------------------------
// PTX helpers (arch-portable: cp.async / ldmatrix / mma.sync only)
// ---------------------------------------------------------------------------
__device__ __forceinline__ uint32_t smem_u32(const void* p) {
    uint32_t a;
    asm("{ .reg .u64 t; cvta.to.shared.u64 t, %1; cvt.u32.u64 %0, t; }"
        : "=r"(a) : "l"(p));
    return a;
}
__device__ __forceinline__ void cp_async16(uint32_t dst, const void* src) {
    asm volatile("cp.async.cg.shared.global [%0], [%1], 16;"
        :: "r"(dst), "l"(src) : "memory");
}
__device__ __forceinline__ void ldm4(uint32_t* r, uint32_t addr) {
    asm volatile("ldmatrix.sync.aligned.m8n8.x4.shared.b16 {%0,%1,%2,%3}, [%4];"
        : "=r"(r[0]), "=r"(r[1]), "=r"(r[2]), "=r"(r[3]) : "r"(addr));
}
__device__ __forceinline__ void mma16816(float* c, const uint32_t* a, const uint32_t* b) {
    asm volatile("mma.sync.aligned.m16n8k16.row.col.f32.f16.f16.f32 "
        "{%0,%1,%2,%3}, {%4,%5,%6,%7}, {%8,%9}, {%0,%1,%2,%3};"
        : "+f"(c[0]), "+f"(c[1]), "+f"(c[2]), "+f"(c[3])
        : "r"(a[0]), "r"(a[1]), "r"(a[2]), "r"(a[3]), "r"(b[0]), "r"(b[1]));
}

// ---------------------------------------------------------------------------
// misc helpers
// ---------------------------------------------------------------------------
__device__ __forceinline__ float warp_sum(float v) {
    #pragma unroll
    for (int o = 16; o; o >>= 1) v += __shfl_xor_sync(0xffffffffu, v, o);
    return v;
}
__device__ __forceinline__ int window_row(int bt) {
    int bb = bt >> 14;
    int t  = bt & 16383;
    int hh = t >> 9;
    int ww = (t >> 4) & 31;
    int ll = t & 15;
    int win = bb * NWIN_B + (((hh >> 3) * 4 + (ww >> 3)) * 2 + (ll >> 3));
    int n   = (((hh & 7) << 3) + (ww & 7)) * 8 + (ll & 7);
    return win * WN + n;
}
__device__ __forceinline__ void split_h16(float v, __half& h, __half& l) {
    h = __float2half(v);
    l = __float2half(v - __half2float(h));
}
// fast x^p for x >= 0 (x==0 -> lg2 gives -inf -> ex2 gives 0)
__device__ __forceinline__ float fast_pow(float m, float p) {
    float lg, r;
    asm("lg2.approx.f32 %0, %1;" : "=f"(lg) : "f"(m));
    asm("ex2.approx.f32 %0, %1;" : "=f"(r) : "f"(p * lg));
    return r;
}

// ---------------------------------------------------------------------------
// weights: fp32 -> fp16 hi/lo split (vectorized by 4)
// ---------------------------------------------------------------------------
__global__ void __launch_bounds__(256) cvt_kernel(
    const float4* __restrict__ in, uint2* __restrict__ hi,
    uint2* __restrict__ lo, int n4)
{
    int i = blockIdx.x * blockDim.x + threadIdx.x;
    if (i >= n4) return;
    float4 v = in[i];
    __half h0, h1, h2, h3, l0, l1, l2, l3;
    split_h16(v.x, h0, l0); split_h16(v.y, h1, l1);
    split_h16(v.z, h2, l2); split_h16(v.w, h3, l3);
    __half2 ph0 = __halves2half2(h0, h1);
    __half2 ph1 = __halves2half2(h2, h3);
    __half2 pl0 = __halves2half2(l0, l1);
    __half2 pl1 = __halves2half2(l2, l3);
    uint2 uh; uh.x = *(uint32_t*)&ph0; uh.y = *(uint32_t*)&ph1;
    uint2 ul; ul.x = *(uint32_t*)&pl0; ul.y = *(uint32_t*)&pl1;
    hi[i] = uh; lo[i] = ul;
}

// ---------------------------------------------------------------------------
// LayerNorm fused with window partition -> single fp16 plane
// ---------------------------------------------------------------------------
__global__ void __launch_bounds__(256) ln_win_kernel(
    const float* __restrict__ x, const float* __restrict__ g,
    const float* __restrict__ b, __half* __restrict__ o16)
{
    int warp = (blockIdx.x * blockDim.x + threadIdx.x) >> 5;
    int lane = threadIdx.x & 31;
    if (warp >= BTROWS) return;
    const float* xr = x + (size_t)warp * CDIM;
    float v[12];
    float s = 0.f;
    #pragma unroll
    for (int i = 0; i < 12; i++) { v[i] = xr[lane + i * 32]; s += v[i]; }
    s = warp_sum(s);
    float mu = s * (1.f / 384.f);
    float sq = 0.f;
    #pragma unroll
    for (int i = 0; i < 12; i++) { float dv = v[i] - mu; sq += dv * dv; }
    sq = warp_sum(sq);
    float rstd = rsqrtf(sq * (1.f / 384.f) + 1e-5f);
    size_t ro = (size_t)window_row(warp) * CDIM;
    #pragma unroll
    for (int i = 0; i < 12; i++) {
        int c = lane + i * 32;
        float o = (v[i] - mu) * rstd * g[c] + b[c];
        o16[ro + c] = __float2half(o);
    }
}

// ---------------------------------------------------------------------------
// residual-add (window_reverse) + LN2 -> x2 fp32, hn fp16
// ---------------------------------------------------------------------------
__global__ void __launch_bounds__(256) resln_kernel(
    const float* __restrict__ x, const float* __restrict__ aw,
    const float* __restrict__ g, const float* __restrict__ b,
    float* __restrict__ x2, __half* __restrict__ hn)
{
    int warp = (blockIdx.x * blockDim.x + threadIdx.x) >> 5;
    int lane = threadIdx.x & 31;
    if (warp >= BTROWS) return;
    const float* xr = x  + (size_t)warp * CDIM;
    const float* ar = aw + (size_t)window_row(warp) * CDIM;
    float v[12];
    float s = 0.f;
    #pragma unroll
    for (int i = 0; i < 12; i++) {
        int c = lane + i * 32;
        v[i] = xr[c] + ar[c];
        s += v[i];
    }
    s = warp_sum(s);
    float mu = s * (1.f / 384.f);
    float sq = 0.f;
    #pragma unroll
    for (int i = 0; i < 12; i++) { float dv = v[i] - mu; sq += dv * dv; }
    sq = warp_sum(sq);
    float rstd = rsqrtf(sq * (1.f / 384.f) + 1e-5f);
    size_t ro = (size_t)warp * CDIM;
    #pragma unroll
    for (int i = 0; i < 12; i++) {
        int c = lane + i * 32;
        x2[ro + c] = v[i];
        float o = (v[i] - mu) * rstd * g[c] + b[c];
        hn[ro + c] = __float2half(o);
    }
}

// ---------------------------------------------------------------------------
// mma.sync GEMM: C[M,N] = A[M,K] @ W[N,K]^T (+ bias / gelu / residual)
// fp16 2-pass split (A single plane, W hi/lo). BM=BN=128, BK=32, 256 threads,
// 8 warps (2Mx4N), warp tile 64x32, m16n8k16. 4-stage cp.async pipeline,
// XOR-swizzled smem, 2 CTAs/SM.
// EPI: 0 = bias->fp32 C, 1 = bias+gelu->fp16 C16, 2 = bias+res->fp32 C
// ---------------------------------------------------------------------------
#define GSTAGE 24576
#define GSMEM_BYTES (4*GSTAGE)

template <int EPI>
__global__ void __launch_bounds__(256, 2) mma_gemm(
    const __half* __restrict__ A, const __half* __restrict__ Bh,
    const __half* __restrict__ Bl, const float* __restrict__ bias,
    const float* __restrict__ res, float* __restrict__ C,
    __half* __restrict__ C16, int N, int K)
{
    extern __shared__ char smem[];
    const uint32_t sbase = smem_u32(smem);
    const int tid  = threadIdx.x;
    const int lane = tid & 31;
    const int wid  = tid >> 5;
    const int wm   = wid & 1;    // 0..1
    const int wn   = wid >> 1;   // 0..3
    const int bm = blockIdx.y * 128;
    const int bn = blockIdx.x * 128;

    float acc[4][4][4];
    #pragma unroll
    for (int i = 0; i < 4; i++)
        #pragma unroll
        for (int j = 0; j < 4; j++)
            #pragma unroll
            for (int q = 0; q < 4; q++) acc[i][j][q] = 0.f;

    // ---- stage loader: 3 sub-tiles (A, Bh, Bl) 128x32 fp16, swizzled ----
    #define LOAD_STAGE(stage, k0) do {                                        \
        uint32_t sb_ = sbase + (uint32_t)(stage) * GSTAGE;                    \
        const __half* bases_[3] = {A, Bh, Bl};                                \
        _Pragma("unroll")                                                     \
        for (int sub_ = 0; sub_ < 3; sub_++) {                                \
            const __half* bp_ = bases_[sub_];                                 \
            int ro_ = (sub_ == 0) ? bm : bn;                                  \
            _Pragma("unroll")                                                 \
            for (int jj_ = 0; jj_ < 2; jj_++) {                               \
                int cid_ = tid + 256 * jj_;                                   \
                int row_ = cid_ >> 2, ck_ = cid_ & 3;                         \
                int cs_ = ck_ ^ ((row_ >> 1) & 3);                            \
                const void* src_ = bp_ + (size_t)(ro_ + row_) * K + (k0) + ck_ * 8; \
                cp_async16(sb_ + (uint32_t)(sub_ << 13)                       \
                           + (uint32_t)(row_ * 64 + cs_ * 16), src_);         \
            }                                                                 \
        }                                                                     \
    } while (0)

    const int NC = K >> 5;
    LOAD_STAGE(0, 0);
    asm volatile("cp.async.commit_group;" ::: "memory");
    LOAD_STAGE(1, 32);
    asm volatile("cp.async.commit_group;" ::: "memory");
    LOAD_STAGE(2, 64);
    asm volatile("cp.async.commit_group;" ::: "memory");

    // ldmatrix address precompute
    const int arow = wm * 64 + (lane & 15);
    const int asel = lane >> 4;
    const int brow = wn * 32 + ((lane >> 4) << 3) + (lane & 7);
    const int bsel = (lane >> 3) & 1;

    for (int c = 0; c < NC; c++) {
        asm volatile("cp.async.wait_group 2;" ::: "memory");
        __syncthreads();
        if (c + 3 < NC) {
            LOAD_STAGE((c + 3) & 3, (c + 3) << 5);
            asm volatile("cp.async.commit_group;" ::: "memory");
        }

        const uint32_t sb = sbase + (uint32_t)(c & 3) * GSTAGE;
        #pragma unroll
        for (int kk = 0; kk < 2; kk++) {
            uint32_t a[4][4], bh[2][4], bl[2][4];
            #pragma unroll
            for (int mt = 0; mt < 4; mt++) {
                int row = arow + mt * 16;
                int ck  = kk * 2 + asel;
                uint32_t off = (uint32_t)(row * 64 + (ck ^ ((row >> 1) & 3)) * 16);
                ldm4(a[mt], sb + off);
            }
            #pragma unroll
            for (int bt = 0; bt < 2; bt++) {
                int row = brow + bt * 16;
                int ck  = kk * 2 + bsel;
                uint32_t off = (uint32_t)(row * 64 + (ck ^ ((row >> 1) & 3)) * 16);
                ldm4(bh[bt], sb + 8192u + off);
                ldm4(bl[bt], sb + 16384u + off);
            }
            #pragma unroll
            for (int mt = 0; mt < 4; mt++) {
                #pragma unroll
                for (int nt = 0; nt < 4; nt++) {
                    const uint32_t* bhf = &bh[nt >> 1][(nt & 1) * 2];
                    const uint32_t* blf = &bl[nt >> 1][(nt & 1) * 2];
                    mma16816(acc[mt][nt], a[mt], bhf);
                    mma16816(acc[mt][nt], a[mt], blf);
                }
            }
        }
    }

    // ---- epilogue ----
    const int gr = lane >> 2;
    const int nc0 = (lane & 3) * 2;
    #pragma unroll
    for (int mt = 0; mt < 4; mt++) {
        #pragma unroll
        for (int nt = 0; nt < 4; nt++) {
            int col = bn + wn * 32 + nt * 8 + nc0;
            float bs0 = bias[col], bs1 = bias[col + 1];
            #pragma unroll
            for (int half = 0; half < 2; half++) {
                int row = bm + wm * 64 + mt * 16 + gr + half * 8;
                float v0 = acc[mt][nt][half * 2 + 0] + bs0;
                float v1 = acc[mt][nt][half * 2 + 1] + bs1;
                size_t off = (size_t)row * N + col;
                if (EPI == 1) {
                    v0 = 0.5f * v0 * (1.f + erff(v0 * 0.70710678118654752f));
                    v1 = 0.5f * v1 * (1.f + erff(v1 * 0.70710678118654752f));
                    __half2 p = __halves2half2(__float2half(v0), __float2half(v1));
                    *(uint32_t*)(C16 + off) = *(uint32_t*)&p;
                } else {
                    if (EPI == 2) { v0 += res[off]; v1 += res[off + 1]; }
                    float2 o; o.x = v0; o.y = v1;
                    *(float2*)(C + off) = o;
                }
            }
        }
    }
    #undef LOAD_STAGE
}

// ---------------------------------------------------------------------------
// Pola linear attention, one block per (window, head). 256 threads.
// ---------------------------------------------------------------------------
__global__ void __launch_bounds__(256) attn_kernel(
    const float* __restrict__ kvg, const float* __restrict__ qb,
    const float* __restrict__ pos_enc, const float* __restrict__ scale_p,
    const float* __restrict__ power_p, float* __restrict__ xo)
{
    const int wg = blockIdx.x;   // 0..63
    const int h  = blockIdx.y;   // 0..11
    const int tid = threadIdx.x;

    __shared__ float sc_s[32], pw_s[32];
    __shared__ float buf[64][65];    // kc (phase A) / qf (phase C)
    __shared__ float vm[64][32];     // v (phase A) / M (phase C)
    __shared__ float km2_s[2][64];   // z feature vectors
    __shared__ float z_s[64][2];

    if (tid < 32) {
        float sp = scale_p[h * 32 + tid];
        sc_s[tid] = 1.f / log1pf(expf(sp));          // 1/softplus
        float pp = power_p[h * 32 + tid];
        pw_s[tid] = 1.f + 4.f / (1.f + expf(-pp));   // 1 + ALPHA*sigmoid
    }
    __syncthreads();

    const int f0 = (tid >> 3) << 1;   // 0,2,..,62
    const int vc = (tid & 7) << 2;    // 0,4,..,28

    float kv00 = 0.f, kv01 = 0.f, kv02 = 0.f, kv03 = 0.f;
    float kv10 = 0.f, kv11 = 0.f, kv12 = 0.f, kv13 = 0.f;
    float ksum = 0.f;

    // -------- phase A: kc features, kv = kc^T v, ksum --------
    for (int c0 = 0; c0 < WN; c0 += 64) {
        #pragma unroll
        for (int i = 0; i < 8; i++) {
            int idx = tid + 256 * i;
            int nl = idx >> 5;
            int d  = idx & 31;
            int row = wg * WN + c0 + nl;
            float kval = (kvg[(size_t)row * KVGC + h * 32 + d]
                          + pos_enc[(c0 + nl) * CDIM + h * 32 + d]) * sc_s[d];
            float r = fast_pow(fabsf(kval), pw_s[d]);
            buf[nl][d]      = kval > 0.f ? r : 0.f;
            buf[nl][d + 32] = kval < 0.f ? r : 0.f;
            vm[nl][d] = kvg[(size_t)row * KVGC + 384 + h * 32 + d];
        }
        __syncthreads();
        #pragma unroll 4
        for (int n = 0; n < 64; n++) {
            float k0 = buf[n][f0];
            float k1 = buf[n][f0 + 1];
            float4 v4 = *(const float4*)&vm[n][vc];
            kv00 += k0 * v4.x; kv01 += k0 * v4.y;
            kv02 += k0 * v4.z; kv03 += k0 * v4.w;
            kv10 += k1 * v4.x; kv11 += k1 * v4.y;
            kv12 += k1 * v4.z; kv13 += k1 * v4.w;
        }
        if (tid < 64) {
            float s = ksum;
            #pragma unroll 8
            for (int n = 0; n < 64; n++) s += buf[n][tid];
            ksum = s;
        }
        __syncthreads();
    }

    // -------- finalize: write M (reordered kv) and km vectors --------
    {
        const float sN2 = 1.f / 512.f;
        int fr0 = (vc < 16) ? f0 : ((f0 + 32) & 63);
        vm[fr0][vc + 0] = kv00 * sN2; vm[fr0][vc + 1] = kv01 * sN2;
        vm[fr0][vc + 2] = kv02 * sN2; vm[fr0][vc + 3] = kv03 * sN2;
        int fr1 = (vc < 16) ? (f0 + 1) : ((f0 + 33) & 63);
        vm[fr1][vc + 0] = kv10 * sN2; vm[fr1][vc + 1] = kv11 * sN2;
        vm[fr1][vc + 2] = kv12 * sN2; vm[fr1][vc + 3] = kv13 * sN2;
        if (tid < 64) {
            float km = ksum * sN2;
            km2_s[0][tid] = km;
            km2_s[1][(tid + 32) & 63] = km;
        }
    }
    __syncthreads();

    // -------- phase C: q features + O = qf @ M, z, write --------
    const int n0 = (tid >> 3) << 1;   // 0,2,..,62
    for (int c0 = 0; c0 < WN; c0 += 64) {
        #pragma unroll
        for (int i = 0; i < 8; i++) {
            int idx = tid + 256 * i;
            int nl = idx >> 5;
            int d  = idx & 31;
            int row = wg * WN + c0 + nl;
            float qv = qb[(size_t)row * CDIM + h * 32 + d] * sc_s[d];
            float r = fast_pow(fabsf(qv), pw_s[d]);
            buf[nl][d]      = qv > 0.f ? r : 0.f;
            buf[nl][d + 32] = qv < 0.f ? r : 0.f;
        }
        __syncthreads();

        float a00 = 0.f, a01 = 0.f, a02 = 0.f, a03 = 0.f;
        float a10 = 0.f, a11 = 0.f, a12 = 0.f, a13 = 0.f;
        #pragma unroll 4
        for (int f = 0; f < 64; f++) {
            float q0 = buf[n0][f];
            float q1 = buf[n0 + 1][f];
            float4 m = *(const float4*)&vm[f][vc];
            a00 += q0 * m.x; a01 += q0 * m.y; a02 += q0 * m.z; a03 += q0 * m.w;
            a10 += q1 * m.x; a11 += q1 * m.y; a12 += q1 * m.z; a13 += q1 * m.w;
        }
        if (tid < 128) {
            int n = tid >> 1, zi = tid & 1;
            float z = 1e-6f;
            #pragma unroll 8
            for (int f = 0; f < 64; f++) z += buf[n][f] * km2_s[zi][f];
            z_s[n][zi] = z;
        }
        __syncthreads();

        int zi = (vc >= 16) ? 1 : 0;
        float rz0 = 1.f / z_s[n0][zi];
        float rz1 = 1.f / z_s[n0 + 1][zi];
        size_t base0 = (size_t)(wg * WN + c0 + n0) * CDIM + h * 32 + vc;
        float4 o0; o0.x = a00 * rz0; o0.y = a01 * rz0; o0.z = a02 * rz0; o0.w = a03 * rz0;
        float4 o1; o1.x = a10 * rz1; o1.y = a11 * rz1; o1.z = a12 * rz1; o1.w = a13 * rz1;
        *(float4*)&xo[base0] = o0;
        *(float4*)&xo[base0 + CDIM] = o1;
        __syncthreads();
    }
}

// ---------------------------------------------------------------------------
// Depthwise 5^3 conv + (xo + vv) * g -> single fp16 plane
// ---------------------------------------------------------------------------
__global__ void __launch_bounds__(256) dwconv_kernel(
    const float* __restrict__ kvg, const float* __restrict__ dwc_w,
    const float* __restrict__ dwc_b, const float* __restrict__ xo,
    __half* __restrict__ xo16)
{
    extern __shared__ float sm[];
    float* v_s = sm;
    float* w_s = sm + 512 * 32;
    const int bh = blockIdx.x;
    const int b_ = bh / NHEADS, h = bh % NHEADS;
    const int tid = threadIdx.x;

    for (int i = tid; i < 512 * 32; i += 256) {
        int n = i >> 5, d = i & 31;
        v_s[i] = kvg[(size_t)(b_ * WN + n) * KVGC + 384 + h * 32 + d];
    }
    for (int i = tid; i < 125 * 32; i += 256) w_s[i] = dwc_w[i];
    __syncthreads();

    const int d  = tid & 31;
    const int lo = tid >> 5;
    const float bval = dwc_b[d];
    const size_t base = (size_t)b_ * (WN * CDIM) + (size_t)h * (WN * HD);

    for (int jg = 0; jg < 4; jg++) {
        float acc[16];
        #pragma unroll
        for (int jj = 0; jj < 16; jj++) acc[jj] = bval;
        for (int kd = 0; kd < 5; kd++) {
            for (int kh = 0; kh < 5; kh++) {
                for (int kw = 0; kw < 5; kw++) {
                    int li = lo + kw - 2;
                    if (li < 0 || li > 7) continue;
                    float w = w_s[((kd * 5 + kh) * 5 + kw) * 32 + d];
                    #pragma unroll
                    for (int jj = 0; jj < 16; jj++) {
                        int j = jg * 16 + jj;
                        int hi = (j >> 3) + kd - 2;
                        int wi = (j & 7) + kh - 2;
                        if (hi < 0 || hi > 7 || wi < 0 || wi > 7) continue;
                        acc[jj] += v_s[((hi * 8 + wi) * 8 + li) * 32 + d] * w;
                    }
                }
            }
        }
        #pragma unroll
        for (int jj = 0; jj < 16; jj++) {
            int j = jg * 16 + jj;
            size_t flat = base + (size_t)(lo + 8 * j) * 32 + d;
            size_t grow = flat / CDIM;
            int    gcol = (int)(flat % CDIM);
            float g = kvg[grow * KVGC + 768 + gcol];
            float val = (xo[flat] + acc[jj]) * g;
            xo16[flat] = __float2half(val);
        }
    }
}

// ---------------------------------------------------------------------------
// kernel_launch
// ---------------------------------------------------------------------------
extern "C" void kernel_launch(void* const* d_in, const int* in_sizes, int n_in,
                              void* d_out, int out_size)
{
    const float* x       = (const float*)d_in[0];
    const float* y       = (const float*)d_in[1];
    const float* w_qkvg  = (const float*)d_in[2];
    const float* b_qkvg  = (const float*)d_in[3];
    const float* w_proj  = (const float*)d_in[4];
    const float* b_proj  = (const float*)d_in[5];
    const float* dwc_w   = (const float*)d_in[6];
    const float* dwc_b   = (const float*)d_in[7];
    const float* power_p = (const float*)d_in[8];
    const float* scale_p = (const float*)d_in[9];
    const float* pos_enc = (const float*)d_in[10];
    const float* g1      = (const float*)d_in[11];
    const float* b1      = (const float*)d_in[12];
    const float* g2      = (const float*)d_in[13];
    const float* b2      = (const float*)d_in[14];
    const float* w_fc1   = (const float*)d_in[15];
    const float* b_fc1   = (const float*)d_in[16];
    const float* w_fc2   = (const float*)d_in[17];
    const float* b_fc2   = (const float*)d_in[18];
    float* out = (float*)d_out;

    __half *p_xw16, *p_yw16, *p_hn16, *p_xo16, *p_h116;
    __half *p_wqh, *p_wql, *p_wph, *p_wpl, *p_w1h, *p_w1l, *p_w2h, *p_w2l;
    float *p_kvg, *p_qb, *p_xo, *p_aw, *p_x2;
    cudaGetSymbolAddress((void**)&p_xw16, d_xw16);
    cudaGetSymbolAddress((void**)&p_yw16, d_yw16);
    cudaGetSymbolAddress((void**)&p_hn16, d_hn16);
    cudaGetSymbolAddress((void**)&p_xo16, d_xo16);
    cudaGetSymbolAddress((void**)&p_h116, d_h116);
    cudaGetSymbolAddress((void**)&p_wqh, d_wqh);
    cudaGetSymbolAddress((void**)&p_wql, d_wql);
    cudaGetSymbolAddress((void**)&p_wph, d_wph);
    cudaGetSymbolAddress((void**)&p_wpl, d_wpl);
    cudaGetSymbolAddress((void**)&p_w1h, d_w1h);
    cudaGetSymbolAddress((void**)&p_w1l, d_w1l);
    cudaGetSymbolAddress((void**)&p_w2h, d_w2h);
    cudaGetSymbolAddress((void**)&p_w2l, d_w2l);
    cudaGetSymbolAddress((void**)&p_kvg, d_kvg);
    cudaGetSymbolAddress((void**)&p_qb,  d_qb);
    cudaGetSymbolAddress((void**)&p_xo,  d_xo);
    cudaGetSymbolAddress((void**)&p_aw,  d_aw);
    cudaGetSymbolAddress((void**)&p_x2,  d_x2);

    const int conv_smem = (512 * 32 + 125 * 32) * (int)sizeof(float);
    cudaFuncSetAttribute(dwconv_kernel,
                         cudaFuncAttributeMaxDynamicSharedMemorySize, conv_smem);
    cudaFuncSetAttribute(mma_gemm<0>,
                         cudaFuncAttributeMaxDynamicSharedMemorySize, GSMEM_BYTES);
    cudaFuncSetAttribute(mma_gemm<1>,
                         cudaFuncAttributeMaxDynamicSharedMemorySize, GSMEM_BYTES);
    cudaFuncSetAttribute(mma_gemm<2>,
                         cudaFuncAttributeMaxDynamicSharedMemorySize, GSMEM_BYTES);

    // 0) weight splits (fp16 hi/lo)
    cvt_kernel<<<(1536*384/4 + 255)/256, 256>>>((const float4*)w_qkvg,
        (uint2*)p_wqh, (uint2*)p_wql, 1536*384/4);
    cvt_kernel<<<(384*384/4 + 255)/256, 256>>>((const float4*)w_proj,
        (uint2*)p_wph, (uint2*)p_wpl, 384*384/4);
    cvt_kernel<<<(1536*384/4 + 255)/256, 256>>>((const float4*)w_fc1,
        (uint2*)p_w1h, (uint2*)p_w1l, 1536*384/4);
    cvt_kernel<<<(384*1536/4 + 255)/256, 256>>>((const float4*)w_fc2,
        (uint2*)p_w2h, (uint2*)p_w2l, 384*1536/4);

    // 1) LN + window partition -> fp16
    ln_win_kernel<<<BTROWS / 8, 256>>>(x, g1, b1, p_xw16);
    ln_win_kernel<<<BTROWS / 8, 256>>>(y, g1, b1, p_yw16);

    // 2) kvg = xw @ W[384:1536]^T + b[384:]   (N=1152, K=384)
    mma_gemm<0><<<dim3(KVGC/128, BTROWS/128), 256, GSMEM_BYTES>>>(
        p_xw16, p_wqh + 384*384, p_wql + 384*384, b_qkvg + 384,
        nullptr, p_kvg, nullptr, KVGC, 384);

    // 3) q = yw @ W[0:384]^T + b[0:384]
    mma_gemm<0><<<dim3(CDIM/128, BTROWS/128), 256, GSMEM_BYTES>>>(
        p_yw16, p_wqh, p_wql, b_qkvg,
        nullptr, p_qb, nullptr, CDIM, 384);

    // 4) attention -> xo
    attn_kernel<<<dim3(NWIN, NHEADS), 256>>>(p_kvg, p_qb, pos_enc,
                                             scale_p, power_p, p_xo);

    // 5) depthwise conv + gating -> fp16
    dwconv_kernel<<<NWIN * NHEADS, 256, conv_smem>>>(p_kvg, dwc_w, dwc_b,
                                                     p_xo, p_xo16);

    // 6) aw = xo @ w_proj^T + b_proj
    mma_gemm<0><<<dim3(CDIM/128, BTROWS/128), 256, GSMEM_BYTES>>>(
        p_xo16, p_wph, p_wpl, b_proj,
        nullptr, p_aw, nullptr, CDIM, 384);

    // 7) x2 = x + window_reverse(aw); hn = LN2(x2) -> fp16
    resln_kernel<<<BTROWS / 8, 256>>>(x, p_aw, g2, b2, p_x2, p_hn16);

    // 8) h1 = gelu(hn @ w_fc1^T + b_fc1) -> fp16   (N=1536, K=384)
    mma_gemm<1><<<dim3(HIDDEN/128, BTROWS/128), 256, GSMEM_BYTES>>>(
        p_hn16, p_w1h, p_w1l, b_fc1,
        nullptr, nullptr, p_h116, HIDDEN, 384);

    // 9) out = x2 + h1 @ w_fc2^T + b_fc2    (N=384, K=1536)
    mma_gemm<2><<<dim3(CDIM/128, BTROWS/128), 256, GSMEM_BYTES>>>(
        p_h116, p_w2h, p_w2l, b_fc2,
        p_x2, out, nullptr, CDIM, 1536);
}

// round 7
// speedup vs baseline: 3.6926x; 1.0872x over previous
#include <cuda_runtime.h>
#include <cuda_fp16.h>
#include <math.h>
#include <stdint.h>

// ---------------------------------------------------------------------------
// Problem constants
// ---------------------------------------------------------------------------
#define BATCH   2
#define RES_H   32
#define RES_W   32
#define RES_L   16
#define WSZ     8
#define CDIM    384
#define NHEADS  12
#define HD      32
#define NTOK    (RES_H*RES_W*RES_L)       // 16384
#define BTROWS  (BATCH*NTOK)              // 32768
#define NWIN_B  ((RES_H/WSZ)*(RES_W/WSZ)*(RES_L/WSZ))  // 32
#define NWIN    (BATCH*NWIN_B)            // 64
#define WN      (WSZ*WSZ*WSZ)             // 512
#define KVGC    1152
#define HIDDEN  1536

// ---------------------------------------------------------------------------
// Scratch (static device globals)
// ---------------------------------------------------------------------------
static __device__ __align__(256) __half d_xw16[BTROWS*CDIM];
static __device__ __align__(256) __half d_yw16[BTROWS*CDIM];
static __device__ __align__(256) __half d_hn16[BTROWS*CDIM];
static __device__ __align__(256) __half d_xo16[BTROWS*CDIM];
static __device__ __align__(256) __half d_h116[BTROWS*HIDDEN];
static __device__ __align__(256) __half d_kvg16[BTROWS*KVGC];
static __device__ __align__(256) __half d_qb16[BTROWS*CDIM];
static __device__ __align__(256) __half d_wqh[1536*384];
static __device__ __align__(256) __half d_wql[1536*384];
static __device__ __align__(256) __half d_wph[384*384];
static __device__ __align__(256) __half d_wpl[384*384];
static __device__ __align__(256) __half d_w1h[1536*384];
static __device__ __align__(256) __half d_w1l[1536*384];
static __device__ __align__(256) __half d_w2h[384*1536];
static __device__ __align__(256) __half d_w2l[384*1536];

static __device__ float d_aw [BTROWS*CDIM];
static __device__ float d_x2 [BTROWS*CDIM];

// ---------------------------------------------------------------------------
// PTX helpers (arch-portable: cp.async / ldmatrix / mma.sync only)
// ---------------------------------------------------------------------------
__device__ __forceinline__ uint32_t smem_u32(const void* p) {
    uint32_t a;
    asm("{ .reg .u64 t; cvta.to.shared.u64 t, %1; cvt.u32.u64 %0, t; }"
        : "=r"(a) : "l"(p));
    return a;
}
__device__ __forceinline__ void cp_async16(uint32_t dst, const void* src) {
    asm volatile("cp.async.cg.shared.global [%0], [%1], 16;"
        :: "r"(dst), "l"(src) : "memory");
}
__device__ __forceinline__ void ldm4(uint32_t* r, uint32_t addr) {
    asm volatile("ldmatrix.sync.aligned.m8n8.x4.shared.b16 {%0,%1,%2,%3}, [%4];"
        : "=r"(r[0]), "=r"(r[1]), "=r"(r[2]), "=r"(r[3]) : "r"(addr));
}
__device__ __forceinline__ void mma16816(float* c, const uint32_t* a, const uint32_t* b) {
    asm volatile("mma.sync.aligned.m16n8k16.row.col.f32.f16.f16.f32 "
        "{%0,%1,%2,%3}, {%4,%5,%6,%7}, {%8,%9}, {%0,%1,%2,%3};"
        : "+f"(c[0]), "+f"(c[1]), "+f"(c[2]), "+f"(c[3])
        : "r"(a[0]), "r"(a[1]), "r"(a[2]), "r"(a[3]), "r"(b[0]), "r"(b[1]));
}

// ---------------------------------------------------------------------------
// misc helpers
// ---------------------------------------------------------------------------
__device__ __forceinline__ float warp_sum(float v) {
    #pragma unroll
    for (int o = 16; o; o >>= 1) v += __shfl_xor_sync(0xffffffffu, v, o);
    return v;
}
__device__ __forceinline__ int window_row(int bt) {
    int bb = bt >> 14;
    int t  = bt & 16383;
    int hh = t >> 9;
    int ww = (t >> 4) & 31;
    int ll = t & 15;
    int win = bb * NWIN_B + (((hh >> 3) * 4 + (ww >> 3)) * 2 + (ll >> 3));
    int n   = (((hh & 7) << 3) + (ww & 7)) * 8 + (ll & 7);
    return win * WN + n;
}
__device__ __forceinline__ void split_h16(float v, __half& h, __half& l) {
    h = __float2half(v);
    l = __float2half(v - __half2float(h));
}
// fast x^p for x >= 0 (x==0 -> lg2 gives -inf -> ex2 gives 0)
__device__ __forceinline__ float fast_pow(float m, float p) {
    float lg, r;
    asm("lg2.approx.f32 %0, %1;" : "=f"(lg) : "f"(m));
    asm("ex2.approx.f32 %0, %1;" : "=f"(r) : "f"(p * lg));
    return r;
}

// ---------------------------------------------------------------------------
// all weights: fp32 -> fp16 hi/lo split, single launch
// ---------------------------------------------------------------------------
__global__ void __launch_bounds__(256) cvt_all_kernel(
    const float4* __restrict__ s0, uint2* __restrict__ h0, uint2* __restrict__ l0, int n0,
    const float4* __restrict__ s1, uint2* __restrict__ h1, uint2* __restrict__ l1, int n1,
    const float4* __restrict__ s2, uint2* __restrict__ h2, uint2* __restrict__ l2, int n2,
    const float4* __restrict__ s3, uint2* __restrict__ h3, uint2* __restrict__ l3, int n3)
{
    int i = blockIdx.x * blockDim.x + threadIdx.x;
    const float4* s; uint2 *hp, *lp; int idx;
    if (i < n0)                { s = s0; hp = h0; lp = l0; idx = i; }
    else if (i < n0+n1)        { s = s1; hp = h1; lp = l1; idx = i - n0; }
    else if (i < n0+n1+n2)     { s = s2; hp = h2; lp = l2; idx = i - n0 - n1; }
    else if (i < n0+n1+n2+n3)  { s = s3; hp = h3; lp = l3; idx = i - n0 - n1 - n2; }
    else return;
    float4 v = s[idx];
    __half a0, a1, a2, a3, b0, b1, b2, b3;
    split_h16(v.x, a0, b0); split_h16(v.y, a1, b1);
    split_h16(v.z, a2, b2); split_h16(v.w, a3, b3);
    __half2 ph0 = __halves2half2(a0, a1);
    __half2 ph1 = __halves2half2(a2, a3);
    __half2 pl0 = __halves2half2(b0, b1);
    __half2 pl1 = __halves2half2(b2, b3);
    uint2 uh; uh.x = *(uint32_t*)&ph0; uh.y = *(uint32_t*)&ph1;
    uint2 ul; ul.x = *(uint32_t*)&pl0; ul.y = *(uint32_t*)&pl1;
    hp[idx] = uh; lp[idx] = ul;
}

// ---------------------------------------------------------------------------
// LayerNorm fused with window partition -> single fp16 plane
// ---------------------------------------------------------------------------
__global__ void __launch_bounds__(256) ln_win_kernel(
    const float* __restrict__ x, const float* __restrict__ g,
    const float* __restrict__ b, __half* __restrict__ o16)
{
    int warp = (blockIdx.x * blockDim.x + threadIdx.x) >> 5;
    int lane = threadIdx.x & 31;
    if (warp >= BTROWS) return;
    const float* xr = x + (size_t)warp * CDIM;
    float v[12];
    float s = 0.f;
    #pragma unroll
    for (int i = 0; i < 12; i++) { v[i] = xr[lane + i * 32]; s += v[i]; }
    s = warp_sum(s);
    float mu = s * (1.f / 384.f);
    float sq = 0.f;
    #pragma unroll
    for (int i = 0; i < 12; i++) { float dv = v[i] - mu; sq += dv * dv; }
    sq = warp_sum(sq);
    float rstd = rsqrtf(sq * (1.f / 384.f) + 1e-5f);
    size_t ro = (size_t)window_row(warp) * CDIM;
    #pragma unroll
    for (int i = 0; i < 12; i++) {
        int c = lane + i * 32;
        float o = (v[i] - mu) * rstd * g[c] + b[c];
        o16[ro + c] = __float2half(o);
    }
}

// ---------------------------------------------------------------------------
// residual-add (window_reverse) + LN2 -> x2 fp32, hn fp16
// ---------------------------------------------------------------------------
__global__ void __launch_bounds__(256) resln_kernel(
    const float* __restrict__ x, const float* __restrict__ aw,
    const float* __restrict__ g, const float* __restrict__ b,
    float* __restrict__ x2, __half* __restrict__ hn)
{
    int warp = (blockIdx.x * blockDim.x + threadIdx.x) >> 5;
    int lane = threadIdx.x & 31;
    if (warp >= BTROWS) return;
    const float* xr = x  + (size_t)warp * CDIM;
    const float* ar = aw + (size_t)window_row(warp) * CDIM;
    float v[12];
    float s = 0.f;
    #pragma unroll
    for (int i = 0; i < 12; i++) {
        int c = lane + i * 32;
        v[i] = xr[c] + ar[c];
        s += v[i];
    }
    s = warp_sum(s);
    float mu = s * (1.f / 384.f);
    float sq = 0.f;
    #pragma unroll
    for (int i = 0; i < 12; i++) { float dv = v[i] - mu; sq += dv * dv; }
    sq = warp_sum(sq);
    float rstd = rsqrtf(sq * (1.f / 384.f) + 1e-5f);
    size_t ro = (size_t)warp * CDIM;
    #pragma unroll
    for (int i = 0; i < 12; i++) {
        int c = lane + i * 32;
        x2[ro + c] = v[i];
        float o = (v[i] - mu) * rstd * g[c] + b[c];
        hn[ro + c] = __float2half(o);
    }
}

// ---------------------------------------------------------------------------
// mma.sync GEMM: C[M,N] = A[M,K] @ W[N,K]^T (+ bias / gelu / residual)
// A single fp16 plane; W hi(+lo) fp16 planes (PASSES=1 or 2).
// BM=BN=128, BK=32, 256 threads, 8 warps (2Mx4N), warp tile 64x32, m16n8k16.
// 4-stage cp.async pipeline, XOR-swizzled smem, 2 CTAs/SM.
// EPI: 0 = bias->fp32 C, 1 = bias+gelu->fp16 C16, 2 = bias+res->fp32 C,
//      3 = bias->fp16 C16
// ---------------------------------------------------------------------------
#define GSTAGE 24576
#define GSMEM_BYTES (4*GSTAGE)

template <int EPI, int PASSES>
__global__ void __launch_bounds__(256, 2) mma_gemm(
    const __half* __restrict__ A, const __half* __restrict__ Bh,
    const __half* __restrict__ Bl, const float* __restrict__ bias,
    const float* __restrict__ res, float* __restrict__ C,
    __half* __restrict__ C16, int N, int K)
{
    extern __shared__ char smem[];
    const uint32_t sbase = smem_u32(smem);
    const int tid  = threadIdx.x;
    const int lane = tid & 31;
    const int wid  = tid >> 5;
    const int wm   = wid & 1;    // 0..1
    const int wn   = wid >> 1;   // 0..3
    const int bm = blockIdx.y * 128;
    const int bn = blockIdx.x * 128;

    float acc[4][4][4];
    #pragma unroll
    for (int i = 0; i < 4; i++)
        #pragma unroll
        for (int j = 0; j < 4; j++)
            #pragma unroll
            for (int q = 0; q < 4; q++) acc[i][j][q] = 0.f;

    // ---- stage loader: sub-tiles (A, Bh[, Bl]) 128x32 fp16, swizzled ----
    #define LOAD_STAGE(stage, k0) do {                                        \
        uint32_t sb_ = sbase + (uint32_t)(stage) * GSTAGE;                    \
        const __half* bases_[3] = {A, Bh, Bl};                                \
        _Pragma("unroll")                                                     \
        for (int sub_ = 0; sub_ < 1 + PASSES; sub_++) {                       \
            const __half* bp_ = bases_[sub_];                                 \
            int ro_ = (sub_ == 0) ? bm : bn;                                  \
            _Pragma("unroll")                                                 \
            for (int jj_ = 0; jj_ < 2; jj_++) {                               \
                int cid_ = tid + 256 * jj_;                                   \
                int row_ = cid_ >> 2, ck_ = cid_ & 3;                         \
                int cs_ = ck_ ^ ((row_ >> 1) & 3);                            \
                const void* src_ = bp_ + (size_t)(ro_ + row_) * K + (k0) + ck_ * 8; \
                cp_async16(sb_ + (uint32_t)(sub_ << 13)                       \
                           + (uint32_t)(row_ * 64 + cs_ * 16), src_);         \
            }                                                                 \
        }                                                                     \
    } while (0)

    const int NC = K >> 5;
    LOAD_STAGE(0, 0);
    asm volatile("cp.async.commit_group;" ::: "memory");
    LOAD_STAGE(1, 32);
    asm volatile("cp.async.commit_group;" ::: "memory");
    LOAD_STAGE(2, 64);
    asm volatile("cp.async.commit_group;" ::: "memory");

    // ldmatrix address precompute
    const int arow = wm * 64 + (lane & 15);
    const int asel = lane >> 4;
    const int brow = wn * 32 + ((lane >> 4) << 3) + (lane & 7);
    const int bsel = (lane >> 3) & 1;

    for (int c = 0; c < NC; c++) {
        asm volatile("cp.async.wait_group 2;" ::: "memory");
        __syncthreads();
        if (c + 3 < NC) {
            LOAD_STAGE((c + 3) & 3, (c + 3) << 5);
            asm volatile("cp.async.commit_group;" ::: "memory");
        }

        const uint32_t sb = sbase + (uint32_t)(c & 3) * GSTAGE;
        #pragma unroll
        for (int kk = 0; kk < 2; kk++) {
            uint32_t a[4][4], bh[2][4], bl[2][4];
            #pragma unroll
            for (int mt = 0; mt < 4; mt++) {
                int row = arow + mt * 16;
                int ck  = kk * 2 + asel;
                uint32_t off = (uint32_t)(row * 64 + (ck ^ ((row >> 1) & 3)) * 16);
                ldm4(a[mt], sb + off);
            }
            #pragma unroll
            for (int bt = 0; bt < 2; bt++) {
                int row = brow + bt * 16;
                int ck  = kk * 2 + bsel;
                uint32_t off = (uint32_t)(row * 64 + (ck ^ ((row >> 1) & 3)) * 16);
                ldm4(bh[bt], sb + 8192u + off);
                if (PASSES == 2) ldm4(bl[bt], sb + 16384u + off);
            }
            #pragma unroll
            for (int mt = 0; mt < 4; mt++) {
                #pragma unroll
                for (int nt = 0; nt < 4; nt++) {
                    const uint32_t* bhf = &bh[nt >> 1][(nt & 1) * 2];
                    mma16816(acc[mt][nt], a[mt], bhf);
                    if (PASSES == 2) {
                        const uint32_t* blf = &bl[nt >> 1][(nt & 1) * 2];
                        mma16816(acc[mt][nt], a[mt], blf);
                    }
                }
            }
        }
    }

    // ---- epilogue ----
    const int gr = lane >> 2;
    const int nc0 = (lane & 3) * 2;
    #pragma unroll
    for (int mt = 0; mt < 4; mt++) {
        #pragma unroll
        for (int nt = 0; nt < 4; nt++) {
            int col = bn + wn * 32 + nt * 8 + nc0;
            float bs0 = bias[col], bs1 = bias[col + 1];
            #pragma unroll
            for (int half = 0; half < 2; half++) {
                int row = bm + wm * 64 + mt * 16 + gr + half * 8;
                float v0 = acc[mt][nt][half * 2 + 0] + bs0;
                float v1 = acc[mt][nt][half * 2 + 1] + bs1;
                size_t off = (size_t)row * N + col;
                if (EPI == 1 || EPI == 3) {
                    if (EPI == 1) {
                        v0 = 0.5f * v0 * (1.f + erff(v0 * 0.70710678118654752f));
                        v1 = 0.5f * v1 * (1.f + erff(v1 * 0.70710678118654752f));
                    }
                    __half2 p = __halves2half2(__float2half(v0), __float2half(v1));
                    *(uint32_t*)(C16 + off) = *(uint32_t*)&p;
                } else {
                    if (EPI == 2) { v0 += res[off]; v1 += res[off + 1]; }
                    float2 o; o.x = v0; o.y = v1;
                    *(float2*)(C + off) = o;
                }
            }
        }
    }
    #undef LOAD_STAGE
}

// ---------------------------------------------------------------------------
// Pola linear attention, one block per (window, head). 256 threads.
// fp16 global IO, fp32 smem compute.
// ---------------------------------------------------------------------------
__global__ void __launch_bounds__(256) attn_kernel(
    const __half* __restrict__ kvg, const __half* __restrict__ qb,
    const float* __restrict__ pos_enc, const float* __restrict__ scale_p,
    const float* __restrict__ power_p, __half* __restrict__ xo)
{
    const int wg = blockIdx.x;   // 0..63
    const int h  = blockIdx.y;   // 0..11
    const int tid = threadIdx.x;

    __shared__ float sc_s[32], pw_s[32];
    __shared__ float buf[64][65];    // kc (phase A) / qf (phase C)
    __shared__ float vm[64][32];     // v (phase A) / M (phase C)
    __shared__ float km2_s[2][64];   // z feature vectors
    __shared__ float z_s[64][2];

    if (tid < 32) {
        float sp = scale_p[h * 32 + tid];
        sc_s[tid] = 1.f / log1pf(expf(sp));          // 1/softplus
        float pp = power_p[h * 32 + tid];
        pw_s[tid] = 1.f + 4.f / (1.f + expf(-pp));   // 1 + ALPHA*sigmoid
    }
    __syncthreads();

    const int f0 = (tid >> 3) << 1;   // 0,2,..,62
    const int vc = (tid & 7) << 2;    // 0,4,..,28

    float kv00 = 0.f, kv01 = 0.f, kv02 = 0.f, kv03 = 0.f;
    float kv10 = 0.f, kv11 = 0.f, kv12 = 0.f, kv13 = 0.f;
    float ksum = 0.f;

    // -------- phase A: kc features, kv = kc^T v, ksum --------
    for (int c0 = 0; c0 < WN; c0 += 64) {
        #pragma unroll
        for (int i = 0; i < 8; i++) {
            int idx = tid + 256 * i;
            int nl = idx >> 5;
            int d  = idx & 31;
            int row = wg * WN + c0 + nl;
            float kval = (__half2float(kvg[(size_t)row * KVGC + h * 32 + d])
                          + pos_enc[(c0 + nl) * CDIM + h * 32 + d]) * sc_s[d];
            float r = fast_pow(fabsf(kval), pw_s[d]);
            buf[nl][d]      = kval > 0.f ? r : 0.f;
            buf[nl][d + 32] = kval < 0.f ? r : 0.f;
            vm[nl][d] = __half2float(kvg[(size_t)row * KVGC + 384 + h * 32 + d]);
        }
        __syncthreads();
        #pragma unroll 4
        for (int n = 0; n < 64; n++) {
            float k0 = buf[n][f0];
            float k1 = buf[n][f0 + 1];
            float4 v4 = *(const float4*)&vm[n][vc];
            kv00 += k0 * v4.x; kv01 += k0 * v4.y;
            kv02 += k0 * v4.z; kv03 += k0 * v4.w;
            kv10 += k1 * v4.x; kv11 += k1 * v4.y;
            kv12 += k1 * v4.z; kv13 += k1 * v4.w;
        }
        if (tid < 64) {
            float s = ksum;
            #pragma unroll 8
            for (int n = 0; n < 64; n++) s += buf[n][tid];
            ksum = s;
        }
        __syncthreads();
    }

    // -------- finalize: write M (reordered kv) and km vectors --------
    {
        const float sN2 = 1.f / 512.f;
        int fr0 = (vc < 16) ? f0 : ((f0 + 32) & 63);
        vm[fr0][vc + 0] = kv00 * sN2; vm[fr0][vc + 1] = kv01 * sN2;
        vm[fr0][vc + 2] = kv02 * sN2; vm[fr0][vc + 3] = kv03 * sN2;
        int fr1 = (vc < 16) ? (f0 + 1) : ((f0 + 33) & 63);
        vm[fr1][vc + 0] = kv10 * sN2; vm[fr1][vc + 1] = kv11 * sN2;
        vm[fr1][vc + 2] = kv12 * sN2; vm[fr1][vc + 3] = kv13 * sN2;
        if (tid < 64) {
            float km = ksum * sN2;
            km2_s[0][tid] = km;
            km2_s[1][(tid + 32) & 63] = km;
        }
    }
    __syncthreads();

    // -------- phase C: q features + O = qf @ M, z, write --------
    const int n0 = (tid >> 3) << 1;   // 0,2,..,62
    for (int c0 = 0; c0 < WN; c0 += 64) {
        #pragma unroll
        for (int i = 0; i < 8; i++) {
            int idx = tid + 256 * i;
            int nl = idx >> 5;
            int d  = idx & 31;
            int row = wg * WN + c0 + nl;
            float qv = __half2float(qb[(size_t)row * CDIM + h * 32 + d]) * sc_s[d];
            float r = fast_pow(fabsf(qv), pw_s[d]);
            buf[nl][d]      = qv > 0.f ? r : 0.f;
            buf[nl][d + 32] = qv < 0.f ? r : 0.f;
        }
        __syncthreads();

        float a00 = 0.f, a01 = 0.f, a02 = 0.f, a03 = 0.f;
        float a10 = 0.f, a11 = 0.f, a12 = 0.f, a13 = 0.f;
        #pragma unroll 4
        for (int f = 0; f < 64; f++) {
            float q0 = buf[n0][f];
            float q1 = buf[n0 + 1][f];
            float4 m = *(const float4*)&vm[f][vc];
            a00 += q0 * m.x; a01 += q0 * m.y; a02 += q0 * m.z; a03 += q0 * m.w;
            a10 += q1 * m.x; a11 += q1 * m.y; a12 += q1 * m.z; a13 += q1 * m.w;
        }
        if (tid < 128) {
            int n = tid >> 1, zi = tid & 1;
            float z = 1e-6f;
            #pragma unroll 8
            for (int f = 0; f < 64; f++) z += buf[n][f] * km2_s[zi][f];
            z_s[n][zi] = z;
        }
        __syncthreads();

        int zi = (vc >= 16) ? 1 : 0;
        float rz0 = 1.f / z_s[n0][zi];
        float rz1 = 1.f / z_s[n0 + 1][zi];
        size_t base0 = (size_t)(wg * WN + c0 + n0) * CDIM + h * 32 + vc;
        __half2 p00 = __halves2half2(__float2half(a00 * rz0), __float2half(a01 * rz0));
        __half2 p01 = __halves2half2(__float2half(a02 * rz0), __float2half(a03 * rz0));
        __half2 p10 = __halves2half2(__float2half(a10 * rz1), __float2half(a11 * rz1));
        __half2 p11 = __halves2half2(__float2half(a12 * rz1), __float2half(a13 * rz1));
        uint2 o0; o0.x = *(uint32_t*)&p00; o0.y = *(uint32_t*)&p01;
        uint2 o1; o1.x = *(uint32_t*)&p10; o1.y = *(uint32_t*)&p11;
        *(uint2*)&xo[base0] = o0;
        *(uint2*)&xo[base0 + CDIM] = o1;
        __syncthreads();
    }
}

// ---------------------------------------------------------------------------
// Depthwise 5^3 conv + (xo + vv) * g, in place on fp16 xo plane
// ---------------------------------------------------------------------------
__global__ void __launch_bounds__(256) dwconv_kernel(
    const __half* __restrict__ kvg, const float* __restrict__ dwc_w,
    const float* __restrict__ dwc_b, __half* __restrict__ xo16)
{
    extern __shared__ float sm[];
    float* v_s = sm;
    float* w_s = sm + 512 * 32;
    const int bh = blockIdx.x;
    const int b_ = bh / NHEADS, h = bh % NHEADS;
    const int tid = threadIdx.x;

    for (int i = tid; i < 512 * 32; i += 256) {
        int n = i >> 5, d = i & 31;
        v_s[i] = __half2float(kvg[(size_t)(b_ * WN + n) * KVGC + 384 + h * 32 + d]);
    }
    for (int i = tid; i < 125 * 32; i += 256) w_s[i] = dwc_w[i];
    __syncthreads();

    const int d  = tid & 31;
    const int lo = tid >> 5;
    const float bval = dwc_b[d];
    const size_t base = (size_t)b_ * (WN * CDIM) + (size_t)h * (WN * HD);

    for (int jg = 0; jg < 4; jg++) {
        float acc[16];
        #pragma unroll
        for (int jj = 0; jj < 16; jj++) acc[jj] = bval;
        for (int kd = 0; kd < 5; kd++) {
            for (int kh = 0; kh < 5; kh++) {
                for (int kw = 0; kw < 5; kw++) {
                    int li = lo + kw - 2;
                    if (li < 0 || li > 7) continue;
                    float w = w_s[((kd * 5 + kh) * 5 + kw) * 32 + d];
                    #pragma unroll
                    for (int jj = 0; jj < 16; jj++) {
                        int j = jg * 16 + jj;
                        int hi = (j >> 3) + kd - 2;
                        int wi = (j & 7) + kh - 2;
                        if (hi < 0 || hi > 7 || wi < 0 || wi > 7) continue;
                        acc[jj] += v_s[((hi * 8 + wi) * 8 + li) * 32 + d] * w;
                    }
                }
            }
        }
        #pragma unroll
        for (int jj = 0; jj < 16; jj++) {
            int j = jg * 16 + jj;
            size_t flat = base + (size_t)(lo + 8 * j) * 32 + d;
            size_t grow = flat / CDIM;
            int    gcol = (int)(flat % CDIM);
            float g = __half2float(kvg[grow * KVGC + 768 + gcol]);
            float val = (__half2float(xo16[flat]) + acc[jj]) * g;
            xo16[flat] = __float2half(val);
        }
    }
}

// ---------------------------------------------------------------------------
// kernel_launch
// ---------------------------------------------------------------------------
extern "C" void kernel_launch(void* const* d_in, const int* in_sizes, int n_in,
                              void* d_out, int out_size)
{
    const float* x       = (const float*)d_in[0];
    const float* y       = (const float*)d_in[1];
    const float* w_qkvg  = (const float*)d_in[2];
    const float* b_qkvg  = (const float*)d_in[3];
    const float* w_proj  = (const float*)d_in[4];
    const float* b_proj  = (const float*)d_in[5];
    const float* dwc_w   = (const float*)d_in[6];
    const float* dwc_b   = (const float*)d_in[7];
    const float* power_p = (const float*)d_in[8];
    const float* scale_p = (const float*)d_in[9];
    const float* pos_enc = (const float*)d_in[10];
    const float* g1      = (const float*)d_in[11];
    const float* b1      = (const float*)d_in[12];
    const float* g2      = (const float*)d_in[13];
    const float* b2      = (const float*)d_in[14];
    const float* w_fc1   = (const float*)d_in[15];
    const float* b_fc1   = (const float*)d_in[16];
    const float* w_fc2   = (const float*)d_in[17];
    const float* b_fc2   = (const float*)d_in[18];
    float* out = (float*)d_out;

    __half *p_xw16, *p_yw16, *p_hn16, *p_xo16, *p_h116, *p_kvg16, *p_qb16;
    __half *p_wqh, *p_wql, *p_wph, *p_wpl, *p_w1h, *p_w1l, *p_w2h, *p_w2l;
    float *p_aw, *p_x2;
    cudaGetSymbolAddress((void**)&p_xw16, d_xw16);
    cudaGetSymbolAddress((void**)&p_yw16, d_yw16);
    cudaGetSymbolAddress((void**)&p_hn16, d_hn16);
    cudaGetSymbolAddress((void**)&p_xo16, d_xo16);
    cudaGetSymbolAddress((void**)&p_h116, d_h116);
    cudaGetSymbolAddress((void**)&p_kvg16, d_kvg16);
    cudaGetSymbolAddress((void**)&p_qb16, d_qb16);
    cudaGetSymbolAddress((void**)&p_wqh, d_wqh);
    cudaGetSymbolAddress((void**)&p_wql, d_wql);
    cudaGetSymbolAddress((void**)&p_wph, d_wph);
    cudaGetSymbolAddress((void**)&p_wpl, d_wpl);
    cudaGetSymbolAddress((void**)&p_w1h, d_w1h);
    cudaGetSymbolAddress((void**)&p_w1l, d_w1l);
    cudaGetSymbolAddress((void**)&p_w2h, d_w2h);
    cudaGetSymbolAddress((void**)&p_w2l, d_w2l);
    cudaGetSymbolAddress((void**)&p_aw,  d_aw);
    cudaGetSymbolAddress((void**)&p_x2,  d_x2);

    const int conv_smem = (512 * 32 + 125 * 32) * (int)sizeof(float);
    cudaFuncSetAttribute(dwconv_kernel,
                         cudaFuncAttributeMaxDynamicSharedMemorySize, conv_smem);
    cudaFuncSetAttribute(mma_gemm<0,2>,
                         cudaFuncAttributeMaxDynamicSharedMemorySize, GSMEM_BYTES);
    cudaFuncSetAttribute(mma_gemm<1,1>,
                         cudaFuncAttributeMaxDynamicSharedMemorySize, GSMEM_BYTES);
    cudaFuncSetAttribute(mma_gemm<2,2>,
                         cudaFuncAttributeMaxDynamicSharedMemorySize, GSMEM_BYTES);
    cudaFuncSetAttribute(mma_gemm<3,2>,
                         cudaFuncAttributeMaxDynamicSharedMemorySize, GSMEM_BYTES);

    // 0) weight splits (fp16 hi/lo), single launch
    {
        int n0 = 1536*384/4, n1 = 384*384/4, n2 = 1536*384/4, n3 = 384*1536/4;
        int tot = n0 + n1 + n2 + n3;
        cvt_all_kernel<<<(tot + 255)/256, 256>>>(
            (const float4*)w_qkvg, (uint2*)p_wqh, (uint2*)p_wql, n0,
            (const float4*)w_proj, (uint2*)p_wph, (uint2*)p_wpl, n1,
            (const float4*)w_fc1,  (uint2*)p_w1h, (uint2*)p_w1l, n2,
            (const float4*)w_fc2,  (uint2*)p_w2h, (uint2*)p_w2l, n3);
    }

    // 1) LN + window partition -> fp16
    ln_win_kernel<<<BTROWS / 8, 256>>>(x, g1, b1, p_xw16);
    ln_win_kernel<<<BTROWS / 8, 256>>>(y, g1, b1, p_yw16);

    // 2) kvg = xw @ W[384:1536]^T + b[384:]   (N=1152, K=384) -> fp16
    mma_gemm<3,2><<<dim3(KVGC/128, BTROWS/128), 256, GSMEM_BYTES>>>(
        p_xw16, p_wqh + 384*384, p_wql + 384*384, b_qkvg + 384,
        nullptr, nullptr, p_kvg16, KVGC, 384);

    // 3) q = yw @ W[0:384]^T + b[0:384] -> fp16
    mma_gemm<3,2><<<dim3(CDIM/128, BTROWS/128), 256, GSMEM_BYTES>>>(
        p_yw16, p_wqh, p_wql, b_qkvg,
        nullptr, nullptr, p_qb16, CDIM, 384);

    // 4) attention -> xo16
    attn_kernel<<<dim3(NWIN, NHEADS), 256>>>(p_kvg16, p_qb16, pos_enc,
                                             scale_p, power_p, p_xo16);

    // 5) depthwise conv + gating, in place on xo16
    dwconv_kernel<<<NWIN * NHEADS, 256, conv_smem>>>(p_kvg16, dwc_w, dwc_b,
                                                     p_xo16);

    // 6) aw = xo @ w_proj^T + b_proj -> fp32
    mma_gemm<0,2><<<dim3(CDIM/128, BTROWS/128), 256, GSMEM_BYTES>>>(
        p_xo16, p_wph, p_wpl, b_proj,
        nullptr, p_aw, nullptr, CDIM, 384);

    // 7) x2 = x + window_reverse(aw); hn = LN2(x2) -> fp16
    resln_kernel<<<BTROWS / 8, 256>>>(x, p_aw, g2, b2, p_x2, p_hn16);

    // 8) h1 = gelu(hn @ w_fc1^T + b_fc1) -> fp16, SINGLE pass (N=1536, K=384)
    mma_gemm<1,1><<<dim3(HIDDEN/128, BTROWS/128), 256, GSMEM_BYTES>>>(
        p_hn16, p_w1h, nullptr, b_fc1,
        nullptr, nullptr, p_h116, HIDDEN, 384);

    // 9) out = x2 + h1 @ w_fc2^T + b_fc2    (N=384, K=1536)
    mma_gemm<2,2><<<dim3(CDIM/128, BTROWS/128), 256, GSMEM_BYTES>>>(
        p_h116, p_w2h, p_w2l, b_fc2,
        p_x2, out, nullptr, CDIM, 1536);
}

// round 8
// speedup vs baseline: 4.1442x; 1.1223x over previous
#include <cuda_runtime.h>
#include <cuda_fp16.h>
#include <math.h>
#include <stdint.h>

// ---------------------------------------------------------------------------
// Problem constants
// ---------------------------------------------------------------------------
#define BATCH   2
#define RES_H   32
#define RES_W   32
#define RES_L   16
#define WSZ     8
#define CDIM    384
#define NHEADS  12
#define HD      32
#define NTOK    (RES_H*RES_W*RES_L)       // 16384
#define BTROWS  (BATCH*NTOK)              // 32768
#define NWIN_B  ((RES_H/WSZ)*(RES_W/WSZ)*(RES_L/WSZ))  // 32
#define NWIN    (BATCH*NWIN_B)            // 64
#define WN      (WSZ*WSZ*WSZ)             // 512
#define KVGC    1152
#define HIDDEN  1536

// ---------------------------------------------------------------------------
// Scratch (static device globals)
// ---------------------------------------------------------------------------
static __device__ __align__(256) __half d_xw16[BTROWS*CDIM];
static __device__ __align__(256) __half d_yw16[BTROWS*CDIM];
static __device__ __align__(256) __half d_hn16[BTROWS*CDIM];
static __device__ __align__(256) __half d_xo16[BTROWS*CDIM];
static __device__ __align__(256) __half d_h116[BTROWS*HIDDEN];
static __device__ __align__(256) __half d_kvg16[BTROWS*KVGC];
static __device__ __align__(256) __half d_qb16[BTROWS*CDIM];
static __device__ __align__(256) __half d_wqh[1536*384];
static __device__ __align__(256) __half d_wql[1536*384];
static __device__ __align__(256) __half d_wph[384*384];
static __device__ __align__(256) __half d_wpl[384*384];
static __device__ __align__(256) __half d_w1h[1536*384];
static __device__ __align__(256) __half d_w2h[384*1536];

static __device__ float d_aw [BTROWS*CDIM];
static __device__ float d_x2 [BTROWS*CDIM];

// ---------------------------------------------------------------------------
// PTX helpers
// ---------------------------------------------------------------------------
__device__ __forceinline__ uint32_t smem_u32(const void* p) {
    uint32_t a;
    asm("{ .reg .u64 t; cvta.to.shared.u64 t, %1; cvt.u32.u64 %0, t; }"
        : "=r"(a) : "l"(p));
    return a;
}
__device__ __forceinline__ void cp_async16(uint32_t dst, const void* src) {
    asm volatile("cp.async.cg.shared.global [%0], [%1], 16;"
        :: "r"(dst), "l"(src) : "memory");
}
__device__ __forceinline__ void ldm4(uint32_t* r, uint32_t addr) {
    asm volatile("ldmatrix.sync.aligned.m8n8.x4.shared.b16 {%0,%1,%2,%3}, [%4];"
        : "=r"(r[0]), "=r"(r[1]), "=r"(r[2]), "=r"(r[3]) : "r"(addr));
}
__device__ __forceinline__ void mma16816(float* c, const uint32_t* a, const uint32_t* b) {
    asm volatile("mma.sync.aligned.m16n8k16.row.col.f32.f16.f16.f32 "
        "{%0,%1,%2,%3}, {%4,%5,%6,%7}, {%8,%9}, {%0,%1,%2,%3};"
        : "+f"(c[0]), "+f"(c[1]), "+f"(c[2]), "+f"(c[3])
        : "r"(a[0]), "r"(a[1]), "r"(a[2]), "r"(a[3]), "r"(b[0]), "r"(b[1]));
}

// ---------------------------------------------------------------------------
// misc helpers
// ---------------------------------------------------------------------------
__device__ __forceinline__ float warp_sum(float v) {
    #pragma unroll
    for (int o = 16; o; o >>= 1) v += __shfl_xor_sync(0xffffffffu, v, o);
    return v;
}
__device__ __forceinline__ int window_row(int bt) {
    int bb = bt >> 14;
    int t  = bt & 16383;
    int hh = t >> 9;
    int ww = (t >> 4) & 31;
    int ll = t & 15;
    int win = bb * NWIN_B + (((hh >> 3) * 4 + (ww >> 3)) * 2 + (ll >> 3));
    int n   = (((hh & 7) << 3) + (ww & 7)) * 8 + (ll & 7);
    return win * WN + n;
}
__device__ __forceinline__ void split_h16(float v, __half& h, __half& l) {
    h = __float2half(v);
    l = __float2half(v - __half2float(h));
}
// fast x^p for x >= 0 (x==0 -> lg2 gives -inf -> ex2 gives 0)
__device__ __forceinline__ float fast_pow(float m, float p) {
    float lg, r;
    asm("lg2.approx.f32 %0, %1;" : "=f"(lg) : "f"(m));
    asm("ex2.approx.f32 %0, %1;" : "=f"(r) : "f"(p * lg));
    return r;
}

// ---------------------------------------------------------------------------
// all weights: fp32 -> fp16 hi/lo split, single launch (lo optional)
// ---------------------------------------------------------------------------
__global__ void __launch_bounds__(256) cvt_all_kernel(
    const float4* __restrict__ s0, uint2* __restrict__ h0, uint2* __restrict__ l0, int n0,
    const float4* __restrict__ s1, uint2* __restrict__ h1, uint2* __restrict__ l1, int n1,
    const float4* __restrict__ s2, uint2* __restrict__ h2, uint2* __restrict__ l2, int n2,
    const float4* __restrict__ s3, uint2* __restrict__ h3, uint2* __restrict__ l3, int n3)
{
    int i = blockIdx.x * blockDim.x + threadIdx.x;
    const float4* s; uint2 *hp, *lp; int idx;
    if (i < n0)                { s = s0; hp = h0; lp = l0; idx = i; }
    else if (i < n0+n1)        { s = s1; hp = h1; lp = l1; idx = i - n0; }
    else if (i < n0+n1+n2)     { s = s2; hp = h2; lp = l2; idx = i - n0 - n1; }
    else if (i < n0+n1+n2+n3)  { s = s3; hp = h3; lp = l3; idx = i - n0 - n1 - n2; }
    else return;
    float4 v = s[idx];
    __half a0, a1, a2, a3, b0, b1, b2, b3;
    split_h16(v.x, a0, b0); split_h16(v.y, a1, b1);
    split_h16(v.z, a2, b2); split_h16(v.w, a3, b3);
    __half2 ph0 = __halves2half2(a0, a1);
    __half2 ph1 = __halves2half2(a2, a3);
    uint2 uh; uh.x = *(uint32_t*)&ph0; uh.y = *(uint32_t*)&ph1;
    hp[idx] = uh;
    if (lp) {
        __half2 pl0 = __halves2half2(b0, b1);
        __half2 pl1 = __halves2half2(b2, b3);
        uint2 ul; ul.x = *(uint32_t*)&pl0; ul.y = *(uint32_t*)&pl1;
        lp[idx] = ul;
    }
}

// ---------------------------------------------------------------------------
// LayerNorm fused with window partition -> fp16; y selects (x->xw | y->yw)
// ---------------------------------------------------------------------------
__global__ void __launch_bounds__(256) ln_win_kernel(
    const float* __restrict__ xa, const float* __restrict__ xb,
    const float* __restrict__ g, const float* __restrict__ b,
    __half* __restrict__ oa, __half* __restrict__ ob)
{
    int warp = (blockIdx.x * blockDim.x + threadIdx.x) >> 5;
    int lane = threadIdx.x & 31;
    if (warp >= BTROWS) return;
    const float* x = blockIdx.y ? xb : xa;
    __half* o16 = blockIdx.y ? ob : oa;
    const float* xr = x + (size_t)warp * CDIM;
    float v[12];
    float s = 0.f;
    #pragma unroll
    for (int i = 0; i < 12; i++) { v[i] = xr[lane + i * 32]; s += v[i]; }
    s = warp_sum(s);
    float mu = s * (1.f / 384.f);
    float sq = 0.f;
    #pragma unroll
    for (int i = 0; i < 12; i++) { float dv = v[i] - mu; sq += dv * dv; }
    sq = warp_sum(sq);
    float rstd = rsqrtf(sq * (1.f / 384.f) + 1e-5f);
    size_t ro = (size_t)window_row(warp) * CDIM;
    #pragma unroll
    for (int i = 0; i < 12; i++) {
        int c = lane + i * 32;
        float o = (v[i] - mu) * rstd * g[c] + b[c];
        o16[ro + c] = __float2half(o);
    }
}

// ---------------------------------------------------------------------------
// residual-add (window_reverse) + LN2 -> x2 fp32, hn fp16
// ---------------------------------------------------------------------------
__global__ void __launch_bounds__(256) resln_kernel(
    const float* __restrict__ x, const float* __restrict__ aw,
    const float* __restrict__ g, const float* __restrict__ b,
    float* __restrict__ x2, __half* __restrict__ hn)
{
    int warp = (blockIdx.x * blockDim.x + threadIdx.x) >> 5;
    int lane = threadIdx.x & 31;
    if (warp >= BTROWS) return;
    const float* xr = x  + (size_t)warp * CDIM;
    const float* ar = aw + (size_t)window_row(warp) * CDIM;
    float v[12];
    float s = 0.f;
    #pragma unroll
    for (int i = 0; i < 12; i++) {
        int c = lane + i * 32;
        v[i] = xr[c] + ar[c];
        s += v[i];
    }
    s = warp_sum(s);
    float mu = s * (1.f / 384.f);
    float sq = 0.f;
    #pragma unroll
    for (int i = 0; i < 12; i++) { float dv = v[i] - mu; sq += dv * dv; }
    sq = warp_sum(sq);
    float rstd = rsqrtf(sq * (1.f / 384.f) + 1e-5f);
    size_t ro = (size_t)warp * CDIM;
    #pragma unroll
    for (int i = 0; i < 12; i++) {
        int c = lane + i * 32;
        x2[ro + c] = v[i];
        float o = (v[i] - mu) * rstd * g[c] + b[c];
        hn[ro + c] = __float2half(o);
    }
}

// ---------------------------------------------------------------------------
// mma.sync GEMM: C[M,N] = A[M,K] @ W[N,K]^T (+ bias / gelu / residual)
// A single fp16 plane; W hi(+lo) fp16 planes (PASSES=1 or 2).
// BM=BN=128, BK=32, 256 threads, 8 warps (2Mx4N), warp tile 64x32, m16n8k16.
// 4-stage cp.async pipeline, XOR-swizzled smem, 2 CTAs/SM.
// EPI: 0 = bias->fp32 C, 1 = bias+gelu->fp16 C16, 2 = bias+res->fp32 C,
//      3 = bias->fp16 C16
// ---------------------------------------------------------------------------
#define GSTAGE 24576
#define GSMEM_BYTES (4*GSTAGE)

template <int EPI, int PASSES>
__global__ void __launch_bounds__(256, 2) mma_gemm(
    const __half* __restrict__ A, const __half* __restrict__ Bh,
    const __half* __restrict__ Bl, const float* __restrict__ bias,
    const float* __restrict__ res, float* __restrict__ C,
    __half* __restrict__ C16, int N, int K)
{
    extern __shared__ char smem[];
    const uint32_t sbase = smem_u32(smem);
    const int tid  = threadIdx.x;
    const int lane = tid & 31;
    const int wid  = tid >> 5;
    const int wm   = wid & 1;
    const int wn   = wid >> 1;
    const int bm = blockIdx.y * 128;
    const int bn = blockIdx.x * 128;

    float acc[4][4][4];
    #pragma unroll
    for (int i = 0; i < 4; i++)
        #pragma unroll
        for (int j = 0; j < 4; j++)
            #pragma unroll
            for (int q = 0; q < 4; q++) acc[i][j][q] = 0.f;

    #define LOAD_STAGE(stage, k0) do {                                        \
        uint32_t sb_ = sbase + (uint32_t)(stage) * GSTAGE;                    \
        const __half* bases_[3] = {A, Bh, Bl};                                \
        _Pragma("unroll")                                                     \
        for (int sub_ = 0; sub_ < 1 + PASSES; sub_++) {                       \
            const __half* bp_ = bases_[sub_];                                 \
            int ro_ = (sub_ == 0) ? bm : bn;                                  \
            _Pragma("unroll")                                                 \
            for (int jj_ = 0; jj_ < 2; jj_++) {                               \
                int cid_ = tid + 256 * jj_;                                   \
                int row_ = cid_ >> 2, ck_ = cid_ & 3;                         \
                int cs_ = ck_ ^ ((row_ >> 1) & 3);                            \
                const void* src_ = bp_ + (size_t)(ro_ + row_) * K + (k0) + ck_ * 8; \
                cp_async16(sb_ + (uint32_t)(sub_ << 13)                       \
                           + (uint32_t)(row_ * 64 + cs_ * 16), src_);         \
            }                                                                 \
        }                                                                     \
    } while (0)

    const int NC = K >> 5;
    LOAD_STAGE(0, 0);
    asm volatile("cp.async.commit_group;" ::: "memory");
    LOAD_STAGE(1, 32);
    asm volatile("cp.async.commit_group;" ::: "memory");
    LOAD_STAGE(2, 64);
    asm volatile("cp.async.commit_group;" ::: "memory");

    const int arow = wm * 64 + (lane & 15);
    const int asel = lane >> 4;
    const int brow = wn * 32 + ((lane >> 4) << 3) + (lane & 7);
    const int bsel = (lane >> 3) & 1;

    for (int c = 0; c < NC; c++) {
        asm volatile("cp.async.wait_group 2;" ::: "memory");
        __syncthreads();
        if (c + 3 < NC) {
            LOAD_STAGE((c + 3) & 3, (c + 3) << 5);
            asm volatile("cp.async.commit_group;" ::: "memory");
        }

        const uint32_t sb = sbase + (uint32_t)(c & 3) * GSTAGE;
        #pragma unroll
        for (int kk = 0; kk < 2; kk++) {
            uint32_t a[4][4], bh[2][4], bl[2][4];
            #pragma unroll
            for (int mt = 0; mt < 4; mt++) {
                int row = arow + mt * 16;
                int ck  = kk * 2 + asel;
                uint32_t off = (uint32_t)(row * 64 + (ck ^ ((row >> 1) & 3)) * 16);
                ldm4(a[mt], sb + off);
            }
            #pragma unroll
            for (int bt = 0; bt < 2; bt++) {
                int row = brow + bt * 16;
                int ck  = kk * 2 + bsel;
                uint32_t off = (uint32_t)(row * 64 + (ck ^ ((row >> 1) & 3)) * 16);
                ldm4(bh[bt], sb + 8192u + off);
                if (PASSES == 2) ldm4(bl[bt], sb + 16384u + off);
            }
            #pragma unroll
            for (int mt = 0; mt < 4; mt++) {
                #pragma unroll
                for (int nt = 0; nt < 4; nt++) {
                    const uint32_t* bhf = &bh[nt >> 1][(nt & 1) * 2];
                    mma16816(acc[mt][nt], a[mt], bhf);
                    if (PASSES == 2) {
                        const uint32_t* blf = &bl[nt >> 1][(nt & 1) * 2];
                        mma16816(acc[mt][nt], a[mt], blf);
                    }
                }
            }
        }
    }

    // ---- epilogue ----
    const int gr = lane >> 2;
    const int nc0 = (lane & 3) * 2;
    #pragma unroll
    for (int mt = 0; mt < 4; mt++) {
        #pragma unroll
        for (int nt = 0; nt < 4; nt++) {
            int col = bn + wn * 32 + nt * 8 + nc0;
            float bs0 = bias[col], bs1 = bias[col + 1];
            #pragma unroll
            for (int half = 0; half < 2; half++) {
                int row = bm + wm * 64 + mt * 16 + gr + half * 8;
                float v0 = acc[mt][nt][half * 2 + 0] + bs0;
                float v1 = acc[mt][nt][half * 2 + 1] + bs1;
                size_t off = (size_t)row * N + col;
                if (EPI == 1 || EPI == 3) {
                    if (EPI == 1) {
                        v0 = 0.5f * v0 * (1.f + erff(v0 * 0.70710678118654752f));
                        v1 = 0.5f * v1 * (1.f + erff(v1 * 0.70710678118654752f));
                    }
                    __half2 p = __halves2half2(__float2half(v0), __float2half(v1));
                    *(uint32_t*)(C16 + off) = *(uint32_t*)&p;
                } else {
                    if (EPI == 2) { v0 += res[off]; v1 += res[off + 1]; }
                    float2 o; o.x = v0; o.y = v1;
                    *(float2*)(C + off) = o;
                }
            }
        }
    }
    #undef LOAD_STAGE
}

// ---------------------------------------------------------------------------
// Pola linear attention, one block per (window, head). 256 threads.
// Phase A retiled: 4f x 4d per thread, n split across two 128-thread halves.
// ---------------------------------------------------------------------------
__global__ void __launch_bounds__(256) attn_kernel(
    const __half* __restrict__ kvg, const __half* __restrict__ qb,
    const float* __restrict__ pos_enc, const float* __restrict__ scale_p,
    const float* __restrict__ power_p, __half* __restrict__ xo)
{
    const int wg = blockIdx.x;   // 0..63
    const int h  = blockIdx.y;   // 0..11
    const int tid = threadIdx.x;

    __shared__ float sc_s[32], pw_s[32];
    __shared__ float buf[64][68];    // kc (phase A) / qf (phase C); 16B-aligned rows
    __shared__ float vm[64][36];     // v (phase A) / kv partial / M (phase C)
    __shared__ float km2_s[2][64];
    __shared__ float z_s[64][2];

    if (tid < 32) {
        float sp = scale_p[h * 32 + tid];
        sc_s[tid] = 1.f / log1pf(expf(sp));          // 1/softplus
        float pp = power_p[h * 32 + tid];
        pw_s[tid] = 1.f + 4.f / (1.f + expf(-pp));   // 1 + ALPHA*sigmoid
    }
    __syncthreads();

    const int nh = tid >> 7;          // n-half 0/1
    const int tt = tid & 127;
    const int fq = (tt >> 3) << 2;    // f0: 0,4,..,60
    const int dq = (tt & 7) << 2;     // d0: 0,4,..,28

    float acc[4][4];
    #pragma unroll
    for (int i = 0; i < 4; i++)
        #pragma unroll
        for (int j = 0; j < 4; j++) acc[i][j] = 0.f;
    float ksum = 0.f;

    // -------- phase A: kc features, kv = kc^T v (n-split), ksum --------
    for (int c0 = 0; c0 < WN; c0 += 64) {
        #pragma unroll
        for (int i = 0; i < 8; i++) {
            int idx = tid + 256 * i;
            int nl = idx >> 5;
            int d  = idx & 31;
            int row = wg * WN + c0 + nl;
            float kval = (__half2float(kvg[(size_t)row * KVGC + h * 32 + d])
                          + pos_enc[(c0 + nl) * CDIM + h * 32 + d]) * sc_s[d];
            float r = fast_pow(fabsf(kval), pw_s[d]);
            buf[nl][d]      = kval > 0.f ? r : 0.f;
            buf[nl][d + 32] = kval < 0.f ? r : 0.f;
            vm[nl][d] = __half2float(kvg[(size_t)row * KVGC + 384 + h * 32 + d]);
        }
        __syncthreads();
        #pragma unroll 4
        for (int n = 0; n < 32; n++) {
            int nn = (nh << 5) + n;
            float4 kq = *(const float4*)&buf[nn][fq];
            float4 v4 = *(const float4*)&vm[nn][dq];
            acc[0][0] += kq.x * v4.x; acc[0][1] += kq.x * v4.y;
            acc[0][2] += kq.x * v4.z; acc[0][3] += kq.x * v4.w;
            acc[1][0] += kq.y * v4.x; acc[1][1] += kq.y * v4.y;
            acc[1][2] += kq.y * v4.z; acc[1][3] += kq.y * v4.w;
            acc[2][0] += kq.z * v4.x; acc[2][1] += kq.z * v4.y;
            acc[2][2] += kq.z * v4.z; acc[2][3] += kq.z * v4.w;
            acc[3][0] += kq.w * v4.x; acc[3][1] += kq.w * v4.y;
            acc[3][2] += kq.w * v4.z; acc[3][3] += kq.w * v4.w;
        }
        if (tid < 64) {
            float s = ksum;
            #pragma unroll 8
            for (int n = 0; n < 64; n++) s += buf[n][tid];
            ksum = s;
        }
        __syncthreads();
    }

    // -------- merge n-halves, write M (reordered kv) and km vectors --------
    if (nh == 1) {
        #pragma unroll
        for (int i = 0; i < 4; i++)
            #pragma unroll
            for (int j = 0; j < 4; j++)
                vm[fq + i][dq + j] = acc[i][j];
    }
    __syncthreads();
    float mreg[4][4];
    if (nh == 0) {
        const float sN2 = 1.f / 512.f;
        #pragma unroll
        for (int i = 0; i < 4; i++)
            #pragma unroll
            for (int j = 0; j < 4; j++)
                mreg[i][j] = (acc[i][j] + vm[fq + i][dq + j]) * sN2;
    }
    if (tid < 64) {
        float km = ksum * (1.f / 512.f);
        km2_s[0][tid] = km;
        km2_s[1][(tid + 32) & 63] = km;
    }
    __syncthreads();
    if (nh == 0) {
        // M[g][d<16] = kv[g][d];  M[g][d>=16] = kv[(g+32)&63][d]
        // inverse: row fr of M gets kv row f where fr = f (d<16) or (f+32)&63
        #pragma unroll
        for (int i = 0; i < 4; i++) {
            int fr = (dq < 16) ? (fq + i) : ((fq + i + 32) & 63);
            #pragma unroll
            for (int j = 0; j < 4; j++)
                vm[fr][dq + j] = mreg[i][j];
        }
    }
    __syncthreads();

    // -------- phase C: q features + O = qf @ M, z, write --------
    const int n0 = (tid >> 3) << 1;   // 0,2,..,62
    const int vc = (tid & 7) << 2;    // 0,4,..,28
    for (int c0 = 0; c0 < WN; c0 += 64) {
        #pragma unroll
        for (int i = 0; i < 8; i++) {
            int idx = tid + 256 * i;
            int nl = idx >> 5;
            int d  = idx & 31;
            int row = wg * WN + c0 + nl;
            float qv = __half2float(qb[(size_t)row * CDIM + h * 32 + d]) * sc_s[d];
            float r = fast_pow(fabsf(qv), pw_s[d]);
            buf[nl][d]      = qv > 0.f ? r : 0.f;
            buf[nl][d + 32] = qv < 0.f ? r : 0.f;
        }
        __syncthreads();

        float a00 = 0.f, a01 = 0.f, a02 = 0.f, a03 = 0.f;
        float a10 = 0.f, a11 = 0.f, a12 = 0.f, a13 = 0.f;
        #pragma unroll 4
        for (int f = 0; f < 64; f++) {
            float q0 = buf[n0][f];
            float q1 = buf[n0 + 1][f];
            float4 m = *(const float4*)&vm[f][vc];
            a00 += q0 * m.x; a01 += q0 * m.y; a02 += q0 * m.z; a03 += q0 * m.w;
            a10 += q1 * m.x; a11 += q1 * m.y; a12 += q1 * m.z; a13 += q1 * m.w;
        }
        if (tid < 128) {
            int n = tid >> 1, zi = tid & 1;
            float z = 1e-6f;
            #pragma unroll 8
            for (int f = 0; f < 64; f++) z += buf[n][f] * km2_s[zi][f];
            z_s[n][zi] = z;
        }
        __syncthreads();

        int zi = (vc >= 16) ? 1 : 0;
        float rz0 = 1.f / z_s[n0][zi];
        float rz1 = 1.f / z_s[n0 + 1][zi];
        size_t base0 = (size_t)(wg * WN + c0 + n0) * CDIM + h * 32 + vc;
        __half2 p00 = __halves2half2(__float2half(a00 * rz0), __float2half(a01 * rz0));
        __half2 p01 = __halves2half2(__float2half(a02 * rz0), __float2half(a03 * rz0));
        __half2 p10 = __halves2half2(__float2half(a10 * rz1), __float2half(a11 * rz1));
        __half2 p11 = __halves2half2(__float2half(a12 * rz1), __float2half(a13 * rz1));
        uint2 o0; o0.x = *(uint32_t*)&p00; o0.y = *(uint32_t*)&p01;
        uint2 o1; o1.x = *(uint32_t*)&p10; o1.y = *(uint32_t*)&p11;
        *(uint2*)&xo[base0] = o0;
        *(uint2*)&xo[base0 + CDIM] = o1;
        __syncthreads();
    }
}

// ---------------------------------------------------------------------------
// Depthwise 5^3 conv + (xo + vv) * g, in place on fp16 xo plane
// ---------------------------------------------------------------------------
__global__ void __launch_bounds__(256) dwconv_kernel(
    const __half* __restrict__ kvg, const float* __restrict__ dwc_w,
    const float* __restrict__ dwc_b, __half* __restrict__ xo16)
{
    extern __shared__ float sm[];
    float* v_s = sm;
    float* w_s = sm + 512 * 32;
    const int bh = blockIdx.x;
    const int b_ = bh / NHEADS, h = bh % NHEADS;
    const int tid = threadIdx.x;

    for (int i = tid; i < 512 * 32; i += 256) {
        int n = i >> 5, d = i & 31;
        v_s[i] = __half2float(kvg[(size_t)(b_ * WN + n) * KVGC + 384 + h * 32 + d]);
    }
    for (int i = tid; i < 125 * 32; i += 256) w_s[i] = dwc_w[i];
    __syncthreads();

    const int d  = tid & 31;
    const int lo = tid >> 5;
    const float bval = dwc_b[d];
    const size_t base = (size_t)b_ * (WN * CDIM) + (size_t)h * (WN * HD);

    for (int jg = 0; jg < 4; jg++) {
        float acc[16];
        #pragma unroll
        for (int jj = 0; jj < 16; jj++) acc[jj] = bval;
        for (int kd = 0; kd < 5; kd++) {
            for (int kh = 0; kh < 5; kh++) {
                for (int kw = 0; kw < 5; kw++) {
                    int li = lo + kw - 2;
                    if (li < 0 || li > 7) continue;
                    float w = w_s[((kd * 5 + kh) * 5 + kw) * 32 + d];
                    #pragma unroll
                    for (int jj = 0; jj < 16; jj++) {
                        int j = jg * 16 + jj;
                        int hi = (j >> 3) + kd - 2;
                        int wi = (j & 7) + kh - 2;
                        if (hi < 0 || hi > 7 || wi < 0 || wi > 7) continue;
                        acc[jj] += v_s[((hi * 8 + wi) * 8 + li) * 32 + d] * w;
                    }
                }
            }
        }
        #pragma unroll
        for (int jj = 0; jj < 16; jj++) {
            int j = jg * 16 + jj;
            size_t flat = base + (size_t)(lo + 8 * j) * 32 + d;
            size_t grow = flat / CDIM;
            int    gcol = (int)(flat % CDIM);
            float g = __half2float(kvg[grow * KVGC + 768 + gcol]);
            float val = (__half2float(xo16[flat]) + acc[jj]) * g;
            xo16[flat] = __float2half(val);
        }
    }
}

// ---------------------------------------------------------------------------
// kernel_launch
// ---------------------------------------------------------------------------
extern "C" void kernel_launch(void* const* d_in, const int* in_sizes, int n_in,
                              void* d_out, int out_size)
{
    const float* x       = (const float*)d_in[0];
    const float* y       = (const float*)d_in[1];
    const float* w_qkvg  = (const float*)d_in[2];
    const float* b_qkvg  = (const float*)d_in[3];
    const float* w_proj  = (const float*)d_in[4];
    const float* b_proj  = (const float*)d_in[5];
    const float* dwc_w   = (const float*)d_in[6];
    const float* dwc_b   = (const float*)d_in[7];
    const float* power_p = (const float*)d_in[8];
    const float* scale_p = (const float*)d_in[9];
    const float* pos_enc = (const float*)d_in[10];
    const float* g1      = (const float*)d_in[11];
    const float* b1      = (const float*)d_in[12];
    const float* g2      = (const float*)d_in[13];
    const float* b2      = (const float*)d_in[14];
    const float* w_fc1   = (const float*)d_in[15];
    const float* b_fc1   = (const float*)d_in[16];
    const float* w_fc2   = (const float*)d_in[17];
    const float* b_fc2   = (const float*)d_in[18];
    float* out = (float*)d_out;

    __half *p_xw16, *p_yw16, *p_hn16, *p_xo16, *p_h116, *p_kvg16, *p_qb16;
    __half *p_wqh, *p_wql, *p_wph, *p_wpl, *p_w1h, *p_w2h;
    float *p_aw, *p_x2;
    cudaGetSymbolAddress((void**)&p_xw16, d_xw16);
    cudaGetSymbolAddress((void**)&p_yw16, d_yw16);
    cudaGetSymbolAddress((void**)&p_hn16, d_hn16);
    cudaGetSymbolAddress((void**)&p_xo16, d_xo16);
    cudaGetSymbolAddress((void**)&p_h116, d_h116);
    cudaGetSymbolAddress((void**)&p_kvg16, d_kvg16);
    cudaGetSymbolAddress((void**)&p_qb16, d_qb16);
    cudaGetSymbolAddress((void**)&p_wqh, d_wqh);
    cudaGetSymbolAddress((void**)&p_wql, d_wql);
    cudaGetSymbolAddress((void**)&p_wph, d_wph);
    cudaGetSymbolAddress((void**)&p_wpl, d_wpl);
    cudaGetSymbolAddress((void**)&p_w1h, d_w1h);
    cudaGetSymbolAddress((void**)&p_w2h, d_w2h);
    cudaGetSymbolAddress((void**)&p_aw,  d_aw);
    cudaGetSymbolAddress((void**)&p_x2,  d_x2);

    const int conv_smem = (512 * 32 + 125 * 32) * (int)sizeof(float);
    cudaFuncSetAttribute(dwconv_kernel,
                         cudaFuncAttributeMaxDynamicSharedMemorySize, conv_smem);
    cudaFuncSetAttribute(mma_gemm<0,2>,
                         cudaFuncAttributeMaxDynamicSharedMemorySize, GSMEM_BYTES);
    cudaFuncSetAttribute(mma_gemm<1,1>,
                         cudaFuncAttributeMaxDynamicSharedMemorySize, GSMEM_BYTES);
    cudaFuncSetAttribute(mma_gemm<2,1>,
                         cudaFuncAttributeMaxDynamicSharedMemorySize, GSMEM_BYTES);
    cudaFuncSetAttribute(mma_gemm<3,2>,
                         cudaFuncAttributeMaxDynamicSharedMemorySize, GSMEM_BYTES);

    // 0) weight splits (fp16 hi/lo; fc1+fc2 hi-only), single launch
    {
        int n0 = 1536*384/4, n1 = 384*384/4, n2 = 1536*384/4, n3 = 384*1536/4;
        int tot = n0 + n1 + n2 + n3;
        cvt_all_kernel<<<(tot + 255)/256, 256>>>(
            (const float4*)w_qkvg, (uint2*)p_wqh, (uint2*)p_wql, n0,
            (const float4*)w_proj, (uint2*)p_wph, (uint2*)p_wpl, n1,
            (const float4*)w_fc1,  (uint2*)p_w1h, nullptr, n2,
            (const float4*)w_fc2,  (uint2*)p_w2h, nullptr, n3);
    }

    // 1) LN + window partition (x and y in one launch) -> fp16
    ln_win_kernel<<<dim3(BTROWS / 8, 2), 256>>>(x, y, g1, b1, p_xw16, p_yw16);

    // 2) kvg = xw @ W[384:1536]^T + b[384:]   (N=1152, K=384) -> fp16, 2-pass
    mma_gemm<3,2><<<dim3(KVGC/128, BTROWS/128), 256, GSMEM_BYTES>>>(
        p_xw16, p_wqh + 384*384, p_wql + 384*384, b_qkvg + 384,
        nullptr, nullptr, p_kvg16, KVGC, 384);

    // 3) q = yw @ W[0:384]^T + b[0:384] -> fp16, 2-pass
    mma_gemm<3,2><<<dim3(CDIM/128, BTROWS/128), 256, GSMEM_BYTES>>>(
        p_yw16, p_wqh, p_wql, b_qkvg,
        nullptr, nullptr, p_qb16, CDIM, 384);

    // 4) attention -> xo16
    attn_kernel<<<dim3(NWIN, NHEADS), 256>>>(p_kvg16, p_qb16, pos_enc,
                                             scale_p, power_p, p_xo16);

    // 5) depthwise conv + gating, in place on xo16
    dwconv_kernel<<<NWIN * NHEADS, 256, conv_smem>>>(p_kvg16, dwc_w, dwc_b,
                                                     p_xo16);

    // 6) aw = xo @ w_proj^T + b_proj -> fp32, 2-pass
    mma_gemm<0,2><<<dim3(CDIM/128, BTROWS/128), 256, GSMEM_BYTES>>>(
        p_xo16, p_wph, p_wpl, b_proj,
        nullptr, p_aw, nullptr, CDIM, 384);

    // 7) x2 = x + window_reverse(aw); hn = LN2(x2) -> fp16
    resln_kernel<<<BTROWS / 8, 256>>>(x, p_aw, g2, b2, p_x2, p_hn16);

    // 8) h1 = gelu(hn @ w_fc1^T + b_fc1) -> fp16, single pass (N=1536, K=384)
    mma_gemm<1,1><<<dim3(HIDDEN/128, BTROWS/128), 256, GSMEM_BYTES>>>(
        p_hn16, p_w1h, nullptr, b_fc1,
        nullptr, nullptr, p_h116, HIDDEN, 384);

    // 9) out = x2 + h1 @ w_fc2^T + b_fc2, single pass (N=384, K=1536)
    mma_gemm<2,1><<<dim3(CDIM/128, BTROWS/128), 256, GSMEM_BYTES>>>(
        p_h116, p_w2h, nullptr, b_fc2,
        p_x2, out, nullptr, CDIM, 1536);
}

// round 9
// speedup vs baseline: 4.5424x; 1.0961x over previous
#include <cuda_runtime.h>
#include <cuda_fp16.h>
#include <math.h>
#include <stdint.h>

// ---------------------------------------------------------------------------
// Problem constants
// ---------------------------------------------------------------------------
#define BATCH   2
#define RES_H   32
#define RES_W   32
#define RES_L   16
#define WSZ     8
#define CDIM    384
#define NHEADS  12
#define HD      32
#define NTOK    (RES_H*RES_W*RES_L)       // 16384
#define BTROWS  (BATCH*NTOK)              // 32768
#define NWIN_B  ((RES_H/WSZ)*(RES_W/WSZ)*(RES_L/WSZ))  // 32
#define NWIN    (BATCH*NWIN_B)            // 64
#define WN      (WSZ*WSZ*WSZ)             // 512
#define KVGC    1152
#define HIDDEN  1536

// ---------------------------------------------------------------------------
// Scratch (static device globals)
// ---------------------------------------------------------------------------
static __device__ __align__(256) __half d_xw16[BTROWS*CDIM];
static __device__ __align__(256) __half d_yw16[BTROWS*CDIM];
static __device__ __align__(256) __half d_hn16[BTROWS*CDIM];
static __device__ __align__(256) __half d_xo16[BTROWS*CDIM];
static __device__ __align__(256) __half d_h116[BTROWS*HIDDEN];
static __device__ __align__(256) __half d_kvg16[BTROWS*KVGC];
static __device__ __align__(256) __half d_qb16[BTROWS*CDIM];
static __device__ __align__(256) __half d_wqh[1536*384];
static __device__ __align__(256) __half d_wph[384*384];
static __device__ __align__(256) __half d_w1h[1536*384];
static __device__ __align__(256) __half d_w2h[384*1536];

static __device__ float d_aw [BTROWS*CDIM];
static __device__ float d_x2 [BTROWS*CDIM];

// ---------------------------------------------------------------------------
// PTX helpers
// ---------------------------------------------------------------------------
__device__ __forceinline__ uint32_t smem_u32(const void* p) {
    uint32_t a;
    asm("{ .reg .u64 t; cvta.to.shared.u64 t, %1; cvt.u32.u64 %0, t; }"
        : "=r"(a) : "l"(p));
    return a;
}
__device__ __forceinline__ void cp_async16(uint32_t dst, const void* src) {
    asm volatile("cp.async.cg.shared.global [%0], [%1], 16;"
        :: "r"(dst), "l"(src) : "memory");
}
__device__ __forceinline__ void ldm4(uint32_t* r, uint32_t addr) {
    asm volatile("ldmatrix.sync.aligned.m8n8.x4.shared.b16 {%0,%1,%2,%3}, [%4];"
        : "=r"(r[0]), "=r"(r[1]), "=r"(r[2]), "=r"(r[3]) : "r"(addr));
}
__device__ __forceinline__ void mma16816(float* c, const uint32_t* a, const uint32_t* b) {
    asm volatile("mma.sync.aligned.m16n8k16.row.col.f32.f16.f16.f32 "
        "{%0,%1,%2,%3}, {%4,%5,%6,%7}, {%8,%9}, {%0,%1,%2,%3};"
        : "+f"(c[0]), "+f"(c[1]), "+f"(c[2]), "+f"(c[3])
        : "r"(a[0]), "r"(a[1]), "r"(a[2]), "r"(a[3]), "r"(b[0]), "r"(b[1]));
}

// ---------------------------------------------------------------------------
// misc helpers
// ---------------------------------------------------------------------------
__device__ __forceinline__ float warp_sum(float v) {
    #pragma unroll
    for (int o = 16; o; o >>= 1) v += __shfl_xor_sync(0xffffffffu, v, o);
    return v;
}
__device__ __forceinline__ int window_row(int bt) {
    int bb = bt >> 14;
    int t  = bt & 16383;
    int hh = t >> 9;
    int ww = (t >> 4) & 31;
    int ll = t & 15;
    int win = bb * NWIN_B + (((hh >> 3) * 4 + (ww >> 3)) * 2 + (ll >> 3));
    int n   = (((hh & 7) << 3) + (ww & 7)) * 8 + (ll & 7);
    return win * WN + n;
}
// fast x^p for x >= 0 (x==0 -> lg2 gives -inf -> ex2 gives 0)
__device__ __forceinline__ float fast_pow(float m, float p) {
    float lg, r;
    asm("lg2.approx.f32 %0, %1;" : "=f"(lg) : "f"(m));
    asm("ex2.approx.f32 %0, %1;" : "=f"(r) : "f"(p * lg));
    return r;
}

// ---------------------------------------------------------------------------
// all weights: fp32 -> fp16, single launch
// ---------------------------------------------------------------------------
__global__ void __launch_bounds__(256) cvt_all_kernel(
    const float4* __restrict__ s0, uint2* __restrict__ h0, int n0,
    const float4* __restrict__ s1, uint2* __restrict__ h1, int n1,
    const float4* __restrict__ s2, uint2* __restrict__ h2, int n2,
    const float4* __restrict__ s3, uint2* __restrict__ h3, int n3)
{
    int i = blockIdx.x * blockDim.x + threadIdx.x;
    const float4* s; uint2* hp; int idx;
    if (i < n0)                { s = s0; hp = h0; idx = i; }
    else if (i < n0+n1)        { s = s1; hp = h1; idx = i - n0; }
    else if (i < n0+n1+n2)     { s = s2; hp = h2; idx = i - n0 - n1; }
    else if (i < n0+n1+n2+n3)  { s = s3; hp = h3; idx = i - n0 - n1 - n2; }
    else return;
    float4 v = s[idx];
    __half2 ph0 = __halves2half2(__float2half(v.x), __float2half(v.y));
    __half2 ph1 = __halves2half2(__float2half(v.z), __float2half(v.w));
    uint2 uh; uh.x = *(uint32_t*)&ph0; uh.y = *(uint32_t*)&ph1;
    hp[idx] = uh;
}

// ---------------------------------------------------------------------------
// LayerNorm fused with window partition -> fp16; y selects (x->xw | y->yw)
// ---------------------------------------------------------------------------
__global__ void __launch_bounds__(256) ln_win_kernel(
    const float* __restrict__ xa, const float* __restrict__ xb,
    const float* __restrict__ g, const float* __restrict__ b,
    __half* __restrict__ oa, __half* __restrict__ ob)
{
    int warp = (blockIdx.x * blockDim.x + threadIdx.x) >> 5;
    int lane = threadIdx.x & 31;
    if (warp >= BTROWS) return;
    const float* x = blockIdx.y ? xb : xa;
    __half* o16 = blockIdx.y ? ob : oa;
    const float* xr = x + (size_t)warp * CDIM;
    float v[12];
    float s = 0.f;
    #pragma unroll
    for (int i = 0; i < 12; i++) { v[i] = xr[lane + i * 32]; s += v[i]; }
    s = warp_sum(s);
    float mu = s * (1.f / 384.f);
    float sq = 0.f;
    #pragma unroll
    for (int i = 0; i < 12; i++) { float dv = v[i] - mu; sq += dv * dv; }
    sq = warp_sum(sq);
    float rstd = rsqrtf(sq * (1.f / 384.f) + 1e-5f);
    size_t ro = (size_t)window_row(warp) * CDIM;
    #pragma unroll
    for (int i = 0; i < 12; i++) {
        int c = lane + i * 32;
        float o = (v[i] - mu) * rstd * g[c] + b[c];
        o16[ro + c] = __float2half(o);
    }
}

// ---------------------------------------------------------------------------
// residual-add (window_reverse) + LN2 -> x2 fp32, hn fp16
// ---------------------------------------------------------------------------
__global__ void __launch_bounds__(256) resln_kernel(
    const float* __restrict__ x, const float* __restrict__ aw,
    const float* __restrict__ g, const float* __restrict__ b,
    float* __restrict__ x2, __half* __restrict__ hn)
{
    int warp = (blockIdx.x * blockDim.x + threadIdx.x) >> 5;
    int lane = threadIdx.x & 31;
    if (warp >= BTROWS) return;
    const float* xr = x  + (size_t)warp * CDIM;
    const float* ar = aw + (size_t)window_row(warp) * CDIM;
    float v[12];
    float s = 0.f;
    #pragma unroll
    for (int i = 0; i < 12; i++) {
        int c = lane + i * 32;
        v[i] = xr[c] + ar[c];
        s += v[i];
    }
    s = warp_sum(s);
    float mu = s * (1.f / 384.f);
    float sq = 0.f;
    #pragma unroll
    for (int i = 0; i < 12; i++) { float dv = v[i] - mu; sq += dv * dv; }
    sq = warp_sum(sq);
    float rstd = rsqrtf(sq * (1.f / 384.f) + 1e-5f);
    size_t ro = (size_t)warp * CDIM;
    #pragma unroll
    for (int i = 0; i < 12; i++) {
        int c = lane + i * 32;
        x2[ro + c] = v[i];
        float o = (v[i] - mu) * rstd * g[c] + b[c];
        hn[ro + c] = __float2half(o);
    }
}

// ---------------------------------------------------------------------------
// mma.sync GEMM body: C[M,N] = A[M,K] @ W[N,K]^T (+ bias / gelu / residual)
// fp16 single pass. BM=BN=128, BK=32, 256 threads, 8 warps (2Mx4N),
// warp tile 64x32, m16n8k16. 4-stage cp.async pipeline, XOR-swizzled smem.
// EPI: 0 = bias->fp32 C, 1 = bias+gelu->fp16 C16, 2 = bias+res->fp32 C,
//      3 = bias->fp16 C16
// ---------------------------------------------------------------------------
#define GSTAGE 16384
#define GSMEM_BYTES (4*GSTAGE)

template <int EPI>
__device__ __forceinline__ void gemm_body(
    const __half* __restrict__ A, const __half* __restrict__ Bh,
    const float* __restrict__ bias, const float* __restrict__ res,
    float* __restrict__ C, __half* __restrict__ C16,
    int N, int K, int bm, int bn, char* smem)
{
    const uint32_t sbase = smem_u32(smem);
    const int tid  = threadIdx.x;
    const int lane = tid & 31;
    const int wid  = tid >> 5;
    const int wm   = wid & 1;
    const int wn   = wid >> 1;

    float acc[4][4][4];
    #pragma unroll
    for (int i = 0; i < 4; i++)
        #pragma unroll
        for (int j = 0; j < 4; j++)
            #pragma unroll
            for (int q = 0; q < 4; q++) acc[i][j][q] = 0.f;

    #define LOAD_STAGE(stage, k0) do {                                        \
        uint32_t sb_ = sbase + (uint32_t)(stage) * GSTAGE;                    \
        const __half* bases_[2] = {A, Bh};                                    \
        _Pragma("unroll")                                                     \
        for (int sub_ = 0; sub_ < 2; sub_++) {                                \
            const __half* bp_ = bases_[sub_];                                 \
            int ro_ = (sub_ == 0) ? bm : bn;                                  \
            _Pragma("unroll")                                                 \
            for (int jj_ = 0; jj_ < 2; jj_++) {                               \
                int cid_ = tid + 256 * jj_;                                   \
                int row_ = cid_ >> 2, ck_ = cid_ & 3;                         \
                int cs_ = ck_ ^ ((row_ >> 1) & 3);                            \
                const void* src_ = bp_ + (size_t)(ro_ + row_) * K + (k0) + ck_ * 8; \
                cp_async16(sb_ + (uint32_t)(sub_ << 13)                       \
                           + (uint32_t)(row_ * 64 + cs_ * 16), src_);         \
            }                                                                 \
        }                                                                     \
    } while (0)

    const int NC = K >> 5;
    LOAD_STAGE(0, 0);
    asm volatile("cp.async.commit_group;" ::: "memory");
    LOAD_STAGE(1, 32);
    asm volatile("cp.async.commit_group;" ::: "memory");
    LOAD_STAGE(2, 64);
    asm volatile("cp.async.commit_group;" ::: "memory");

    const int arow = wm * 64 + (lane & 15);
    const int asel = lane >> 4;
    const int brow = wn * 32 + ((lane >> 4) << 3) + (lane & 7);
    const int bsel = (lane >> 3) & 1;

    for (int c = 0; c < NC; c++) {
        asm volatile("cp.async.wait_group 2;" ::: "memory");
        __syncthreads();
        if (c + 3 < NC) {
            LOAD_STAGE((c + 3) & 3, (c + 3) << 5);
            asm volatile("cp.async.commit_group;" ::: "memory");
        }

        const uint32_t sb = sbase + (uint32_t)(c & 3) * GSTAGE;
        #pragma unroll
        for (int kk = 0; kk < 2; kk++) {
            uint32_t a[4][4], bh[2][4];
            #pragma unroll
            for (int mt = 0; mt < 4; mt++) {
                int row = arow + mt * 16;
                int ck  = kk * 2 + asel;
                uint32_t off = (uint32_t)(row * 64 + (ck ^ ((row >> 1) & 3)) * 16);
                ldm4(a[mt], sb + off);
            }
            #pragma unroll
            for (int bt = 0; bt < 2; bt++) {
                int row = brow + bt * 16;
                int ck  = kk * 2 + bsel;
                uint32_t off = (uint32_t)(row * 64 + (ck ^ ((row >> 1) & 3)) * 16);
                ldm4(bh[bt], sb + 8192u + off);
            }
            #pragma unroll
            for (int mt = 0; mt < 4; mt++) {
                #pragma unroll
                for (int nt = 0; nt < 4; nt++) {
                    const uint32_t* bhf = &bh[nt >> 1][(nt & 1) * 2];
                    mma16816(acc[mt][nt], a[mt], bhf);
                }
            }
        }
    }

    // ---- epilogue ----
    const int gr = lane >> 2;
    const int nc0 = (lane & 3) * 2;
    #pragma unroll
    for (int mt = 0; mt < 4; mt++) {
        #pragma unroll
        for (int nt = 0; nt < 4; nt++) {
            int col = bn + wn * 32 + nt * 8 + nc0;
            float bs0 = bias[col], bs1 = bias[col + 1];
            #pragma unroll
            for (int half = 0; half < 2; half++) {
                int row = bm + wm * 64 + mt * 16 + gr + half * 8;
                float v0 = acc[mt][nt][half * 2 + 0] + bs0;
                float v1 = acc[mt][nt][half * 2 + 1] + bs1;
                size_t off = (size_t)row * N + col;
                if (EPI == 1 || EPI == 3) {
                    if (EPI == 1) {
                        v0 = 0.5f * v0 * (1.f + erff(v0 * 0.70710678118654752f));
                        v1 = 0.5f * v1 * (1.f + erff(v1 * 0.70710678118654752f));
                    }
                    __half2 p = __halves2half2(__float2half(v0), __float2half(v1));
                    *(uint32_t*)(C16 + off) = *(uint32_t*)&p;
                } else {
                    if (EPI == 2) { v0 += res[off]; v1 += res[off + 1]; }
                    float2 o; o.x = v0; o.y = v1;
                    *(float2*)(C + off) = o;
                }
            }
        }
    }
    #undef LOAD_STAGE
}

template <int EPI>
__global__ void __launch_bounds__(256, 2) mma_gemm(
    const __half* __restrict__ A, const __half* __restrict__ Bh,
    const float* __restrict__ bias, const float* __restrict__ res,
    float* __restrict__ C, __half* __restrict__ C16, int N, int K)
{
    extern __shared__ char smem[];
    gemm_body<EPI>(A, Bh, bias, res, C, C16, N, K,
                   blockIdx.y * 128, blockIdx.x * 128, smem);
}

// fused kvg + q GEMM: blockIdx.x < 9 -> kvg tile, else q tile
__global__ void __launch_bounds__(256, 2) mma_gemm_qkv(
    const __half* __restrict__ xw, const __half* __restrict__ yw,
    const __half* __restrict__ wq, const float* __restrict__ bq,
    __half* __restrict__ kvg16, __half* __restrict__ qb16)
{
    extern __shared__ char smem[];
    if (blockIdx.x < 9) {
        gemm_body<3>(xw, wq + 384*384, bq + 384, nullptr, nullptr, kvg16,
                     KVGC, 384, blockIdx.y * 128, blockIdx.x * 128, smem);
    } else {
        gemm_body<3>(yw, wq, bq, nullptr, nullptr, qb16,
                     CDIM, 384, blockIdx.y * 128, (blockIdx.x - 9) * 128, smem);
    }
}

// ---------------------------------------------------------------------------
// Pola linear attention, one block per (window, head). 256 threads.
// ---------------------------------------------------------------------------
__global__ void __launch_bounds__(256) attn_kernel(
    const __half* __restrict__ kvg, const __half* __restrict__ qb,
    const float* __restrict__ pos_enc, const float* __restrict__ scale_p,
    const float* __restrict__ power_p, __half* __restrict__ xo)
{
    const int wg = blockIdx.x;   // 0..63
    const int h  = blockIdx.y;   // 0..11
    const int tid = threadIdx.x;

    __shared__ float sc_s[32], pw_s[32];
    __shared__ float buf[64][68];    // kc (phase A) / qf (phase C)
    __shared__ float vm[64][36];     // v (phase A) / kv partial / M (phase C)
    __shared__ float km2_s[2][64];
    __shared__ float z_s[64][2];

    if (tid < 32) {
        float sp = scale_p[h * 32 + tid];
        sc_s[tid] = 1.f / log1pf(expf(sp));          // 1/softplus
        float pp = power_p[h * 32 + tid];
        pw_s[tid] = 1.f + 4.f / (1.f + expf(-pp));   // 1 + ALPHA*sigmoid
    }
    __syncthreads();

    const int nh = tid >> 7;
    const int tt = tid & 127;
    const int fq = (tt >> 3) << 2;
    const int dq = (tt & 7) << 2;

    float acc[4][4];
    #pragma unroll
    for (int i = 0; i < 4; i++)
        #pragma unroll
        for (int j = 0; j < 4; j++) acc[i][j] = 0.f;
    float ksum = 0.f;

    // -------- phase A: kc features, kv = kc^T v (n-split), ksum --------
    for (int c0 = 0; c0 < WN; c0 += 64) {
        #pragma unroll
        for (int i = 0; i < 8; i++) {
            int idx = tid + 256 * i;
            int nl = idx >> 5;
            int d  = idx & 31;
            int row = wg * WN + c0 + nl;
            float kval = (__half2float(kvg[(size_t)row * KVGC + h * 32 + d])
                          + pos_enc[(c0 + nl) * CDIM + h * 32 + d]) * sc_s[d];
            float r = fast_pow(fabsf(kval), pw_s[d]);
            buf[nl][d]      = kval > 0.f ? r : 0.f;
            buf[nl][d + 32] = kval < 0.f ? r : 0.f;
            vm[nl][d] = __half2float(kvg[(size_t)row * KVGC + 384 + h * 32 + d]);
        }
        __syncthreads();
        #pragma unroll 4
        for (int n = 0; n < 32; n++) {
            int nn = (nh << 5) + n;
            float4 kq = *(const float4*)&buf[nn][fq];
            float4 v4 = *(const float4*)&vm[nn][dq];
            acc[0][0] += kq.x * v4.x; acc[0][1] += kq.x * v4.y;
            acc[0][2] += kq.x * v4.z; acc[0][3] += kq.x * v4.w;
            acc[1][0] += kq.y * v4.x; acc[1][1] += kq.y * v4.y;
            acc[1][2] += kq.y * v4.z; acc[1][3] += kq.y * v4.w;
            acc[2][0] += kq.z * v4.x; acc[2][1] += kq.z * v4.y;
            acc[2][2] += kq.z * v4.z; acc[2][3] += kq.z * v4.w;
            acc[3][0] += kq.w * v4.x; acc[3][1] += kq.w * v4.y;
            acc[3][2] += kq.w * v4.z; acc[3][3] += kq.w * v4.w;
        }
        if (tid < 64) {
            float s = ksum;
            #pragma unroll 8
            for (int n = 0; n < 64; n++) s += buf[n][tid];
            ksum = s;
        }
        __syncthreads();
    }

    // -------- merge n-halves, write M (reordered kv) and km vectors --------
    if (nh == 1) {
        #pragma unroll
        for (int i = 0; i < 4; i++)
            #pragma unroll
            for (int j = 0; j < 4; j++)
                vm[fq + i][dq + j] = acc[i][j];
    }
    __syncthreads();
    float mreg[4][4];
    if (nh == 0) {
        const float sN2 = 1.f / 512.f;
        #pragma unroll
        for (int i = 0; i < 4; i++)
            #pragma unroll
            for (int j = 0; j < 4; j++)
                mreg[i][j] = (acc[i][j] + vm[fq + i][dq + j]) * sN2;
    }
    if (tid < 64) {
        float km = ksum * (1.f / 512.f);
        km2_s[0][tid] = km;
        km2_s[1][(tid + 32) & 63] = km;
    }
    __syncthreads();
    if (nh == 0) {
        #pragma unroll
        for (int i = 0; i < 4; i++) {
            int fr = (dq < 16) ? (fq + i) : ((fq + i + 32) & 63);
            #pragma unroll
            for (int j = 0; j < 4; j++)
                vm[fr][dq + j] = mreg[i][j];
        }
    }
    __syncthreads();

    // -------- phase C: q features + O = qf @ M, z, write --------
    const int n0 = (tid >> 3) << 1;
    const int vc = (tid & 7) << 2;
    for (int c0 = 0; c0 < WN; c0 += 64) {
        #pragma unroll
        for (int i = 0; i < 8; i++) {
            int idx = tid + 256 * i;
            int nl = idx >> 5;
            int d  = idx & 31;
            int row = wg * WN + c0 + nl;
            float qv = __half2float(qb[(size_t)row * CDIM + h * 32 + d]) * sc_s[d];
            float r = fast_pow(fabsf(qv), pw_s[d]);
            buf[nl][d]      = qv > 0.f ? r : 0.f;
            buf[nl][d + 32] = qv < 0.f ? r : 0.f;
        }
        __syncthreads();

        float a00 = 0.f, a01 = 0.f, a02 = 0.f, a03 = 0.f;
        float a10 = 0.f, a11 = 0.f, a12 = 0.f, a13 = 0.f;
        #pragma unroll 4
        for (int f = 0; f < 64; f++) {
            float q0 = buf[n0][f];
            float q1 = buf[n0 + 1][f];
            float4 m = *(const float4*)&vm[f][vc];
            a00 += q0 * m.x; a01 += q0 * m.y; a02 += q0 * m.z; a03 += q0 * m.w;
            a10 += q1 * m.x; a11 += q1 * m.y; a12 += q1 * m.z; a13 += q1 * m.w;
        }
        if (tid < 128) {
            int n = tid >> 1, zi = tid & 1;
            float z = 1e-6f;
            #pragma unroll 8
            for (int f = 0; f < 64; f++) z += buf[n][f] * km2_s[zi][f];
            z_s[n][zi] = z;
        }
        __syncthreads();

        int zi = (vc >= 16) ? 1 : 0;
        float rz0 = 1.f / z_s[n0][zi];
        float rz1 = 1.f / z_s[n0 + 1][zi];
        size_t base0 = (size_t)(wg * WN + c0 + n0) * CDIM + h * 32 + vc;
        __half2 p00 = __halves2half2(__float2half(a00 * rz0), __float2half(a01 * rz0));
        __half2 p01 = __halves2half2(__float2half(a02 * rz0), __float2half(a03 * rz0));
        __half2 p10 = __halves2half2(__float2half(a10 * rz1), __float2half(a11 * rz1));
        __half2 p11 = __halves2half2(__float2half(a12 * rz1), __float2half(a13 * rz1));
        uint2 o0; o0.x = *(uint32_t*)&p00; o0.y = *(uint32_t*)&p01;
        uint2 o1; o1.x = *(uint32_t*)&p10; o1.y = *(uint32_t*)&p11;
        *(uint2*)&xo[base0] = o0;
        *(uint2*)&xo[base0 + CDIM] = o1;
        __syncthreads();
    }
}

// ---------------------------------------------------------------------------
// Depthwise 5^3 conv + (xo + vv) * g, in place on fp16 xo plane
// ---------------------------------------------------------------------------
__global__ void __launch_bounds__(256) dwconv_kernel(
    const __half* __restrict__ kvg, const float* __restrict__ dwc_w,
    const float* __restrict__ dwc_b, __half* __restrict__ xo16)
{
    extern __shared__ float sm[];
    float* v_s = sm;
    float* w_s = sm + 512 * 32;
    const int bh = blockIdx.x;
    const int b_ = bh / NHEADS, h = bh % NHEADS;
    const int tid = threadIdx.x;

    for (int i = tid; i < 512 * 32; i += 256) {
        int n = i >> 5, d = i & 31;
        v_s[i] = __half2float(kvg[(size_t)(b_ * WN + n) * KVGC + 384 + h * 32 + d]);
    }
    for (int i = tid; i < 125 * 32; i += 256) w_s[i] = dwc_w[i];
    __syncthreads();

    const int d  = tid & 31;
    const int lo = tid >> 5;
    const float bval = dwc_b[d];
    const size_t base = (size_t)b_ * (WN * CDIM) + (size_t)h * (WN * HD);

    for (int jg = 0; jg < 4; jg++) {
        float acc[16];
        #pragma unroll
        for (int jj = 0; jj < 16; jj++) acc[jj] = bval;
        for (int kd = 0; kd < 5; kd++) {
            for (int kh = 0; kh < 5; kh++) {
                for (int kw = 0; kw < 5; kw++) {
                    int li = lo + kw - 2;
                    if (li < 0 || li > 7) continue;
                    float w = w_s[((kd * 5 + kh) * 5 + kw) * 32 + d];
                    #pragma unroll
                    for (int jj = 0; jj < 16; jj++) {
                        int j = jg * 16 + jj;
                        int hi = (j >> 3) + kd - 2;
                        int wi = (j & 7) + kh - 2;
                        if (hi < 0 || hi > 7 || wi < 0 || wi > 7) continue;
                        acc[jj] += v_s[((hi * 8 + wi) * 8 + li) * 32 + d] * w;
                    }
                }
            }
        }
        #pragma unroll
        for (int jj = 0; jj < 16; jj++) {
            int j = jg * 16 + jj;
            size_t flat = base + (size_t)(lo + 8 * j) * 32 + d;
            size_t grow = flat / CDIM;
            int    gcol = (int)(flat % CDIM);
            float g = __half2float(kvg[grow * KVGC + 768 + gcol]);
            float val = (__half2float(xo16[flat]) + acc[jj]) * g;
            xo16[flat] = __float2half(val);
        }
    }
}

// ---------------------------------------------------------------------------
// kernel_launch
// ---------------------------------------------------------------------------
extern "C" void kernel_launch(void* const* d_in, const int* in_sizes, int n_in,
                              void* d_out, int out_size)
{
    const float* x       = (const float*)d_in[0];
    const float* y       = (const float*)d_in[1];
    const float* w_qkvg  = (const float*)d_in[2];
    const float* b_qkvg  = (const float*)d_in[3];
    const float* w_proj  = (const float*)d_in[4];
    const float* b_proj  = (const float*)d_in[5];
    const float* dwc_w   = (const float*)d_in[6];
    const float* dwc_b   = (const float*)d_in[7];
    const float* power_p = (const float*)d_in[8];
    const float* scale_p = (const float*)d_in[9];
    const float* pos_enc = (const float*)d_in[10];
    const float* g1      = (const float*)d_in[11];
    const float* b1      = (const float*)d_in[12];
    const float* g2      = (const float*)d_in[13];
    const float* b2      = (const float*)d_in[14];
    const float* w_fc1   = (const float*)d_in[15];
    const float* b_fc1   = (const float*)d_in[16];
    const float* w_fc2   = (const float*)d_in[17];
    const float* b_fc2   = (const float*)d_in[18];
    float* out = (float*)d_out;

    __half *p_xw16, *p_yw16, *p_hn16, *p_xo16, *p_h116, *p_kvg16, *p_qb16;
    __half *p_wqh, *p_wph, *p_w1h, *p_w2h;
    float *p_aw, *p_x2;
    cudaGetSymbolAddress((void**)&p_xw16, d_xw16);
    cudaGetSymbolAddress((void**)&p_yw16, d_yw16);
    cudaGetSymbolAddress((void**)&p_hn16, d_hn16);
    cudaGetSymbolAddress((void**)&p_xo16, d_xo16);
    cudaGetSymbolAddress((void**)&p_h116, d_h116);
    cudaGetSymbolAddress((void**)&p_kvg16, d_kvg16);
    cudaGetSymbolAddress((void**)&p_qb16, d_qb16);
    cudaGetSymbolAddress((void**)&p_wqh, d_wqh);
    cudaGetSymbolAddress((void**)&p_wph, d_wph);
    cudaGetSymbolAddress((void**)&p_w1h, d_w1h);
    cudaGetSymbolAddress((void**)&p_w2h, d_w2h);
    cudaGetSymbolAddress((void**)&p_aw,  d_aw);
    cudaGetSymbolAddress((void**)&p_x2,  d_x2);

    const int conv_smem = (512 * 32 + 125 * 32) * (int)sizeof(float);
    cudaFuncSetAttribute(dwconv_kernel,
                         cudaFuncAttributeMaxDynamicSharedMemorySize, conv_smem);
    cudaFuncSetAttribute(mma_gemm<0>,
                         cudaFuncAttributeMaxDynamicSharedMemorySize, GSMEM_BYTES);
    cudaFuncSetAttribute(mma_gemm<1>,
                         cudaFuncAttributeMaxDynamicSharedMemorySize, GSMEM_BYTES);
    cudaFuncSetAttribute(mma_gemm<2>,
                         cudaFuncAttributeMaxDynamicSharedMemorySize, GSMEM_BYTES);
    cudaFuncSetAttribute(mma_gemm_qkv,
                         cudaFuncAttributeMaxDynamicSharedMemorySize, GSMEM_BYTES);

    // 0) weight -> fp16, single launch
    {
        int n0 = 1536*384/4, n1 = 384*384/4, n2 = 1536*384/4, n3 = 384*1536/4;
        int tot = n0 + n1 + n2 + n3;
        cvt_all_kernel<<<(tot + 255)/256, 256>>>(
            (const float4*)w_qkvg, (uint2*)p_wqh, n0,
            (const float4*)w_proj, (uint2*)p_wph, n1,
            (const float4*)w_fc1,  (uint2*)p_w1h, n2,
            (const float4*)w_fc2,  (uint2*)p_w2h, n3);
    }

    // 1) LN + window partition (x and y in one launch) -> fp16
    ln_win_kernel<<<dim3(BTROWS / 8, 2), 256>>>(x, y, g1, b1, p_xw16, p_yw16);

    // 2+3) fused kvg + q GEMM (single pass) -> fp16
    mma_gemm_qkv<<<dim3(12, BTROWS/128), 256, GSMEM_BYTES>>>(
        p_xw16, p_yw16, p_wqh, b_qkvg, p_kvg16, p_qb16);

    // 4) attention -> xo16
    attn_kernel<<<dim3(NWIN, NHEADS), 256>>>(p_kvg16, p_qb16, pos_enc,
                                             scale_p, power_p, p_xo16);

    // 5) depthwise conv + gating, in place on xo16
    dwconv_kernel<<<NWIN * NHEADS, 256, conv_smem>>>(p_kvg16, dwc_w, dwc_b,
                                                     p_xo16);

    // 6) aw = xo @ w_proj^T + b_proj -> fp32 (single pass)
    mma_gemm<0><<<dim3(CDIM/128, BTROWS/128), 256, GSMEM_BYTES>>>(
        p_xo16, p_wph, b_proj, nullptr, p_aw, nullptr, CDIM, 384);

    // 7) x2 = x + window_reverse(aw); hn = LN2(x2) -> fp16
    resln_kernel<<<BTROWS / 8, 256>>>(x, p_aw, g2, b2, p_x2, p_hn16);

    // 8) h1 = gelu(hn @ w_fc1^T + b_fc1) -> fp16 (single pass, N=1536)
    mma_gemm<1><<<dim3(HIDDEN/128, BTROWS/128), 256, GSMEM_BYTES>>>(
        p_hn16, p_w1h, b_fc1, nullptr, nullptr, p_h116, HIDDEN, 384);

    // 9) out = x2 + h1 @ w_fc2^T + b_fc2 (single pass, K=1536)
    mma_gemm<2><<<dim3(CDIM/128, BTROWS/128), 256, GSMEM_BYTES>>>(
        p_h116, p_w2h, b_fc2, p_x2, out, nullptr, CDIM, 1536);
}